// round 5
// baseline (speedup 1.0000x reference)
#include <cuda_runtime.h>
#include <cuda_bf16.h>
#include <math.h>
#include <stdint.h>

#define B_   8
#define C_   512
#define G_   4
#define D_   128
#define H_   128
#define W_   128
#define WF_  65
#define F_   (H_*WF_)        // 8320
#define NIMG (B_*C_)         // 4096

// Scratch (allocation-free requirement -> device globals).
static __device__ float g_specR[(size_t)NIMG * F_];
static __device__ float g_specI[(size_t)NIMG * F_];
static __device__ float g_outR [(size_t)NIMG * F_];
static __device__ float g_outI [(size_t)NIMG * F_];
static __device__ unsigned short g_wimg[32 * 128 * 136];            // pre-split W planes
static __device__ unsigned short g_o1[(size_t)32 * 130 * 4 * 8192]; // O1 planes (272MB)

#define RPIT 129
#define CPIT 65
#define UBUF 8320
#define NT_F 512

#define WP   136            // bf16 plane pitch (conflict-free: 68 words % 32 == 4)
#define PLW  (128 * WP)     // W plane elems (17408)
#define PLX  (64 * WP)      // X plane elems (8704)

__device__ __forceinline__ int brev7(int v) { return (int)(__brev((unsigned)v) >> 25); }

__device__ __forceinline__ void split_bf16(float v, unsigned short& h, unsigned short& l) {
    __nv_bfloat16 hb = __float2bfloat16(v);
    float r = v - __bfloat162float(hb);
    h = __bfloat16_as_ushort(hb);
    l = __bfloat16_as_ushort(__float2bfloat16(r));
}

// ---------------------------------------------------------------------------
// Weight prep: pre-split bf16 hi/lo planes, layout A[m=out][k=in], pitch WP.
// ---------------------------------------------------------------------------
__global__ void __launch_bounds__(256) wprep(const float* __restrict__ w1,
                                             const float* __restrict__ w2) {
    int idx = blockIdx.x * 256 + threadIdx.x;      // 262144
    int m    = idx & 127;
    int k    = (idx >> 7) & 127;
    int part = (idx >> 14) & 1;
    int g    = (idx >> 15) & 3;
    int l    = (idx >> 17) & 1;
    const float* src = l ? w2 : w1;
    float v = src[(((size_t)(part * 4 + g) * 128 + k) * 128) + m];
    unsigned short h, lo;
    split_bf16(v, h, lo);
    size_t base = (size_t)((l * 4 + g) * 4 + part * 2) * PLW;
    g_wimg[base + m * WP + k]       = h;
    g_wimg[base + PLW + m * WP + k] = lo;
}

// ============================ FFT passes (unchanged) ========================
template<int S>
__device__ __forceinline__ void pass4_rows(float* R, float* I,
                                           const float* twR, const float* twI) {
    const int h = 1 << (S - 1);
    for (int it = threadIdx.x; it < 64 * 32; it += NT_F) {
        int r = it & 63, q = it >> 6;
        int j = q & (h - 1);
        int base = (q >> (S - 1)) << (S + 1);
        int i0 = r * RPIT + base + j;
        float e0r = R[i0],       e0i = I[i0];
        float e1r = R[i0 + h],   e1i = I[i0 + h];
        float e2r = R[i0 + 2*h], e2i = I[i0 + 2*h];
        float e3r = R[i0 + 3*h], e3i = I[i0 + 3*h];
        float w1r = twR[j << (7-S)], w1i = twI[j << (7-S)];
        float w2r = twR[j << (6-S)], w2i = twI[j << (6-S)];
        float w3r = twR[(j+h) << (6-S)], w3i = twI[(j+h) << (6-S)];
        float tr = e1r*w1r - e1i*w1i, ti = e1r*w1i + e1i*w1r;
        float A0r = e0r + tr, A0i = e0i + ti, A1r = e0r - tr, A1i = e0i - ti;
        tr = e3r*w1r - e3i*w1i; ti = e3r*w1i + e3i*w1r;
        float A2r = e2r + tr, A2i = e2i + ti, A3r = e2r - tr, A3i = e2i - ti;
        tr = A2r*w2r - A2i*w2i; ti = A2r*w2i + A2i*w2r;
        R[i0]       = A0r + tr; I[i0]       = A0i + ti;
        R[i0 + 2*h] = A0r - tr; I[i0 + 2*h] = A0i - ti;
        tr = A3r*w3r - A3i*w3i; ti = A3r*w3i + A3i*w3r;
        R[i0 + h]   = A1r + tr; I[i0 + h]   = A1i + ti;
        R[i0 + 3*h] = A1r - tr; I[i0 + 3*h] = A1i - ti;
    }
}

__device__ __forceinline__ void pass2_rows(float* R, float* I,
                                           const float* twR, const float* twI) {
    for (int it = threadIdx.x; it < 64 * 64; it += NT_F) {
        int r = it & 63, j = it >> 6;
        int i0 = r * RPIT + j, i1 = i0 + 64;
        float wr = twR[j], wi = twI[j];
        float ar = R[i0], ai = I[i0], br = R[i1], bi = I[i1];
        float tr = br*wr - bi*wi, ti = br*wi + bi*wr;
        R[i0] = ar + tr; I[i0] = ai + ti;
        R[i1] = ar - tr; I[i1] = ai - ti;
    }
}

template<int S>
__device__ __forceinline__ void pass4_cols(float* R, float* I,
                                           const float* twR, const float* twI) {
    const int h = 1 << (S - 1);
    const int st = h * CPIT;
    for (int it = threadIdx.x; it < 65 * 32; it += NT_F) {
        int c = it % 65, q = it / 65;
        int j = q & (h - 1);
        int base = (q >> (S - 1)) << (S + 1);
        int i0 = (base + j) * CPIT + c;
        float e0r = R[i0],        e0i = I[i0];
        float e1r = R[i0 + st],   e1i = I[i0 + st];
        float e2r = R[i0 + 2*st], e2i = I[i0 + 2*st];
        float e3r = R[i0 + 3*st], e3i = I[i0 + 3*st];
        float w1r = twR[j << (7-S)], w1i = twI[j << (7-S)];
        float w2r = twR[j << (6-S)], w2i = twI[j << (6-S)];
        float w3r = twR[(j+h) << (6-S)], w3i = twI[(j+h) << (6-S)];
        float tr = e1r*w1r - e1i*w1i, ti = e1r*w1i + e1i*w1r;
        float A0r = e0r + tr, A0i = e0i + ti, A1r = e0r - tr, A1i = e0i - ti;
        tr = e3r*w1r - e3i*w1i; ti = e3r*w1i + e3i*w1r;
        float A2r = e2r + tr, A2i = e2i + ti, A3r = e2r - tr, A3i = e2i - ti;
        tr = A2r*w2r - A2i*w2i; ti = A2r*w2i + A2i*w2r;
        R[i0]        = A0r + tr; I[i0]        = A0i + ti;
        R[i0 + 2*st] = A0r - tr; I[i0 + 2*st] = A0i - ti;
        tr = A3r*w3r - A3i*w3i; ti = A3r*w3i + A3i*w3r;
        R[i0 + st]   = A1r + tr; I[i0 + st]   = A1i + ti;
        R[i0 + 3*st] = A1r - tr; I[i0 + 3*st] = A1i - ti;
    }
}

__device__ __forceinline__ void pass2_cols(float* R, float* I,
                                           const float* twR, const float* twI) {
    for (int it = threadIdx.x; it < 65 * 64; it += NT_F) {
        int c = it % 65, j = it / 65;
        int i0 = j * CPIT + c, i1 = i0 + 64 * CPIT;
        float wr = twR[j], wi = twI[j];
        float ar = R[i0], ai = I[i0], br = R[i1], bi = I[i1];
        float tr = br*wr - bi*wi, ti = br*wi + bi*wr;
        R[i0] = ar + tr; I[i0] = ai + ti;
        R[i1] = ar - tr; I[i1] = ai - ti;
    }
}

__global__ void __launch_bounds__(NT_F, 2) kfft_fwd(const float* __restrict__ x) {
    extern __shared__ float sm[];
    float* R   = sm;
    float* I   = sm + UBUF;
    float* twR = sm + 2 * UBUF;
    float* twI = twR + 64;

    const int tid = threadIdx.x;
    const int img = blockIdx.x;

    if (tid < 64) {
        float s, c;
        sincospif(-(float)tid / 64.0f, &s, &c);
        twR[tid] = c; twI[tid] = s;
    }

    const float* src = x + (size_t)img * (H_ * W_);
    for (int t = tid; t < 64 * 128; t += NT_F) {
        int p = t >> 7, c = t & 127;
        int cb = brev7(c);
        R[p * RPIT + cb] = src[(2 * p) * 128 + c];
        I[p * RPIT + cb] = src[(2 * p) * 128 + 128 + c];
    }
    __syncthreads();

    pass4_rows<1>(R, I, twR, twI); __syncthreads();
    pass4_rows<3>(R, I, twR, twI); __syncthreads();
    pass4_rows<5>(R, I, twR, twI); __syncthreads();
    pass2_rows   (R, I, twR, twI); __syncthreads();

    float u0r[9], u0i[9], u1r[9], u1i[9];
    #pragma unroll
    for (int n = 0; n < 9; n++) {
        int it = tid + n * NT_F;
        if (it < 64 * 65) {
            int k = it % 65, p = it / 65;
            int m = (128 - k) & 127;
            float a = R[p * RPIT + k], b = I[p * RPIT + k];
            float c2 = R[p * RPIT + m], d = I[p * RPIT + m];
            u0r[n] = 0.5f * (a + c2); u0i[n] = 0.5f * (b - d);
            u1r[n] = 0.5f * (b + d);  u1i[n] = 0.5f * (c2 - a);
        }
    }
    __syncthreads();
    #pragma unroll
    for (int n = 0; n < 9; n++) {
        int it = tid + n * NT_F;
        if (it < 64 * 65) {
            int k = it % 65, p = it / 65;
            int h0 = brev7(2 * p), h1 = brev7(2 * p + 1);
            R[h0 * CPIT + k] = u0r[n]; I[h0 * CPIT + k] = u0i[n];
            R[h1 * CPIT + k] = u1r[n]; I[h1 * CPIT + k] = u1i[n];
        }
    }
    __syncthreads();

    pass4_cols<1>(R, I, twR, twI); __syncthreads();
    pass4_cols<3>(R, I, twR, twI); __syncthreads();
    pass4_cols<5>(R, I, twR, twI); __syncthreads();
    pass2_cols   (R, I, twR, twI); __syncthreads();

    float* dR = g_specR + (size_t)img * F_;
    float* dI = g_specI + (size_t)img * F_;
    const float sc = 1.0f / 128.0f;
    for (int t = tid; t < F_; t += NT_F) {
        dR[t] = R[t] * sc;
        dI[t] = I[t] * sc;
    }
}

// ---------------------------------------------------------------------------
// Tensor-core mixer, layer-split. Each CTA: one (b,g) x chunk of ft tiles,
// W planes loaded into smem ONCE per CTA.
// ---------------------------------------------------------------------------
__device__ __forceinline__ void mma16816(float* d, const uint32_t* a, const uint32_t* b) {
    asm volatile("mma.sync.aligned.m16n8k16.row.col.f32.bf16.bf16.f32 "
        "{%0,%1,%2,%3}, {%4,%5,%6,%7}, {%8,%9}, {%0,%1,%2,%3};"
        : "+f"(d[0]), "+f"(d[1]), "+f"(d[2]), "+f"(d[3])
        : "r"(a[0]), "r"(a[1]), "r"(a[2]), "r"(a[3]), "r"(b[0]), "r"(b[1]));
}

__device__ __forceinline__ void ldA(uint32_t* a, const unsigned short* Wp,
                                    int row, int k0, int tig) {
    const unsigned short* p = Wp + row * WP + k0 + tig * 2;
    a[0] = *(const uint32_t*)p;
    a[1] = *(const uint32_t*)(p + 8 * WP);
    a[2] = *(const uint32_t*)(p + 8);
    a[3] = *(const uint32_t*)(p + 8 * WP + 8);
}
__device__ __forceinline__ void ldB(uint32_t* bb, const unsigned short* Xp,
                                    int row, int k0, int tig) {
    const unsigned short* p = Xp + row * WP + k0 + tig * 2;
    bb[0] = *(const uint32_t*)p;
    bb[1] = *(const uint32_t*)(p + 8);
}

__device__ __forceinline__ void gemm_layer(const unsigned short* smW,
                                           const unsigned short* smX,
                                           float* aOr, float* aP, float* aOi,
                                           int warp_m, int warp_n, int gid, int tig) {
    #pragma unroll 1
    for (int kk = 0; kk < 8; kk++) {
        const int k0 = kk * 16;
        uint32_t A[4][2][4];
        #pragma unroll
        for (int pl = 0; pl < 4; pl++)
            #pragma unroll
            for (int mt = 0; mt < 2; mt++)
                ldA(A[pl][mt], smW + pl * PLW, warp_m + mt * 16 + gid, k0, tig);
        uint32_t Bf[4][4][2];
        #pragma unroll
        for (int pl = 0; pl < 4; pl++)
            #pragma unroll
            for (int nt = 0; nt < 4; nt++)
                ldB(Bf[pl][nt], smX + pl * PLX, warp_n + nt * 8 + gid, k0, tig);
        #pragma unroll
        for (int mt = 0; mt < 2; mt++)
            #pragma unroll
            for (int nt = 0; nt < 4; nt++) {
                float* dOr = aOr + (mt * 4 + nt) * 4;
                float* dP  = aP  + (mt * 4 + nt) * 4;
                float* dOi = aOi + (mt * 4 + nt) * 4;
                mma16816(dOr, A[0][mt], Bf[0][nt]);   // WrH*XrH
                mma16816(dOr, A[1][mt], Bf[0][nt]);   // WrL*XrH
                mma16816(dOr, A[0][mt], Bf[1][nt]);   // WrH*XrL
                mma16816(dP,  A[2][mt], Bf[2][nt]);   // WiH*XiH
                mma16816(dP,  A[3][mt], Bf[2][nt]);   // WiL*XiH
                mma16816(dP,  A[2][mt], Bf[3][nt]);   // WiH*XiL
                mma16816(dOi, A[2][mt], Bf[0][nt]);   // WiH*XrH
                mma16816(dOi, A[3][mt], Bf[0][nt]);   // WiL*XrH
                mma16816(dOi, A[2][mt], Bf[1][nt]);   // WiH*XrL
                mma16816(dOi, A[0][mt], Bf[2][nt]);   // WrH*XiH
                mma16816(dOi, A[1][mt], Bf[2][nt]);   // WrL*XiH
                mma16816(dOi, A[0][mt], Bf[3][nt]);   // WrH*XiL
            }
    }
}

#define SM_MIX (4 * PLW * 2 + 4 * PLX * 2)   // 139264 + 69632 = 208896 B
#define NCHUNK 9

__device__ __forceinline__ void chunk_range(int c, int& start, int& cnt) {
    start = c * 14 + (c < 4 ? c : 4);
    cnt   = 14 + (c < 4 ? 1 : 0);
}

// ================= Layer 1 kernel =================
__global__ void __launch_bounds__(256, 1)
kmixL1(const float* __restrict__ b1) {
    extern __shared__ unsigned short smix[];
    unsigned short* smW = smix;
    unsigned short* smX = smix + 4 * PLW;

    const int tid = threadIdx.x;
    const int wid = tid >> 5, lane = tid & 31;
    const int gid = lane >> 2, tig = lane & 3;
    const int warp_m = (wid & 3) * 32;
    const int warp_n = (wid >> 2) * 32;
    const int bg = blockIdx.x;               // 0..31
    const int b = bg >> 2, g = bg & 3;
    int start, cnt;
    chunk_range(blockIdx.y, start, cnt);

    // W1 planes: once per CTA
    {
        const float4* ws = (const float4*)(g_wimg + (size_t)(0 * 4 + g) * 4 * PLW);
        float4* wd = (float4*)smW;
        for (int i = tid; i < 4 * PLW / 8; i += 256) wd[i] = ws[i];
    }

    const float br_ = b1[g * D_ + 0];  (void)br_;

    for (int t = start; t < start + cnt; t++) {
        const size_t specbase = ((size_t)b * C_ + (size_t)g * D_) * F_ + (size_t)t * 64;
        __syncthreads();
        // build X planes from spec
        for (int it = tid; it < 128 * 64; it += 256) {
            int c = it >> 6, f = it & 63;
            float vr = g_specR[specbase + (size_t)c * F_ + f];
            float vi = g_specI[specbase + (size_t)c * F_ + f];
            unsigned short rh, rl, ih, il;
            split_bf16(vr, rh, rl);
            split_bf16(vi, ih, il);
            int o = f * WP + c;
            smX[o] = rh; smX[PLX + o] = rl; smX[2 * PLX + o] = ih; smX[3 * PLX + o] = il;
        }
        __syncthreads();

        float aOr[32], aP[32], aOi[32];
        #pragma unroll
        for (int i = 0; i < 32; i++) { aOr[i] = 0.f; aP[i] = 0.f; aOi[i] = 0.f; }
        gemm_layer(smW, smX, aOr, aP, aOi, warp_m, warp_n, gid, tig);
        __syncthreads();

        // epilogue: bias + relu, split, write O1 planes back into smX
        #pragma unroll
        for (int mt = 0; mt < 2; mt++) {
            int r0 = warp_m + mt * 16 + gid;
            float br0 = b1[g * D_ + r0],        br1 = b1[g * D_ + r0 + 8];
            float bi0 = b1[(G_ + g) * D_ + r0], bi1 = b1[(G_ + g) * D_ + r0 + 8];
            #pragma unroll
            for (int nt = 0; nt < 4; nt++) {
                int c0 = warp_n + nt * 8 + tig * 2;
                int ai = (mt * 4 + nt) * 4;
                #pragma unroll
                for (int e = 0; e < 4; e++) {
                    int row = (e >= 2) ? r0 + 8 : r0;
                    int col = c0 + (e & 1);
                    float brv = (e >= 2) ? br1 : br0;
                    float biv = (e >= 2) ? bi1 : bi0;
                    float vr = aOr[ai + e] - aP[ai + e] + brv; vr = vr > 0.f ? vr : 0.f;
                    float vi = aOi[ai + e] + biv;              vi = vi > 0.f ? vi : 0.f;
                    unsigned short rh, rl, ih, il;
                    split_bf16(vr, rh, rl);
                    split_bf16(vi, ih, il);
                    int o = col * WP + row;
                    smX[o] = rh; smX[PLX + o] = rl;
                    smX[2 * PLX + o] = ih; smX[3 * PLX + o] = il;
                }
            }
        }
        __syncthreads();

        // coalesced copy-out smX planes -> g_o1[bg][t] (pitch removed)
        {
            uint4* dst = (uint4*)(g_o1 + ((size_t)bg * 130 + t) * 4 * 8192);
            for (int i = tid; i < 4 * 64 * 16; i += 256) {
                int pl = i >> 10, rem = i & 1023;      // rem = f*16 + c16
                int f = rem >> 4, c16 = rem & 15;
                const uint4* s = (const uint4*)(smX + pl * PLX + f * WP) + c16;
                dst[i] = *s;
            }
        }
    }
}

// ================= Layer 2 kernel =================
__global__ void __launch_bounds__(256, 1)
kmixL2(const float* __restrict__ b2) {
    extern __shared__ unsigned short smix[];
    unsigned short* smW = smix;
    unsigned short* smX = smix + 4 * PLW;

    const int tid = threadIdx.x;
    const int wid = tid >> 5, lane = tid & 31;
    const int gid = lane >> 2, tig = lane & 3;
    const int warp_m = (wid & 3) * 32;
    const int warp_n = (wid >> 2) * 32;
    const int bg = blockIdx.x;
    const int b = bg >> 2, g = bg & 3;
    int start, cnt;
    chunk_range(blockIdx.y, start, cnt);

    // W2 planes: once per CTA
    {
        const float4* ws = (const float4*)(g_wimg + (size_t)(1 * 4 + g) * 4 * PLW);
        float4* wd = (float4*)smW;
        for (int i = tid; i < 4 * PLW / 8; i += 256) wd[i] = ws[i];
    }

    for (int t = start; t < start + cnt; t++) {
        const size_t specbase = ((size_t)b * C_ + (size_t)g * D_) * F_ + (size_t)t * 64;
        __syncthreads();
        // copy-in O1 planes (re-add pitch)
        {
            const uint4* src = (const uint4*)(g_o1 + ((size_t)bg * 130 + t) * 4 * 8192);
            for (int i = tid; i < 4 * 64 * 16; i += 256) {
                int pl = i >> 10, rem = i & 1023;
                int f = rem >> 4, c16 = rem & 15;
                uint4* d = (uint4*)(smX + pl * PLX + f * WP) + c16;
                *d = src[i];
            }
        }
        __syncthreads();

        float aOr[32], aP[32], aOi[32];
        #pragma unroll
        for (int i = 0; i < 32; i++) { aOr[i] = 0.f; aP[i] = 0.f; aOi[i] = 0.f; }
        gemm_layer(smW, smX, aOr, aP, aOi, warp_m, warp_n, gid, tig);

        // epilogue: bias, multiply by origin, store (no smem use)
        #pragma unroll
        for (int mt = 0; mt < 2; mt++) {
            int r0 = warp_m + mt * 16 + gid;
            float br0 = b2[g * D_ + r0],        br1 = b2[g * D_ + r0 + 8];
            float bi0 = b2[(G_ + g) * D_ + r0], bi1 = b2[(G_ + g) * D_ + r0 + 8];
            #pragma unroll
            for (int nt = 0; nt < 4; nt++) {
                int c0 = warp_n + nt * 8 + tig * 2;
                int ai = (mt * 4 + nt) * 4;
                #pragma unroll
                for (int rp = 0; rp < 2; rp++) {
                    int row = r0 + rp * 8;
                    float brv = rp ? br1 : br0;
                    float biv = rp ? bi1 : bi0;
                    size_t gi = specbase + (size_t)row * F_ + c0;
                    float2 xr = *(const float2*)&g_specR[gi];
                    float2 xi = *(const float2*)&g_specI[gi];
                    float vr0 = aOr[ai + rp * 2]     - aP[ai + rp * 2]     + brv;
                    float vi0 = aOi[ai + rp * 2]     + biv;
                    float vr1 = aOr[ai + rp * 2 + 1] - aP[ai + rp * 2 + 1] + brv;
                    float vi1 = aOi[ai + rp * 2 + 1] + biv;
                    float2 orv, oiv;
                    orv.x = vr0 * xr.x - vi0 * xi.x;
                    oiv.x = vr0 * xi.x + vi0 * xr.x;
                    orv.y = vr1 * xr.y - vi1 * xi.y;
                    oiv.y = vr1 * xi.y + vi1 * xr.y;
                    *(float2*)&g_outR[gi] = orv;
                    *(float2*)&g_outI[gi] = oiv;
                }
            }
        }
    }
}

// ---------------------------------------------------------------------------
__global__ void __launch_bounds__(NT_F, 2) kfft_inv(float* __restrict__ y) {
    extern __shared__ float sm[];
    float* R   = sm;
    float* I   = sm + UBUF;
    float* twR = sm + 2 * UBUF;
    float* twI = twR + 64;

    const int tid = threadIdx.x;
    const int img = blockIdx.x;

    if (tid < 64) {
        float s, c;
        sincospif((float)tid / 64.0f, &s, &c);
        twR[tid] = c; twI[tid] = s;
    }

    const float* srcR = g_outR + (size_t)img * F_;
    const float* srcI = g_outI + (size_t)img * F_;
    for (int t = tid; t < F_; t += NT_F) {
        int h = t / WF_, k = t - h * WF_;
        int hb = brev7(h);
        R[hb * CPIT + k] = srcR[t];
        I[hb * CPIT + k] = srcI[t];
    }
    __syncthreads();

    pass4_cols<1>(R, I, twR, twI); __syncthreads();
    pass4_cols<3>(R, I, twR, twI); __syncthreads();
    pass4_cols<5>(R, I, twR, twI); __syncthreads();
    pass2_cols   (R, I, twR, twI); __syncthreads();

    float zr[16], zi[16];
    #pragma unroll
    for (int n = 0; n < 16; n++) {
        int it = tid + n * NT_F;
        int w = it & 127, p = it >> 7;
        int r0 = (2 * p) * CPIT, r1 = r0 + CPIT;
        if (w <= 64) {
            float x0r = R[r0 + w], x0i = I[r0 + w];
            float x1r = R[r1 + w], x1i = I[r1 + w];
            if (w == 0 || w == 64) { x0i = 0.f; x1i = 0.f; }
            zr[n] = x0r - x1i;
            zi[n] = x0i + x1r;
        } else {
            int m = 128 - w;
            float x0r = R[r0 + m], x0i = I[r0 + m];
            float x1r = R[r1 + m], x1i = I[r1 + m];
            zr[n] = x0r + x1i;
            zi[n] = x1r - x0i;
        }
    }
    __syncthreads();
    #pragma unroll
    for (int n = 0; n < 16; n++) {
        int it = tid + n * NT_F;
        int w = it & 127, p = it >> 7;
        int wb = brev7(w);
        R[p * RPIT + wb] = zr[n];
        I[p * RPIT + wb] = zi[n];
    }
    __syncthreads();

    pass4_rows<1>(R, I, twR, twI); __syncthreads();
    pass4_rows<3>(R, I, twR, twI); __syncthreads();
    pass4_rows<5>(R, I, twR, twI); __syncthreads();
    pass2_rows   (R, I, twR, twI); __syncthreads();

    float* dst = y + (size_t)img * (H_ * W_);
    const float sc = 1.0f / 128.0f;
    for (int t = tid; t < 64 * 128; t += NT_F) {
        int p = t >> 7, c = t & 127;
        dst[(2 * p) * 128 + c]       = R[p * RPIT + c] * sc;
        dst[(2 * p) * 128 + 128 + c] = I[p * RPIT + c] * sc;
    }
}

// ---------------------------------------------------------------------------
extern "C" void kernel_launch(void* const* d_in, const int* in_sizes, int n_in,
                              void* d_out, int out_size) {
    const float* x  = (const float*)d_in[0];
    const float* w1 = (const float*)d_in[1];
    const float* w2 = (const float*)d_in[2];
    const float* b1 = (const float*)d_in[3];
    const float* b2 = (const float*)d_in[4];
    float* y = (float*)d_out;

    const int smFFT = (2 * UBUF + 128) * (int)sizeof(float);   // ~65.5 KB

    cudaFuncSetAttribute(kfft_fwd, cudaFuncAttributeMaxDynamicSharedMemorySize, smFFT);
    cudaFuncSetAttribute(kmixL1,   cudaFuncAttributeMaxDynamicSharedMemorySize, SM_MIX);
    cudaFuncSetAttribute(kmixL2,   cudaFuncAttributeMaxDynamicSharedMemorySize, SM_MIX);
    cudaFuncSetAttribute(kfft_inv, cudaFuncAttributeMaxDynamicSharedMemorySize, smFFT);

    wprep<<<1024, 256>>>(w1, w2);
    kfft_fwd<<<NIMG, NT_F, smFFT>>>(x);
    kmixL1<<<dim3(32, NCHUNK), 256, SM_MIX>>>(b1);
    kmixL2<<<dim3(32, NCHUNK), 256, SM_MIX>>>(b2);
    kfft_inv<<<NIMG, NT_F, smFFT>>>(y);
}

// round 9
// speedup vs baseline: 1.1396x; 1.1396x over previous
#include <cuda_runtime.h>
#include <cuda_bf16.h>
#include <math.h>
#include <stdint.h>

#define B_   8
#define C_   512
#define G_   4
#define D_   128
#define H_   128
#define W_   128
#define WF_  65
#define F_   (H_*WF_)        // 8320
#define NIMG (B_*C_)         // 4096

// Scratch (allocation-free requirement -> device globals).
static __device__ float g_specR[(size_t)NIMG * F_];
static __device__ float g_specI[(size_t)NIMG * F_];
static __device__ float g_outR [(size_t)NIMG * F_];
static __device__ float g_outI [(size_t)NIMG * F_];
static __device__ unsigned short g_wimg[32 * 128 * 136];            // pre-split W planes
static __device__ unsigned short g_o1[(size_t)32 * 260 * 16384];    // O1 planes (~273MB)

#define RPIT 129
#define CPIT 65
#define UBUF 8320
#define NT_F 512

#define WP    136           // bf16 plane pitch (shorts)
#define PLW   (128 * WP)    // W plane elems (17408)
#define PLX32 (32 * WP)     // X plane elems, N=32 tile (4352)
#define NTILE 260           // 8320 / 32
#define NCHUNK 9
#define RPITCH 36           // raw staging pitch (floats), 144B rows (16B aligned)

__device__ __forceinline__ int brev7(int v) { return (int)(__brev((unsigned)v) >> 25); }

__device__ __forceinline__ void split_bf16(float v, unsigned short& h, unsigned short& l) {
    __nv_bfloat16 hb = __float2bfloat16(v);
    float r = v - __bfloat162float(hb);
    h = __bfloat16_as_ushort(hb);
    l = __bfloat16_as_ushort(__float2bfloat16(r));
}

__device__ __forceinline__ uint32_t smem_u32(const void* p) {
    uint32_t a;
    asm("{ .reg .u64 t; cvta.to.shared.u64 t, %1; cvt.u32.u64 %0, t; }" : "=r"(a) : "l"(p));
    return a;
}
#define CP_ASYNC16(dst, src) \
    asm volatile("cp.async.cg.shared.global [%0], [%1], 16;" :: "r"(dst), "l"(src))
#define CP_COMMIT() asm volatile("cp.async.commit_group;" ::: "memory")
#define CP_WAIT0()  asm volatile("cp.async.wait_group 0;"  ::: "memory")

// ---------------------------------------------------------------------------
// Weight prep: pre-split bf16 hi/lo planes, layout A[m=out][k=in], pitch WP.
// ---------------------------------------------------------------------------
__global__ void __launch_bounds__(256) wprep(const float* __restrict__ w1,
                                             const float* __restrict__ w2) {
    int idx = blockIdx.x * 256 + threadIdx.x;      // 262144
    int m    = idx & 127;
    int k    = (idx >> 7) & 127;
    int part = (idx >> 14) & 1;
    int g    = (idx >> 15) & 3;
    int l    = (idx >> 17) & 1;
    const float* src = l ? w2 : w1;
    float v = src[(((size_t)(part * 4 + g) * 128 + k) * 128) + m];
    unsigned short h, lo;
    split_bf16(v, h, lo);
    size_t base = (size_t)((l * 4 + g) * 4 + part * 2) * PLW;
    g_wimg[base + m * WP + k]       = h;
    g_wimg[base + PLW + m * WP + k] = lo;
}

// ============================ FFT passes ====================================
template<int S>
__device__ __forceinline__ void pass4_rows(float* R, float* I,
                                           const float* twR, const float* twI) {
    const int h = 1 << (S - 1);
    for (int it = threadIdx.x; it < 64 * 32; it += NT_F) {
        int r = it & 63, q = it >> 6;
        int j = q & (h - 1);
        int base = (q >> (S - 1)) << (S + 1);
        int i0 = r * RPIT + base + j;
        float e0r = R[i0],       e0i = I[i0];
        float e1r = R[i0 + h],   e1i = I[i0 + h];
        float e2r = R[i0 + 2*h], e2i = I[i0 + 2*h];
        float e3r = R[i0 + 3*h], e3i = I[i0 + 3*h];
        float w1r = twR[j << (7-S)], w1i = twI[j << (7-S)];
        float w2r = twR[j << (6-S)], w2i = twI[j << (6-S)];
        float w3r = twR[(j+h) << (6-S)], w3i = twI[(j+h) << (6-S)];
        float tr = e1r*w1r - e1i*w1i, ti = e1r*w1i + e1i*w1r;
        float A0r = e0r + tr, A0i = e0i + ti, A1r = e0r - tr, A1i = e0i - ti;
        tr = e3r*w1r - e3i*w1i; ti = e3r*w1i + e3i*w1r;
        float A2r = e2r + tr, A2i = e2i + ti, A3r = e2r - tr, A3i = e2i - ti;
        tr = A2r*w2r - A2i*w2i; ti = A2r*w2i + A2i*w2r;
        R[i0]       = A0r + tr; I[i0]       = A0i + ti;
        R[i0 + 2*h] = A0r - tr; I[i0 + 2*h] = A0i - ti;
        tr = A3r*w3r - A3i*w3i; ti = A3r*w3i + A3i*w3r;
        R[i0 + h]   = A1r + tr; I[i0 + h]   = A1i + ti;
        R[i0 + 3*h] = A1r - tr; I[i0 + 3*h] = A1i - ti;
    }
}

__device__ __forceinline__ void pass2_rows(float* R, float* I,
                                           const float* twR, const float* twI) {
    for (int it = threadIdx.x; it < 64 * 64; it += NT_F) {
        int r = it & 63, j = it >> 6;
        int i0 = r * RPIT + j, i1 = i0 + 64;
        float wr = twR[j], wi = twI[j];
        float ar = R[i0], ai = I[i0], br = R[i1], bi = I[i1];
        float tr = br*wr - bi*wi, ti = br*wi + bi*wr;
        R[i0] = ar + tr; I[i0] = ai + ti;
        R[i1] = ar - tr; I[i1] = ai - ti;
    }
}

template<int S>
__device__ __forceinline__ void pass4_cols(float* R, float* I,
                                           const float* twR, const float* twI) {
    const int h = 1 << (S - 1);
    const int st = h * CPIT;
    for (int it = threadIdx.x; it < 65 * 32; it += NT_F) {
        int c = it % 65, q = it / 65;
        int j = q & (h - 1);
        int base = (q >> (S - 1)) << (S + 1);
        int i0 = (base + j) * CPIT + c;
        float e0r = R[i0],        e0i = I[i0];
        float e1r = R[i0 + st],   e1i = I[i0 + st];
        float e2r = R[i0 + 2*st], e2i = I[i0 + 2*st];
        float e3r = R[i0 + 3*st], e3i = I[i0 + 3*st];
        float w1r = twR[j << (7-S)], w1i = twI[j << (7-S)];
        float w2r = twR[j << (6-S)], w2i = twI[j << (6-S)];
        float w3r = twR[(j+h) << (6-S)], w3i = twI[(j+h) << (6-S)];
        float tr = e1r*w1r - e1i*w1i, ti = e1r*w1i + e1i*w1r;
        float A0r = e0r + tr, A0i = e0i + ti, A1r = e0r - tr, A1i = e0i - ti;
        tr = e3r*w1r - e3i*w1i; ti = e3r*w1i + e3i*w1r;
        float A2r = e2r + tr, A2i = e2i + ti, A3r = e2r - tr, A3i = e2i - ti;
        tr = A2r*w2r - A2i*w2i; ti = A2r*w2i + A2i*w2r;
        R[i0]        = A0r + tr; I[i0]        = A0i + ti;
        R[i0 + 2*st] = A0r - tr; I[i0 + 2*st] = A0i - ti;
        tr = A3r*w3r - A3i*w3i; ti = A3r*w3i + A3i*w3r;
        R[i0 + st]   = A1r + tr; I[i0 + st]   = A1i + ti;
        R[i0 + 3*st] = A1r - tr; I[i0 + 3*st] = A1i - ti;
    }
}

__device__ __forceinline__ void pass2_cols(float* R, float* I,
                                           const float* twR, const float* twI) {
    for (int it = threadIdx.x; it < 65 * 64; it += NT_F) {
        int c = it % 65, j = it / 65;
        int i0 = j * CPIT + c, i1 = i0 + 64 * CPIT;
        float wr = twR[j], wi = twI[j];
        float ar = R[i0], ai = I[i0], br = R[i1], bi = I[i1];
        float tr = br*wr - bi*wi, ti = br*wi + bi*wr;
        R[i0] = ar + tr; I[i0] = ai + ti;
        R[i1] = ar - tr; I[i1] = ai - ti;
    }
}

__global__ void __launch_bounds__(NT_F, 2) kfft_fwd(const float* __restrict__ x) {
    extern __shared__ float sm[];
    float* R   = sm;
    float* I   = sm + UBUF;
    float* twR = sm + 2 * UBUF;
    float* twI = twR + 64;

    const int tid = threadIdx.x;
    const int img = blockIdx.x;

    if (tid < 64) {
        float s, c;
        sincospif(-(float)tid / 64.0f, &s, &c);
        twR[tid] = c; twI[tid] = s;
    }

    const float* src = x + (size_t)img * (H_ * W_);
    for (int t = tid; t < 64 * 128; t += NT_F) {
        int p = t >> 7, c = t & 127;
        int cb = brev7(c);
        R[p * RPIT + cb] = src[(2 * p) * 128 + c];
        I[p * RPIT + cb] = src[(2 * p) * 128 + 128 + c];
    }
    __syncthreads();

    pass4_rows<1>(R, I, twR, twI); __syncthreads();
    pass4_rows<3>(R, I, twR, twI); __syncthreads();
    pass4_rows<5>(R, I, twR, twI); __syncthreads();
    pass2_rows   (R, I, twR, twI); __syncthreads();

    float u0r[9], u0i[9], u1r[9], u1i[9];
    #pragma unroll
    for (int n = 0; n < 9; n++) {
        int it = tid + n * NT_F;
        if (it < 64 * 65) {
            int k = it % 65, p = it / 65;
            int m = (128 - k) & 127;
            float a = R[p * RPIT + k], b = I[p * RPIT + k];
            float c2 = R[p * RPIT + m], d = I[p * RPIT + m];
            u0r[n] = 0.5f * (a + c2); u0i[n] = 0.5f * (b - d);
            u1r[n] = 0.5f * (b + d);  u1i[n] = 0.5f * (c2 - a);
        }
    }
    __syncthreads();
    #pragma unroll
    for (int n = 0; n < 9; n++) {
        int it = tid + n * NT_F;
        if (it < 64 * 65) {
            int k = it % 65, p = it / 65;
            int h0 = brev7(2 * p), h1 = brev7(2 * p + 1);
            R[h0 * CPIT + k] = u0r[n]; I[h0 * CPIT + k] = u0i[n];
            R[h1 * CPIT + k] = u1r[n]; I[h1 * CPIT + k] = u1i[n];
        }
    }
    __syncthreads();

    pass4_cols<1>(R, I, twR, twI); __syncthreads();
    pass4_cols<3>(R, I, twR, twI); __syncthreads();
    pass4_cols<5>(R, I, twR, twI); __syncthreads();
    pass2_cols   (R, I, twR, twI); __syncthreads();

    float* dR = g_specR + (size_t)img * F_;
    float* dI = g_specI + (size_t)img * F_;
    const float sc = 1.0f / 128.0f;
    for (int t = tid; t < F_; t += NT_F) {
        dR[t] = R[t] * sc;
        dI[t] = I[t] * sc;
    }
}

// ---------------------------------------------------------------------------
// Tensor-core mixer, layer-split + W-resident + cp.async pipelined. N=32 tile.
// ---------------------------------------------------------------------------
__device__ __forceinline__ void mma16816(float* d, const uint32_t* a, const uint32_t* b) {
    asm volatile("mma.sync.aligned.m16n8k16.row.col.f32.bf16.bf16.f32 "
        "{%0,%1,%2,%3}, {%4,%5,%6,%7}, {%8,%9}, {%0,%1,%2,%3};"
        : "+f"(d[0]), "+f"(d[1]), "+f"(d[2]), "+f"(d[3])
        : "r"(a[0]), "r"(a[1]), "r"(a[2]), "r"(a[3]), "r"(b[0]), "r"(b[1]));
}

__device__ __forceinline__ void ldA(uint32_t* a, const unsigned short* Wp,
                                    int row, int k0, int tig) {
    const unsigned short* p = Wp + row * WP + k0 + tig * 2;
    a[0] = *(const uint32_t*)p;
    a[1] = *(const uint32_t*)(p + 8 * WP);
    a[2] = *(const uint32_t*)(p + 8);
    a[3] = *(const uint32_t*)(p + 8 * WP + 8);
}
__device__ __forceinline__ void ldB(uint32_t* bb, const unsigned short* Xp,
                                    int row, int k0, int tig) {
    const unsigned short* p = Xp + row * WP + k0 + tig * 2;
    bb[0] = *(const uint32_t*)p;
    bb[1] = *(const uint32_t*)(p + 8);
}

// N=32 GEMM: warp_m in {0,32,64,96}, warp_n in {0,16}; acc 3 x [2mt][2nt][4]
__device__ __forceinline__ void gemm32(const unsigned short* smW,
                                       const unsigned short* smX,
                                       float* aOr, float* aP, float* aOi,
                                       int warp_m, int warp_n, int gid, int tig) {
    #pragma unroll 1
    for (int kk = 0; kk < 8; kk++) {
        const int k0 = kk * 16;
        uint32_t A[4][2][4];
        #pragma unroll
        for (int pl = 0; pl < 4; pl++)
            #pragma unroll
            for (int mt = 0; mt < 2; mt++)
                ldA(A[pl][mt], smW + pl * PLW, warp_m + mt * 16 + gid, k0, tig);
        uint32_t Bf[4][2][2];
        #pragma unroll
        for (int pl = 0; pl < 4; pl++)
            #pragma unroll
            for (int nt = 0; nt < 2; nt++)
                ldB(Bf[pl][nt], smX + pl * PLX32, warp_n + nt * 8 + gid, k0, tig);
        #pragma unroll
        for (int mt = 0; mt < 2; mt++)
            #pragma unroll
            for (int nt = 0; nt < 2; nt++) {
                float* dOr = aOr + (mt * 2 + nt) * 4;
                float* dP  = aP  + (mt * 2 + nt) * 4;
                float* dOi = aOi + (mt * 2 + nt) * 4;
                mma16816(dOr, A[0][mt], Bf[0][nt]);   // WrH*XrH
                mma16816(dOr, A[1][mt], Bf[0][nt]);   // WrL*XrH
                mma16816(dOr, A[0][mt], Bf[1][nt]);   // WrH*XrL
                mma16816(dP,  A[2][mt], Bf[2][nt]);   // WiH*XiH
                mma16816(dP,  A[3][mt], Bf[2][nt]);   // WiL*XiH
                mma16816(dP,  A[2][mt], Bf[3][nt]);   // WiH*XiL
                mma16816(dOi, A[2][mt], Bf[0][nt]);   // WiH*XrH
                mma16816(dOi, A[3][mt], Bf[0][nt]);   // WiL*XrH
                mma16816(dOi, A[2][mt], Bf[1][nt]);   // WiH*XrL
                mma16816(dOi, A[0][mt], Bf[2][nt]);   // WrH*XiH
                mma16816(dOi, A[1][mt], Bf[2][nt]);   // WrL*XiH
                mma16816(dOi, A[0][mt], Bf[3][nt]);   // WrH*XiL
            }
    }
}

__device__ __forceinline__ void chunk_range(int c, int& start, int& cnt) {
    start = c * 29;
    cnt   = (c == 8) ? 28 : 29;
}

// L1 smem: W planes | X planes | raw staging
#define L1_OFF_X   (4 * PLW * 2)                     // 139264
#define L1_OFF_RAW (L1_OFF_X + 4 * PLX32 * 2)        // 174080
#define SM_L1      (L1_OFF_RAW + 2 * 128 * RPITCH * 4)  // 210944
// L2 smem: W planes | 2x X plane buffers
#define L2_OFF_X   (4 * PLW * 2)
#define SM_L2      (L2_OFF_X + 2 * 4 * PLX32 * 2)       // 208896

// ================= Layer 1 kernel =================
__global__ void __launch_bounds__(256, 1)
kmixL1(const float* __restrict__ b1) {
    extern __shared__ char smem[];
    unsigned short* smW = (unsigned short*)smem;
    unsigned short* smX = (unsigned short*)(smem + L1_OFF_X);
    float*          raw = (float*)(smem + L1_OFF_RAW);
    const uint32_t raw_u32 = smem_u32(raw);

    const int tid = threadIdx.x;
    const int wid = tid >> 5, lane = tid & 31;
    const int gid = lane >> 2, tig = lane & 3;
    const int warp_m = (wid & 3) * 32;
    const int warp_n = (wid >> 2) * 16;
    const int bg = blockIdx.x;
    const int b = bg >> 2, g = bg & 3;
    int start, cnt;
    chunk_range(blockIdx.y, start, cnt);
    const int end = start + cnt;

    const size_t chanbase = ((size_t)b * C_ + (size_t)g * D_) * F_;

    // prefetch first tile raw spec (async)
    {
        for (int i = tid; i < 2048; i += 256) {
            int pl = i >> 10, rem = i & 1023, c = rem >> 3, seg = rem & 7;
            const float* src = (pl ? g_specI : g_specR) + chanbase + (size_t)c * F_
                             + (size_t)start * 32 + seg * 4;
            uint32_t dst = raw_u32 + (uint32_t)(pl * (128 * RPITCH * 4) + c * (RPITCH * 4) + seg * 16);
            CP_ASYNC16(dst, src);
        }
        CP_COMMIT();
    }

    // W1 planes: once per CTA (overlaps the cp.async above)
    {
        const float4* ws = (const float4*)(g_wimg + (size_t)(0 * 4 + g) * 4 * PLW);
        float4* wd = (float4*)smW;
        for (int i = tid; i < 4 * PLW / 8; i += 256) wd[i] = ws[i];
    }

    // bias values (fixed rows per warp)
    float br0[2], br1_[2], bi0[2], bi1_[2];
    #pragma unroll
    for (int mt = 0; mt < 2; mt++) {
        int r0 = warp_m + mt * 16 + gid;
        br0[mt]  = b1[g * D_ + r0];        br1_[mt] = b1[g * D_ + r0 + 8];
        bi0[mt]  = b1[(G_ + g) * D_ + r0]; bi1_[mt] = b1[(G_ + g) * D_ + r0 + 8];
    }

    for (int t = start; t < end; t++) {
        CP_WAIT0();
        __syncthreads();

        // convert raw -> X planes (split)
        #pragma unroll
        for (int n = 0; n < 16; n++) {
            int it = tid + n * 256;          // 4096 = 128c x 32f
            int c = it >> 5, f = it & 31;
            float vr = raw[c * RPITCH + f];
            float vi = raw[128 * RPITCH + c * RPITCH + f];
            unsigned short rh, rl, ih, il;
            split_bf16(vr, rh, rl);
            split_bf16(vi, ih, il);
            int o = f * WP + c;
            smX[o] = rh; smX[PLX32 + o] = rl;
            smX[2 * PLX32 + o] = ih; smX[3 * PLX32 + o] = il;
        }
        __syncthreads();

        // prefetch next tile raw (overlaps GEMM)
        if (t + 1 < end) {
            for (int i = tid; i < 2048; i += 256) {
                int pl = i >> 10, rem = i & 1023, c = rem >> 3, seg = rem & 7;
                const float* src = (pl ? g_specI : g_specR) + chanbase + (size_t)c * F_
                                 + (size_t)(t + 1) * 32 + seg * 4;
                uint32_t dst = raw_u32 + (uint32_t)(pl * (128 * RPITCH * 4) + c * (RPITCH * 4) + seg * 16);
                CP_ASYNC16(dst, src);
            }
            CP_COMMIT();
        }

        float aOr[16], aP[16], aOi[16];
        #pragma unroll
        for (int i = 0; i < 16; i++) { aOr[i] = 0.f; aP[i] = 0.f; aOi[i] = 0.f; }
        gemm32(smW, smX, aOr, aP, aOi, warp_m, warp_n, gid, tig);
        __syncthreads();

        // epilogue: bias + relu, split, write O1 planes back into smX
        #pragma unroll
        for (int mt = 0; mt < 2; mt++) {
            int r0 = warp_m + mt * 16 + gid;
            #pragma unroll
            for (int nt = 0; nt < 2; nt++) {
                int c0 = warp_n + nt * 8 + tig * 2;
                int ai = (mt * 2 + nt) * 4;
                #pragma unroll
                for (int e = 0; e < 4; e++) {
                    int row = (e >= 2) ? r0 + 8 : r0;
                    int col = c0 + (e & 1);
                    float brv = (e >= 2) ? br1_[mt] : br0[mt];
                    float biv = (e >= 2) ? bi1_[mt] : bi0[mt];
                    float vr = aOr[ai + e] - aP[ai + e] + brv; vr = vr > 0.f ? vr : 0.f;
                    float vi = aOi[ai + e] + biv;              vi = vi > 0.f ? vi : 0.f;
                    unsigned short rh, rl, ih, il;
                    split_bf16(vr, rh, rl);
                    split_bf16(vi, ih, il);
                    int o = col * WP + row;
                    smX[o] = rh; smX[PLX32 + o] = rl;
                    smX[2 * PLX32 + o] = ih; smX[3 * PLX32 + o] = il;
                }
            }
        }
        __syncthreads();

        // coalesced copy-out smX planes -> g_o1 (pitch removed): [pl][f][c]
        // FULL image: 4 planes x 32 f x 16 uint4 (128 channels) = 2048 uint4
        {
            uint4* dst = (uint4*)(g_o1 + ((size_t)bg * NTILE + t) * 16384);
            for (int i = tid; i < 2048; i += 256) {
                int pl = i >> 9, rem = i & 511, f = rem >> 4, c16 = rem & 15;
                dst[i] = *(const uint4*)(smX + pl * PLX32 + f * WP + c16 * 8);
            }
        }
    }
}

// ================= Layer 2 kernel =================
__global__ void __launch_bounds__(256, 1)
kmixL2(const float* __restrict__ b2) {
    extern __shared__ char smem[];
    unsigned short* smW  = (unsigned short*)smem;
    unsigned short* smX0 = (unsigned short*)(smem + L2_OFF_X);

    const int tid = threadIdx.x;
    const int wid = tid >> 5, lane = tid & 31;
    const int gid = lane >> 2, tig = lane & 3;
    const int warp_m = (wid & 3) * 32;
    const int warp_n = (wid >> 2) * 16;
    const int bg = blockIdx.x;
    const int b = bg >> 2, g = bg & 3;
    int start, cnt;
    chunk_range(blockIdx.y, start, cnt);
    const int end = start + cnt;

    const size_t chanbase = ((size_t)b * C_ + (size_t)g * D_) * F_;

    // prefetch first tile O1 planes into buf0 (2048 uint4 = full image)
    {
        const uint4* src = (const uint4*)(g_o1 + ((size_t)bg * NTILE + start) * 16384);
        uint32_t bufb = smem_u32(smX0);
        for (int i = tid; i < 2048; i += 256) {
            int pl = i >> 9, rem = i & 511, f = rem >> 4, c16 = rem & 15;
            uint32_t dst = bufb + (uint32_t)((pl * PLX32 + f * WP) * 2 + c16 * 16);
            CP_ASYNC16(dst, src + i);
        }
        CP_COMMIT();
    }

    // W2 planes
    {
        const float4* ws = (const float4*)(g_wimg + (size_t)(1 * 4 + g) * 4 * PLW);
        float4* wd = (float4*)smW;
        for (int i = tid; i < 4 * PLW / 8; i += 256) wd[i] = ws[i];
    }

    float br0[2], br1_[2], bi0[2], bi1_[2];
    #pragma unroll
    for (int mt = 0; mt < 2; mt++) {
        int r0 = warp_m + mt * 16 + gid;
        br0[mt]  = b2[g * D_ + r0];        br1_[mt] = b2[g * D_ + r0 + 8];
        bi0[mt]  = b2[(G_ + g) * D_ + r0]; bi1_[mt] = b2[(G_ + g) * D_ + r0 + 8];
    }

    for (int t = start; t < end; t++) {
        unsigned short* buf = smX0 + ((t - start) & 1) * (4 * PLX32);
        CP_WAIT0();
        __syncthreads();

        // prefetch next tile into other buffer (overlaps GEMM)
        if (t + 1 < end) {
            unsigned short* nb = smX0 + (((t - start) + 1) & 1) * (4 * PLX32);
            const uint4* src = (const uint4*)(g_o1 + ((size_t)bg * NTILE + (t + 1)) * 16384);
            uint32_t bufb = smem_u32(nb);
            for (int i = tid; i < 2048; i += 256) {
                int pl = i >> 9, rem = i & 511, f = rem >> 4, c16 = rem & 15;
                uint32_t dst = bufb + (uint32_t)((pl * PLX32 + f * WP) * 2 + c16 * 16);
                CP_ASYNC16(dst, src + i);
            }
            CP_COMMIT();
        }

        // prefetch origin spec values into registers (consumed in epilogue)
        float2 oxr[8], oxi[8];
        #pragma unroll
        for (int mt = 0; mt < 2; mt++)
            #pragma unroll
            for (int nt = 0; nt < 2; nt++)
                #pragma unroll
                for (int rp = 0; rp < 2; rp++) {
                    int row = warp_m + mt * 16 + gid + rp * 8;
                    int c0  = warp_n + nt * 8 + tig * 2;
                    size_t gi = chanbase + (size_t)row * F_ + (size_t)t * 32 + c0;
                    int idx = mt * 4 + nt * 2 + rp;
                    oxr[idx] = *(const float2*)&g_specR[gi];
                    oxi[idx] = *(const float2*)&g_specI[gi];
                }

        float aOr[16], aP[16], aOi[16];
        #pragma unroll
        for (int i = 0; i < 16; i++) { aOr[i] = 0.f; aP[i] = 0.f; aOi[i] = 0.f; }
        gemm32(smW, buf, aOr, aP, aOi, warp_m, warp_n, gid, tig);

        // epilogue: bias, multiply by origin, store
        #pragma unroll
        for (int mt = 0; mt < 2; mt++) {
            #pragma unroll
            for (int nt = 0; nt < 2; nt++) {
                int c0 = warp_n + nt * 8 + tig * 2;
                int ai = (mt * 2 + nt) * 4;
                #pragma unroll
                for (int rp = 0; rp < 2; rp++) {
                    int row = warp_m + mt * 16 + gid + rp * 8;
                    float brv = rp ? br1_[mt] : br0[mt];
                    float biv = rp ? bi1_[mt] : bi0[mt];
                    int idx = mt * 4 + nt * 2 + rp;
                    float2 xr = oxr[idx], xi = oxi[idx];
                    size_t gi = chanbase + (size_t)row * F_ + (size_t)t * 32 + c0;
                    float vr0 = aOr[ai + rp * 2]     - aP[ai + rp * 2]     + brv;
                    float vi0 = aOi[ai + rp * 2]     + biv;
                    float vr1 = aOr[ai + rp * 2 + 1] - aP[ai + rp * 2 + 1] + brv;
                    float vi1 = aOi[ai + rp * 2 + 1] + biv;
                    float2 orv, oiv;
                    orv.x = vr0 * xr.x - vi0 * xi.x;
                    oiv.x = vr0 * xi.x + vi0 * xr.x;
                    orv.y = vr1 * xr.y - vi1 * xi.y;
                    oiv.y = vr1 * xi.y + vi1 * xr.y;
                    *(float2*)&g_outR[gi] = orv;
                    *(float2*)&g_outI[gi] = oiv;
                }
            }
        }
    }
}

// ---------------------------------------------------------------------------
__global__ void __launch_bounds__(NT_F, 2) kfft_inv(float* __restrict__ y) {
    extern __shared__ float sm[];
    float* R   = sm;
    float* I   = sm + UBUF;
    float* twR = sm + 2 * UBUF;
    float* twI = twR + 64;

    const int tid = threadIdx.x;
    const int img = blockIdx.x;

    if (tid < 64) {
        float s, c;
        sincospif((float)tid / 64.0f, &s, &c);
        twR[tid] = c; twI[tid] = s;
    }

    const float* srcR = g_outR + (size_t)img * F_;
    const float* srcI = g_outI + (size_t)img * F_;
    for (int t = tid; t < F_; t += NT_F) {
        int h = t / WF_, k = t - h * WF_;
        int hb = brev7(h);
        R[hb * CPIT + k] = srcR[t];
        I[hb * CPIT + k] = srcI[t];
    }
    __syncthreads();

    pass4_cols<1>(R, I, twR, twI); __syncthreads();
    pass4_cols<3>(R, I, twR, twI); __syncthreads();
    pass4_cols<5>(R, I, twR, twI); __syncthreads();
    pass2_cols   (R, I, twR, twI); __syncthreads();

    float zr[16], zi[16];
    #pragma unroll
    for (int n = 0; n < 16; n++) {
        int it = tid + n * NT_F;
        int w = it & 127, p = it >> 7;
        int r0 = (2 * p) * CPIT, r1 = r0 + CPIT;
        if (w <= 64) {
            float x0r = R[r0 + w], x0i = I[r0 + w];
            float x1r = R[r1 + w], x1i = I[r1 + w];
            if (w == 0 || w == 64) { x0i = 0.f; x1i = 0.f; }
            zr[n] = x0r - x1i;
            zi[n] = x0i + x1r;
        } else {
            int m = 128 - w;
            float x0r = R[r0 + m], x0i = I[r0 + m];
            float x1r = R[r1 + m], x1i = I[r1 + m];
            zr[n] = x0r + x1i;
            zi[n] = x1r - x0i;
        }
    }
    __syncthreads();
    #pragma unroll
    for (int n = 0; n < 16; n++) {
        int it = tid + n * NT_F;
        int w = it & 127, p = it >> 7;
        int wb = brev7(w);
        R[p * RPIT + wb] = zr[n];
        I[p * RPIT + wb] = zi[n];
    }
    __syncthreads();

    pass4_rows<1>(R, I, twR, twI); __syncthreads();
    pass4_rows<3>(R, I, twR, twI); __syncthreads();
    pass4_rows<5>(R, I, twR, twI); __syncthreads();
    pass2_rows   (R, I, twR, twI); __syncthreads();

    float* dst = y + (size_t)img * (H_ * W_);
    const float sc = 1.0f / 128.0f;
    for (int t = tid; t < 64 * 128; t += NT_F) {
        int p = t >> 7, c = t & 127;
        dst[(2 * p) * 128 + c]       = R[p * RPIT + c] * sc;
        dst[(2 * p) * 128 + 128 + c] = I[p * RPIT + c] * sc;
    }
}

// ---------------------------------------------------------------------------
extern "C" void kernel_launch(void* const* d_in, const int* in_sizes, int n_in,
                              void* d_out, int out_size) {
    const float* x  = (const float*)d_in[0];
    const float* w1 = (const float*)d_in[1];
    const float* w2 = (const float*)d_in[2];
    const float* b1 = (const float*)d_in[3];
    const float* b2 = (const float*)d_in[4];
    float* y = (float*)d_out;

    const int smFFT = (2 * UBUF + 128) * (int)sizeof(float);   // ~65.5 KB

    cudaFuncSetAttribute(kfft_fwd, cudaFuncAttributeMaxDynamicSharedMemorySize, smFFT);
    cudaFuncSetAttribute(kmixL1,   cudaFuncAttributeMaxDynamicSharedMemorySize, SM_L1);
    cudaFuncSetAttribute(kmixL2,   cudaFuncAttributeMaxDynamicSharedMemorySize, SM_L2);
    cudaFuncSetAttribute(kfft_inv, cudaFuncAttributeMaxDynamicSharedMemorySize, smFFT);

    wprep<<<1024, 256>>>(w1, w2);
    kfft_fwd<<<NIMG, NT_F, smFFT>>>(x);
    kmixL1<<<dim3(32, NCHUNK), 256, SM_L1>>>(b1);
    kmixL2<<<dim3(32, NCHUNK), 256, SM_L2>>>(b2);
    kfft_inv<<<NIMG, NT_F, smFFT>>>(y);
}

// round 10
// speedup vs baseline: 1.1472x; 1.0067x over previous
#include <cuda_runtime.h>
#include <cuda_bf16.h>
#include <math.h>
#include <stdint.h>

#define B_   8
#define C_   512
#define G_   4
#define D_   128
#define H_   128
#define W_   128
#define WF_  65
#define F_   (H_*WF_)        // 8320
#define NIMG (B_*C_)         // 4096

// Scratch (allocation-free requirement -> device globals).
static __device__ float g_specR[(size_t)NIMG * F_];
static __device__ float g_specI[(size_t)NIMG * F_];
static __device__ float g_outR [(size_t)NIMG * F_];
static __device__ float g_outI [(size_t)NIMG * F_];
static __device__ unsigned short g_wimg[32 * 128 * 136];            // pre-split W planes
static __device__ unsigned short g_o1[(size_t)32 * 260 * 16384];    // O1 planes (~273MB)

#define RPIT 129
#define CPIT 65
#define UBUF 8320
#define NT_F 512

#define WP    136           // bf16 plane pitch (shorts)
#define PLW   (128 * WP)    // W plane elems (17408)
#define PLX32 (32 * WP)     // X plane elems, N=32 tile (4352)
#define NTILE 260           // 8320 / 32
#define NCHUNK 9
#define RPITCH 36           // raw staging pitch (floats)
#define NT_M  512           // mixer threads (16 warps)

__device__ __forceinline__ int brev7(int v) { return (int)(__brev((unsigned)v) >> 25); }

__device__ __forceinline__ void split_bf16(float v, unsigned short& h, unsigned short& l) {
    __nv_bfloat16 hb = __float2bfloat16(v);
    float r = v - __bfloat162float(hb);
    h = __bfloat16_as_ushort(hb);
    l = __bfloat16_as_ushort(__float2bfloat16(r));
}

__device__ __forceinline__ uint32_t smem_u32(const void* p) {
    uint32_t a;
    asm("{ .reg .u64 t; cvta.to.shared.u64 t, %1; cvt.u32.u64 %0, t; }" : "=r"(a) : "l"(p));
    return a;
}
#define CP_ASYNC16(dst, src) \
    asm volatile("cp.async.cg.shared.global [%0], [%1], 16;" :: "r"(dst), "l"(src))
#define CP_COMMIT() asm volatile("cp.async.commit_group;" ::: "memory")
#define CP_WAIT0()  asm volatile("cp.async.wait_group 0;"  ::: "memory")

// ---------------------------------------------------------------------------
// Weight prep
// ---------------------------------------------------------------------------
__global__ void __launch_bounds__(256) wprep(const float* __restrict__ w1,
                                             const float* __restrict__ w2) {
    int idx = blockIdx.x * 256 + threadIdx.x;      // 262144
    int m    = idx & 127;
    int k    = (idx >> 7) & 127;
    int part = (idx >> 14) & 1;
    int g    = (idx >> 15) & 3;
    int l    = (idx >> 17) & 1;
    const float* src = l ? w2 : w1;
    float v = src[(((size_t)(part * 4 + g) * 128 + k) * 128) + m];
    unsigned short h, lo;
    split_bf16(v, h, lo);
    size_t base = (size_t)((l * 4 + g) * 4 + part * 2) * PLW;
    g_wimg[base + m * WP + k]       = h;
    g_wimg[base + PLW + m * WP + k] = lo;
}

// ============================ FFT passes (unchanged) ========================
template<int S>
__device__ __forceinline__ void pass4_rows(float* R, float* I,
                                           const float* twR, const float* twI) {
    const int h = 1 << (S - 1);
    for (int it = threadIdx.x; it < 64 * 32; it += NT_F) {
        int r = it & 63, q = it >> 6;
        int j = q & (h - 1);
        int base = (q >> (S - 1)) << (S + 1);
        int i0 = r * RPIT + base + j;
        float e0r = R[i0],       e0i = I[i0];
        float e1r = R[i0 + h],   e1i = I[i0 + h];
        float e2r = R[i0 + 2*h], e2i = I[i0 + 2*h];
        float e3r = R[i0 + 3*h], e3i = I[i0 + 3*h];
        float w1r = twR[j << (7-S)], w1i = twI[j << (7-S)];
        float w2r = twR[j << (6-S)], w2i = twI[j << (6-S)];
        float w3r = twR[(j+h) << (6-S)], w3i = twI[(j+h) << (6-S)];
        float tr = e1r*w1r - e1i*w1i, ti = e1r*w1i + e1i*w1r;
        float A0r = e0r + tr, A0i = e0i + ti, A1r = e0r - tr, A1i = e0i - ti;
        tr = e3r*w1r - e3i*w1i; ti = e3r*w1i + e3i*w1r;
        float A2r = e2r + tr, A2i = e2i + ti, A3r = e2r - tr, A3i = e2i - ti;
        tr = A2r*w2r - A2i*w2i; ti = A2r*w2i + A2i*w2r;
        R[i0]       = A0r + tr; I[i0]       = A0i + ti;
        R[i0 + 2*h] = A0r - tr; I[i0 + 2*h] = A0i - ti;
        tr = A3r*w3r - A3i*w3i; ti = A3r*w3i + A3i*w3r;
        R[i0 + h]   = A1r + tr; I[i0 + h]   = A1i + ti;
        R[i0 + 3*h] = A1r - tr; I[i0 + 3*h] = A1i - ti;
    }
}

__device__ __forceinline__ void pass2_rows(float* R, float* I,
                                           const float* twR, const float* twI) {
    for (int it = threadIdx.x; it < 64 * 64; it += NT_F) {
        int r = it & 63, j = it >> 6;
        int i0 = r * RPIT + j, i1 = i0 + 64;
        float wr = twR[j], wi = twI[j];
        float ar = R[i0], ai = I[i0], br = R[i1], bi = I[i1];
        float tr = br*wr - bi*wi, ti = br*wi + bi*wr;
        R[i0] = ar + tr; I[i0] = ai + ti;
        R[i1] = ar - tr; I[i1] = ai - ti;
    }
}

template<int S>
__device__ __forceinline__ void pass4_cols(float* R, float* I,
                                           const float* twR, const float* twI) {
    const int h = 1 << (S - 1);
    const int st = h * CPIT;
    for (int it = threadIdx.x; it < 65 * 32; it += NT_F) {
        int c = it % 65, q = it / 65;
        int j = q & (h - 1);
        int base = (q >> (S - 1)) << (S + 1);
        int i0 = (base + j) * CPIT + c;
        float e0r = R[i0],        e0i = I[i0];
        float e1r = R[i0 + st],   e1i = I[i0 + st];
        float e2r = R[i0 + 2*st], e2i = I[i0 + 2*st];
        float e3r = R[i0 + 3*st], e3i = I[i0 + 3*st];
        float w1r = twR[j << (7-S)], w1i = twI[j << (7-S)];
        float w2r = twR[j << (6-S)], w2i = twI[j << (6-S)];
        float w3r = twR[(j+h) << (6-S)], w3i = twI[(j+h) << (6-S)];
        float tr = e1r*w1r - e1i*w1i, ti = e1r*w1i + e1i*w1r;
        float A0r = e0r + tr, A0i = e0i + ti, A1r = e0r - tr, A1i = e0i - ti;
        tr = e3r*w1r - e3i*w1i; ti = e3r*w1i + e3i*w1r;
        float A2r = e2r + tr, A2i = e2i + ti, A3r = e2r - tr, A3i = e2i - ti;
        tr = A2r*w2r - A2i*w2i; ti = A2r*w2i + A2i*w2r;
        R[i0]        = A0r + tr; I[i0]        = A0i + ti;
        R[i0 + 2*st] = A0r - tr; I[i0 + 2*st] = A0i - ti;
        tr = A3r*w3r - A3i*w3i; ti = A3r*w3i + A3i*w3r;
        R[i0 + st]   = A1r + tr; I[i0 + st]   = A1i + ti;
        R[i0 + 3*st] = A1r - tr; I[i0 + 3*st] = A1i - ti;
    }
}

__device__ __forceinline__ void pass2_cols(float* R, float* I,
                                           const float* twR, const float* twI) {
    for (int it = threadIdx.x; it < 65 * 64; it += NT_F) {
        int c = it % 65, j = it / 65;
        int i0 = j * CPIT + c, i1 = i0 + 64 * CPIT;
        float wr = twR[j], wi = twI[j];
        float ar = R[i0], ai = I[i0], br = R[i1], bi = I[i1];
        float tr = br*wr - bi*wi, ti = br*wi + bi*wr;
        R[i0] = ar + tr; I[i0] = ai + ti;
        R[i1] = ar - tr; I[i1] = ai - ti;
    }
}

__global__ void __launch_bounds__(NT_F, 2) kfft_fwd(const float* __restrict__ x) {
    extern __shared__ float sm[];
    float* R   = sm;
    float* I   = sm + UBUF;
    float* twR = sm + 2 * UBUF;
    float* twI = twR + 64;

    const int tid = threadIdx.x;
    const int img = blockIdx.x;

    if (tid < 64) {
        float s, c;
        sincospif(-(float)tid / 64.0f, &s, &c);
        twR[tid] = c; twI[tid] = s;
    }

    const float* src = x + (size_t)img * (H_ * W_);
    for (int t = tid; t < 64 * 128; t += NT_F) {
        int p = t >> 7, c = t & 127;
        int cb = brev7(c);
        R[p * RPIT + cb] = src[(2 * p) * 128 + c];
        I[p * RPIT + cb] = src[(2 * p) * 128 + 128 + c];
    }
    __syncthreads();

    pass4_rows<1>(R, I, twR, twI); __syncthreads();
    pass4_rows<3>(R, I, twR, twI); __syncthreads();
    pass4_rows<5>(R, I, twR, twI); __syncthreads();
    pass2_rows   (R, I, twR, twI); __syncthreads();

    float u0r[9], u0i[9], u1r[9], u1i[9];
    #pragma unroll
    for (int n = 0; n < 9; n++) {
        int it = tid + n * NT_F;
        if (it < 64 * 65) {
            int k = it % 65, p = it / 65;
            int m = (128 - k) & 127;
            float a = R[p * RPIT + k], b = I[p * RPIT + k];
            float c2 = R[p * RPIT + m], d = I[p * RPIT + m];
            u0r[n] = 0.5f * (a + c2); u0i[n] = 0.5f * (b - d);
            u1r[n] = 0.5f * (b + d);  u1i[n] = 0.5f * (c2 - a);
        }
    }
    __syncthreads();
    #pragma unroll
    for (int n = 0; n < 9; n++) {
        int it = tid + n * NT_F;
        if (it < 64 * 65) {
            int k = it % 65, p = it / 65;
            int h0 = brev7(2 * p), h1 = brev7(2 * p + 1);
            R[h0 * CPIT + k] = u0r[n]; I[h0 * CPIT + k] = u0i[n];
            R[h1 * CPIT + k] = u1r[n]; I[h1 * CPIT + k] = u1i[n];
        }
    }
    __syncthreads();

    pass4_cols<1>(R, I, twR, twI); __syncthreads();
    pass4_cols<3>(R, I, twR, twI); __syncthreads();
    pass4_cols<5>(R, I, twR, twI); __syncthreads();
    pass2_cols   (R, I, twR, twI); __syncthreads();

    float* dR = g_specR + (size_t)img * F_;
    float* dI = g_specI + (size_t)img * F_;
    const float sc = 1.0f / 128.0f;
    for (int t = tid; t < F_; t += NT_F) {
        dR[t] = R[t] * sc;
        dI[t] = I[t] * sc;
    }
}

// ---------------------------------------------------------------------------
// Tensor-core mixer: 512 threads / 16 warps, warp tile m16 x n16.
// ---------------------------------------------------------------------------
__device__ __forceinline__ void mma16816(float* d, const uint32_t* a, const uint32_t* b) {
    asm volatile("mma.sync.aligned.m16n8k16.row.col.f32.bf16.bf16.f32 "
        "{%0,%1,%2,%3}, {%4,%5,%6,%7}, {%8,%9}, {%0,%1,%2,%3};"
        : "+f"(d[0]), "+f"(d[1]), "+f"(d[2]), "+f"(d[3])
        : "r"(a[0]), "r"(a[1]), "r"(a[2]), "r"(a[3]), "r"(b[0]), "r"(b[1]));
}

__device__ __forceinline__ void ldA(uint32_t* a, const unsigned short* Wp,
                                    int row, int k0, int tig) {
    const unsigned short* p = Wp + row * WP + k0 + tig * 2;
    a[0] = *(const uint32_t*)p;
    a[1] = *(const uint32_t*)(p + 8 * WP);
    a[2] = *(const uint32_t*)(p + 8);
    a[3] = *(const uint32_t*)(p + 8 * WP + 8);
}
__device__ __forceinline__ void ldB(uint32_t* bb, const unsigned short* Xp,
                                    int row, int k0, int tig) {
    const unsigned short* p = Xp + row * WP + k0 + tig * 2;
    bb[0] = *(const uint32_t*)p;
    bb[1] = *(const uint32_t*)(p + 8);
}

// warp tile m16 (warp_m = (wid&7)*16) x n16 (warp_n = (wid>>3)*16, 2 x n8)
__device__ __forceinline__ void gemm32(const unsigned short* smW,
                                       const unsigned short* smX,
                                       float* aOr, float* aP, float* aOi,
                                       int warp_m, int warp_n, int gid, int tig) {
    #pragma unroll 1
    for (int kk = 0; kk < 8; kk++) {
        const int k0 = kk * 16;
        uint32_t A[4][4];
        #pragma unroll
        for (int pl = 0; pl < 4; pl++)
            ldA(A[pl], smW + pl * PLW, warp_m + gid, k0, tig);
        uint32_t Bf[4][2][2];
        #pragma unroll
        for (int pl = 0; pl < 4; pl++)
            #pragma unroll
            for (int nt = 0; nt < 2; nt++)
                ldB(Bf[pl][nt], smX + pl * PLX32, warp_n + nt * 8 + gid, k0, tig);
        #pragma unroll
        for (int nt = 0; nt < 2; nt++) {
            float* dOr = aOr + nt * 4;
            float* dP  = aP  + nt * 4;
            float* dOi = aOi + nt * 4;
            mma16816(dOr, A[0], Bf[0][nt]);   // WrH*XrH
            mma16816(dOr, A[1], Bf[0][nt]);   // WrL*XrH
            mma16816(dOr, A[0], Bf[1][nt]);   // WrH*XrL
            mma16816(dP,  A[2], Bf[2][nt]);   // WiH*XiH
            mma16816(dP,  A[3], Bf[2][nt]);   // WiL*XiH
            mma16816(dP,  A[2], Bf[3][nt]);   // WiH*XiL
            mma16816(dOi, A[2], Bf[0][nt]);   // WiH*XrH
            mma16816(dOi, A[3], Bf[0][nt]);   // WiL*XrH
            mma16816(dOi, A[2], Bf[1][nt]);   // WiH*XrL
            mma16816(dOi, A[0], Bf[2][nt]);   // WrH*XiH
            mma16816(dOi, A[1], Bf[2][nt]);   // WrL*XiH
            mma16816(dOi, A[0], Bf[3][nt]);   // WrH*XiL
        }
    }
}

__device__ __forceinline__ void chunk_range(int c, int& start, int& cnt) {
    start = c * 29;
    cnt   = (c == 8) ? 28 : 29;
}

// L1 smem: W planes | X planes | raw staging
#define L1_OFF_X   (4 * PLW * 2)                     // 139264
#define L1_OFF_RAW (L1_OFF_X + 4 * PLX32 * 2)        // 174080
#define SM_L1      (L1_OFF_RAW + 2 * 128 * RPITCH * 4)  // 210944
// L2 smem: W planes | 2x X plane buffers
#define L2_OFF_X   (4 * PLW * 2)
#define SM_L2      (L2_OFF_X + 2 * 4 * PLX32 * 2)       // 208896

// ================= Layer 1 kernel =================
__global__ void __launch_bounds__(NT_M, 1)
kmixL1(const float* __restrict__ b1) {
    extern __shared__ char smem[];
    unsigned short* smW = (unsigned short*)smem;
    unsigned short* smX = (unsigned short*)(smem + L1_OFF_X);
    float*          raw = (float*)(smem + L1_OFF_RAW);
    const uint32_t raw_u32 = smem_u32(raw);

    const int tid = threadIdx.x;
    const int wid = tid >> 5, lane = tid & 31;
    const int gid = lane >> 2, tig = lane & 3;
    const int warp_m = (wid & 7) * 16;
    const int warp_n = (wid >> 3) * 16;
    const int bg = blockIdx.x;
    const int b = bg >> 2, g = bg & 3;
    int start, cnt;
    chunk_range(blockIdx.y, start, cnt);
    const int end = start + cnt;

    const size_t chanbase = ((size_t)b * C_ + (size_t)g * D_) * F_;

    // prefetch first tile raw spec (async)
    {
        for (int i = tid; i < 2048; i += NT_M) {
            int pl = i >> 10, rem = i & 1023, c = rem >> 3, seg = rem & 7;
            const float* src = (pl ? g_specI : g_specR) + chanbase + (size_t)c * F_
                             + (size_t)start * 32 + seg * 4;
            uint32_t dst = raw_u32 + (uint32_t)(pl * (128 * RPITCH * 4) + c * (RPITCH * 4) + seg * 16);
            CP_ASYNC16(dst, src);
        }
        CP_COMMIT();
    }

    // W1 planes: once per CTA
    {
        const float4* ws = (const float4*)(g_wimg + (size_t)(0 * 4 + g) * 4 * PLW);
        float4* wd = (float4*)smW;
        for (int i = tid; i < 4 * PLW / 8; i += NT_M) wd[i] = ws[i];
    }

    // bias values (fixed rows per warp)
    const int r0 = warp_m + gid;
    const float br0  = b1[g * D_ + r0];
    const float br1_ = b1[g * D_ + r0 + 8];
    const float bi0  = b1[(G_ + g) * D_ + r0];
    const float bi1_ = b1[(G_ + g) * D_ + r0 + 8];

    for (int t = start; t < end; t++) {
        CP_WAIT0();
        __syncthreads();

        // convert raw -> X planes (split); 4096 elems / 512 threads
        #pragma unroll
        for (int n = 0; n < 8; n++) {
            int it = tid + n * NT_M;
            int c = it >> 5, f = it & 31;
            float vr = raw[c * RPITCH + f];
            float vi = raw[128 * RPITCH + c * RPITCH + f];
            unsigned short rh, rl, ih, il;
            split_bf16(vr, rh, rl);
            split_bf16(vi, ih, il);
            int o = f * WP + c;
            smX[o] = rh; smX[PLX32 + o] = rl;
            smX[2 * PLX32 + o] = ih; smX[3 * PLX32 + o] = il;
        }
        __syncthreads();

        // prefetch next tile raw (overlaps GEMM)
        if (t + 1 < end) {
            for (int i = tid; i < 2048; i += NT_M) {
                int pl = i >> 10, rem = i & 1023, c = rem >> 3, seg = rem & 7;
                const float* src = (pl ? g_specI : g_specR) + chanbase + (size_t)c * F_
                                 + (size_t)(t + 1) * 32 + seg * 4;
                uint32_t dst = raw_u32 + (uint32_t)(pl * (128 * RPITCH * 4) + c * (RPITCH * 4) + seg * 16);
                CP_ASYNC16(dst, src);
            }
            CP_COMMIT();
        }

        float aOr[8], aP[8], aOi[8];
        #pragma unroll
        for (int i = 0; i < 8; i++) { aOr[i] = 0.f; aP[i] = 0.f; aOi[i] = 0.f; }
        gemm32(smW, smX, aOr, aP, aOi, warp_m, warp_n, gid, tig);
        __syncthreads();

        // epilogue: bias + relu, split, write O1 planes back into smX
        #pragma unroll
        for (int nt = 0; nt < 2; nt++) {
            int c0 = warp_n + nt * 8 + tig * 2;
            int ai = nt * 4;
            #pragma unroll
            for (int e = 0; e < 4; e++) {
                int row = (e >= 2) ? r0 + 8 : r0;
                int col = c0 + (e & 1);
                float brv = (e >= 2) ? br1_ : br0;
                float biv = (e >= 2) ? bi1_ : bi0;
                float vr = aOr[ai + e] - aP[ai + e] + brv; vr = vr > 0.f ? vr : 0.f;
                float vi = aOi[ai + e] + biv;              vi = vi > 0.f ? vi : 0.f;
                unsigned short rh, rl, ih, il;
                split_bf16(vr, rh, rl);
                split_bf16(vi, ih, il);
                int o = col * WP + row;
                smX[o] = rh; smX[PLX32 + o] = rl;
                smX[2 * PLX32 + o] = ih; smX[3 * PLX32 + o] = il;
            }
        }
        __syncthreads();

        // coalesced copy-out smX planes -> g_o1: 4 planes x 32 f x 16 uint4
        {
            uint4* dst = (uint4*)(g_o1 + ((size_t)bg * NTILE + t) * 16384);
            for (int i = tid; i < 2048; i += NT_M) {
                int pl = i >> 9, rem = i & 511, f = rem >> 4, c16 = rem & 15;
                dst[i] = *(const uint4*)(smX + pl * PLX32 + f * WP + c16 * 8);
            }
        }
    }
}

// ================= Layer 2 kernel =================
__global__ void __launch_bounds__(NT_M, 1)
kmixL2(const float* __restrict__ b2) {
    extern __shared__ char smem[];
    unsigned short* smW  = (unsigned short*)smem;
    unsigned short* smX0 = (unsigned short*)(smem + L2_OFF_X);

    const int tid = threadIdx.x;
    const int wid = tid >> 5, lane = tid & 31;
    const int gid = lane >> 2, tig = lane & 3;
    const int warp_m = (wid & 7) * 16;
    const int warp_n = (wid >> 3) * 16;
    const int bg = blockIdx.x;
    const int b = bg >> 2, g = bg & 3;
    int start, cnt;
    chunk_range(blockIdx.y, start, cnt);
    const int end = start + cnt;

    const size_t chanbase = ((size_t)b * C_ + (size_t)g * D_) * F_;

    // prefetch first tile O1 planes into buf0
    {
        const uint4* src = (const uint4*)(g_o1 + ((size_t)bg * NTILE + start) * 16384);
        uint32_t bufb = smem_u32(smX0);
        for (int i = tid; i < 2048; i += NT_M) {
            int pl = i >> 9, rem = i & 511, f = rem >> 4, c16 = rem & 15;
            uint32_t dst = bufb + (uint32_t)((pl * PLX32 + f * WP) * 2 + c16 * 16);
            CP_ASYNC16(dst, src + i);
        }
        CP_COMMIT();
    }

    // W2 planes
    {
        const float4* ws = (const float4*)(g_wimg + (size_t)(1 * 4 + g) * 4 * PLW);
        float4* wd = (float4*)smW;
        for (int i = tid; i < 4 * PLW / 8; i += NT_M) wd[i] = ws[i];
    }

    const int r0 = warp_m + gid;
    const float br0  = b2[g * D_ + r0];
    const float br1_ = b2[g * D_ + r0 + 8];
    const float bi0  = b2[(G_ + g) * D_ + r0];
    const float bi1_ = b2[(G_ + g) * D_ + r0 + 8];

    for (int t = start; t < end; t++) {
        unsigned short* buf = smX0 + ((t - start) & 1) * (4 * PLX32);
        CP_WAIT0();
        __syncthreads();

        // prefetch next tile into other buffer (overlaps GEMM)
        if (t + 1 < end) {
            unsigned short* nb = smX0 + (((t - start) + 1) & 1) * (4 * PLX32);
            const uint4* src = (const uint4*)(g_o1 + ((size_t)bg * NTILE + (t + 1)) * 16384);
            uint32_t bufb = smem_u32(nb);
            for (int i = tid; i < 2048; i += NT_M) {
                int pl = i >> 9, rem = i & 511, f = rem >> 4, c16 = rem & 15;
                uint32_t dst = bufb + (uint32_t)((pl * PLX32 + f * WP) * 2 + c16 * 16);
                CP_ASYNC16(dst, src + i);
            }
            CP_COMMIT();
        }

        // prefetch origin spec values into registers (consumed in epilogue)
        float2 oxr[4], oxi[4];
        #pragma unroll
        for (int nt = 0; nt < 2; nt++)
            #pragma unroll
            for (int rp = 0; rp < 2; rp++) {
                int row = r0 + rp * 8;
                int c0  = warp_n + nt * 8 + tig * 2;
                size_t gi = chanbase + (size_t)row * F_ + (size_t)t * 32 + c0;
                int idx = nt * 2 + rp;
                oxr[idx] = *(const float2*)&g_specR[gi];
                oxi[idx] = *(const float2*)&g_specI[gi];
            }

        float aOr[8], aP[8], aOi[8];
        #pragma unroll
        for (int i = 0; i < 8; i++) { aOr[i] = 0.f; aP[i] = 0.f; aOi[i] = 0.f; }
        gemm32(smW, buf, aOr, aP, aOi, warp_m, warp_n, gid, tig);

        // epilogue: bias, multiply by origin, store
        #pragma unroll
        for (int nt = 0; nt < 2; nt++) {
            int c0 = warp_n + nt * 8 + tig * 2;
            int ai = nt * 4;
            #pragma unroll
            for (int rp = 0; rp < 2; rp++) {
                int row = r0 + rp * 8;
                float brv = rp ? br1_ : br0;
                float biv = rp ? bi1_ : bi0;
                int idx = nt * 2 + rp;
                float2 xr = oxr[idx], xi = oxi[idx];
                size_t gi = chanbase + (size_t)row * F_ + (size_t)t * 32 + c0;
                float vr0 = aOr[ai + rp * 2]     - aP[ai + rp * 2]     + brv;
                float vi0 = aOi[ai + rp * 2]     + biv;
                float vr1 = aOr[ai + rp * 2 + 1] - aP[ai + rp * 2 + 1] + brv;
                float vi1 = aOi[ai + rp * 2 + 1] + biv;
                float2 orv, oiv;
                orv.x = vr0 * xr.x - vi0 * xi.x;
                oiv.x = vr0 * xi.x + vi0 * xr.x;
                orv.y = vr1 * xr.y - vi1 * xi.y;
                oiv.y = vr1 * xi.y + vi1 * xr.y;
                *(float2*)&g_outR[gi] = orv;
                *(float2*)&g_outI[gi] = oiv;
            }
        }
    }
}

// ---------------------------------------------------------------------------
__global__ void __launch_bounds__(NT_F, 2) kfft_inv(float* __restrict__ y) {
    extern __shared__ float sm[];
    float* R   = sm;
    float* I   = sm + UBUF;
    float* twR = sm + 2 * UBUF;
    float* twI = twR + 64;

    const int tid = threadIdx.x;
    const int img = blockIdx.x;

    if (tid < 64) {
        float s, c;
        sincospif((float)tid / 64.0f, &s, &c);
        twR[tid] = c; twI[tid] = s;
    }

    const float* srcR = g_outR + (size_t)img * F_;
    const float* srcI = g_outI + (size_t)img * F_;
    for (int t = tid; t < F_; t += NT_F) {
        int h = t / WF_, k = t - h * WF_;
        int hb = brev7(h);
        R[hb * CPIT + k] = srcR[t];
        I[hb * CPIT + k] = srcI[t];
    }
    __syncthreads();

    pass4_cols<1>(R, I, twR, twI); __syncthreads();
    pass4_cols<3>(R, I, twR, twI); __syncthreads();
    pass4_cols<5>(R, I, twR, twI); __syncthreads();
    pass2_cols   (R, I, twR, twI); __syncthreads();

    float zr[16], zi[16];
    #pragma unroll
    for (int n = 0; n < 16; n++) {
        int it = tid + n * NT_F;
        int w = it & 127, p = it >> 7;
        int r0 = (2 * p) * CPIT, r1 = r0 + CPIT;
        if (w <= 64) {
            float x0r = R[r0 + w], x0i = I[r0 + w];
            float x1r = R[r1 + w], x1i = I[r1 + w];
            if (w == 0 || w == 64) { x0i = 0.f; x1i = 0.f; }
            zr[n] = x0r - x1i;
            zi[n] = x0i + x1r;
        } else {
            int m = 128 - w;
            float x0r = R[r0 + m], x0i = I[r0 + m];
            float x1r = R[r1 + m], x1i = I[r1 + m];
            zr[n] = x0r + x1i;
            zi[n] = x1r - x0i;
        }
    }
    __syncthreads();
    #pragma unroll
    for (int n = 0; n < 16; n++) {
        int it = tid + n * NT_F;
        int w = it & 127, p = it >> 7;
        int wb = brev7(w);
        R[p * RPIT + wb] = zr[n];
        I[p * RPIT + wb] = zi[n];
    }
    __syncthreads();

    pass4_rows<1>(R, I, twR, twI); __syncthreads();
    pass4_rows<3>(R, I, twR, twI); __syncthreads();
    pass4_rows<5>(R, I, twR, twI); __syncthreads();
    pass2_rows   (R, I, twR, twI); __syncthreads();

    float* dst = y + (size_t)img * (H_ * W_);
    const float sc = 1.0f / 128.0f;
    for (int t = tid; t < 64 * 128; t += NT_F) {
        int p = t >> 7, c = t & 127;
        dst[(2 * p) * 128 + c]       = R[p * RPIT + c] * sc;
        dst[(2 * p) * 128 + 128 + c] = I[p * RPIT + c] * sc;
    }
}

// ---------------------------------------------------------------------------
extern "C" void kernel_launch(void* const* d_in, const int* in_sizes, int n_in,
                              void* d_out, int out_size) {
    const float* x  = (const float*)d_in[0];
    const float* w1 = (const float*)d_in[1];
    const float* w2 = (const float*)d_in[2];
    const float* b1 = (const float*)d_in[3];
    const float* b2 = (const float*)d_in[4];
    float* y = (float*)d_out;

    const int smFFT = (2 * UBUF + 128) * (int)sizeof(float);   // ~65.5 KB

    cudaFuncSetAttribute(kfft_fwd, cudaFuncAttributeMaxDynamicSharedMemorySize, smFFT);
    cudaFuncSetAttribute(kmixL1,   cudaFuncAttributeMaxDynamicSharedMemorySize, SM_L1);
    cudaFuncSetAttribute(kmixL2,   cudaFuncAttributeMaxDynamicSharedMemorySize, SM_L2);
    cudaFuncSetAttribute(kfft_inv, cudaFuncAttributeMaxDynamicSharedMemorySize, smFFT);

    wprep<<<1024, 256>>>(w1, w2);
    kfft_fwd<<<NIMG, NT_F, smFFT>>>(x);
    kmixL1<<<dim3(32, NCHUNK), NT_M, SM_L1>>>(b1);
    kmixL2<<<dim3(32, NCHUNK), NT_M, SM_L2>>>(b2);
    kfft_inv<<<NIMG, NT_F, smFFT>>>(y);
}

// round 12
// speedup vs baseline: 1.1759x; 1.0251x over previous
#include <cuda_runtime.h>
#include <cuda_bf16.h>
#include <math.h>
#include <stdint.h>

#define B_   8
#define C_   512
#define G_   4
#define D_   128
#define H_   128
#define W_   128
#define WF_  65
#define F_   (H_*WF_)        // 8320
#define NIMG (B_*C_)         // 4096

// Scratch (allocation-free requirement -> device globals).
static __device__ float g_specR[(size_t)NIMG * F_];
static __device__ float g_specI[(size_t)NIMG * F_];
static __device__ float g_outR [(size_t)NIMG * F_];
static __device__ float g_outI [(size_t)NIMG * F_];
static __device__ unsigned short g_wimg[32 * 128 * 136];            // pre-split W planes
static __device__ unsigned short g_o1[(size_t)32 * 260 * 16384];    // O1 planes (~273MB)

#define RPIT 129
#define CPIT 65
#define UBUF 8320
#define NT_F 512

#define WP    136           // bf16 plane pitch (shorts)
#define PLW   (128 * WP)    // W plane elems (17408)
#define PLX32 (32 * WP)     // X plane elems, N=32 tile (4352)
#define NTILE 260           // 8320 / 32
#define NCHUNK 9
#define RPITCH 36           // raw staging pitch (floats)
#define NT_M  512           // mixer threads (16 warps)

__device__ __forceinline__ int brev7(int v) { return (int)(__brev((unsigned)v) >> 25); }

__device__ __forceinline__ void split_bf16(float v, unsigned short& h, unsigned short& l) {
    __nv_bfloat16 hb = __float2bfloat16(v);
    float r = v - __bfloat162float(hb);
    h = __bfloat16_as_ushort(hb);
    l = __bfloat16_as_ushort(__float2bfloat16(r));
}

__device__ __forceinline__ uint32_t smem_u32(const void* p) {
    uint32_t a;
    asm("{ .reg .u64 t; cvta.to.shared.u64 t, %1; cvt.u32.u64 %0, t; }" : "=r"(a) : "l"(p));
    return a;
}
#define CP_ASYNC16(dst, src) \
    asm volatile("cp.async.cg.shared.global [%0], [%1], 16;" :: "r"(dst), "l"(src))
#define CP_COMMIT() asm volatile("cp.async.commit_group;" ::: "memory")
#define CP_WAIT0()  asm volatile("cp.async.wait_group 0;"  ::: "memory")

#define LDSM_X4(r, addr) \
    asm volatile("ldmatrix.sync.aligned.m8n8.x4.shared.b16 {%0,%1,%2,%3}, [%4];" \
        : "=r"((r)[0]), "=r"((r)[1]), "=r"((r)[2]), "=r"((r)[3]) : "r"(addr))

// ---------------------------------------------------------------------------
// Weight prep
// ---------------------------------------------------------------------------
__global__ void __launch_bounds__(256) wprep(const float* __restrict__ w1,
                                             const float* __restrict__ w2) {
    int idx = blockIdx.x * 256 + threadIdx.x;      // 262144
    int m    = idx & 127;
    int k    = (idx >> 7) & 127;
    int part = (idx >> 14) & 1;
    int g    = (idx >> 15) & 3;
    int l    = (idx >> 17) & 1;
    const float* src = l ? w2 : w1;
    float v = src[(((size_t)(part * 4 + g) * 128 + k) * 128) + m];
    unsigned short h, lo;
    split_bf16(v, h, lo);
    size_t base = (size_t)((l * 4 + g) * 4 + part * 2) * PLW;
    g_wimg[base + m * WP + k]       = h;
    g_wimg[base + PLW + m * WP + k] = lo;
}

// ============================ FFT passes (unchanged) ========================
template<int S>
__device__ __forceinline__ void pass4_rows(float* R, float* I,
                                           const float* twR, const float* twI) {
    const int h = 1 << (S - 1);
    for (int it = threadIdx.x; it < 64 * 32; it += NT_F) {
        int r = it & 63, q = it >> 6;
        int j = q & (h - 1);
        int base = (q >> (S - 1)) << (S + 1);
        int i0 = r * RPIT + base + j;
        float e0r = R[i0],       e0i = I[i0];
        float e1r = R[i0 + h],   e1i = I[i0 + h];
        float e2r = R[i0 + 2*h], e2i = I[i0 + 2*h];
        float e3r = R[i0 + 3*h], e3i = I[i0 + 3*h];
        float w1r = twR[j << (7-S)], w1i = twI[j << (7-S)];
        float w2r = twR[j << (6-S)], w2i = twI[j << (6-S)];
        float w3r = twR[(j+h) << (6-S)], w3i = twI[(j+h) << (6-S)];
        float tr = e1r*w1r - e1i*w1i, ti = e1r*w1i + e1i*w1r;
        float A0r = e0r + tr, A0i = e0i + ti, A1r = e0r - tr, A1i = e0i - ti;
        tr = e3r*w1r - e3i*w1i; ti = e3r*w1i + e3i*w1r;
        float A2r = e2r + tr, A2i = e2i + ti, A3r = e2r - tr, A3i = e2i - ti;
        tr = A2r*w2r - A2i*w2i; ti = A2r*w2i + A2i*w2r;
        R[i0]       = A0r + tr; I[i0]       = A0i + ti;
        R[i0 + 2*h] = A0r - tr; I[i0 + 2*h] = A0i - ti;
        tr = A3r*w3r - A3i*w3i; ti = A3r*w3i + A3i*w3r;
        R[i0 + h]   = A1r + tr; I[i0 + h]   = A1i + ti;
        R[i0 + 3*h] = A1r - tr; I[i0 + 3*h] = A1i - ti;
    }
}

__device__ __forceinline__ void pass2_rows(float* R, float* I,
                                           const float* twR, const float* twI) {
    for (int it = threadIdx.x; it < 64 * 64; it += NT_F) {
        int r = it & 63, j = it >> 6;
        int i0 = r * RPIT + j, i1 = i0 + 64;
        float wr = twR[j], wi = twI[j];
        float ar = R[i0], ai = I[i0], br = R[i1], bi = I[i1];
        float tr = br*wr - bi*wi, ti = br*wi + bi*wr;
        R[i0] = ar + tr; I[i0] = ai + ti;
        R[i1] = ar - tr; I[i1] = ai - ti;
    }
}

template<int S>
__device__ __forceinline__ void pass4_cols(float* R, float* I,
                                           const float* twR, const float* twI) {
    const int h = 1 << (S - 1);
    const int st = h * CPIT;
    for (int it = threadIdx.x; it < 65 * 32; it += NT_F) {
        int c = it % 65, q = it / 65;
        int j = q & (h - 1);
        int base = (q >> (S - 1)) << (S + 1);
        int i0 = (base + j) * CPIT + c;
        float e0r = R[i0],        e0i = I[i0];
        float e1r = R[i0 + st],   e1i = I[i0 + st];
        float e2r = R[i0 + 2*st], e2i = I[i0 + 2*st];
        float e3r = R[i0 + 3*st], e3i = I[i0 + 3*st];
        float w1r = twR[j << (7-S)], w1i = twI[j << (7-S)];
        float w2r = twR[j << (6-S)], w2i = twI[j << (6-S)];
        float w3r = twR[(j+h) << (6-S)], w3i = twI[(j+h) << (6-S)];
        float tr = e1r*w1r - e1i*w1i, ti = e1r*w1i + e1i*w1r;
        float A0r = e0r + tr, A0i = e0i + ti, A1r = e0r - tr, A1i = e0i - ti;
        tr = e3r*w1r - e3i*w1i; ti = e3r*w1i + e3i*w1r;
        float A2r = e2r + tr, A2i = e2i + ti, A3r = e2r - tr, A3i = e2i - ti;
        tr = A2r*w2r - A2i*w2i; ti = A2r*w2i + A2i*w2r;
        R[i0]        = A0r + tr; I[i0]        = A0i + ti;
        R[i0 + 2*st] = A0r - tr; I[i0 + 2*st] = A0i - ti;
        tr = A3r*w3r - A3i*w3i; ti = A3r*w3i + A3i*w3r;
        R[i0 + st]   = A1r + tr; I[i0 + st]   = A1i + ti;
        R[i0 + 3*st] = A1r - tr; I[i0 + 3*st] = A1i - ti;
    }
}

__device__ __forceinline__ void pass2_cols(float* R, float* I,
                                           const float* twR, const float* twI) {
    for (int it = threadIdx.x; it < 65 * 64; it += NT_F) {
        int c = it % 65, j = it / 65;
        int i0 = j * CPIT + c, i1 = i0 + 64 * CPIT;
        float wr = twR[j], wi = twI[j];
        float ar = R[i0], ai = I[i0], br = R[i1], bi = I[i1];
        float tr = br*wr - bi*wi, ti = br*wi + bi*wr;
        R[i0] = ar + tr; I[i0] = ai + ti;
        R[i1] = ar - tr; I[i1] = ai - ti;
    }
}

__global__ void __launch_bounds__(NT_F, 2) kfft_fwd(const float* __restrict__ x) {
    extern __shared__ float sm[];
    float* R   = sm;
    float* I   = sm + UBUF;
    float* twR = sm + 2 * UBUF;
    float* twI = twR + 64;

    const int tid = threadIdx.x;
    const int img = blockIdx.x;

    if (tid < 64) {
        float s, c;
        sincospif(-(float)tid / 64.0f, &s, &c);
        twR[tid] = c; twI[tid] = s;
    }

    const float* src = x + (size_t)img * (H_ * W_);
    for (int t = tid; t < 64 * 128; t += NT_F) {
        int p = t >> 7, c = t & 127;
        int cb = brev7(c);
        R[p * RPIT + cb] = src[(2 * p) * 128 + c];
        I[p * RPIT + cb] = src[(2 * p) * 128 + 128 + c];
    }
    __syncthreads();

    pass4_rows<1>(R, I, twR, twI); __syncthreads();
    pass4_rows<3>(R, I, twR, twI); __syncthreads();
    pass4_rows<5>(R, I, twR, twI); __syncthreads();
    pass2_rows   (R, I, twR, twI); __syncthreads();

    float u0r[9], u0i[9], u1r[9], u1i[9];
    #pragma unroll
    for (int n = 0; n < 9; n++) {
        int it = tid + n * NT_F;
        if (it < 64 * 65) {
            int k = it % 65, p = it / 65;
            int m = (128 - k) & 127;
            float a = R[p * RPIT + k], b = I[p * RPIT + k];
            float c2 = R[p * RPIT + m], d = I[p * RPIT + m];
            u0r[n] = 0.5f * (a + c2); u0i[n] = 0.5f * (b - d);
            u1r[n] = 0.5f * (b + d);  u1i[n] = 0.5f * (c2 - a);
        }
    }
    __syncthreads();
    #pragma unroll
    for (int n = 0; n < 9; n++) {
        int it = tid + n * NT_F;
        if (it < 64 * 65) {
            int k = it % 65, p = it / 65;
            int h0 = brev7(2 * p), h1 = brev7(2 * p + 1);
            R[h0 * CPIT + k] = u0r[n]; I[h0 * CPIT + k] = u0i[n];
            R[h1 * CPIT + k] = u1r[n]; I[h1 * CPIT + k] = u1i[n];
        }
    }
    __syncthreads();

    pass4_cols<1>(R, I, twR, twI); __syncthreads();
    pass4_cols<3>(R, I, twR, twI); __syncthreads();
    pass4_cols<5>(R, I, twR, twI); __syncthreads();
    pass2_cols   (R, I, twR, twI); __syncthreads();

    float* dR = g_specR + (size_t)img * F_;
    float* dI = g_specI + (size_t)img * F_;
    const float sc = 1.0f / 128.0f;
    for (int t = tid; t < F_; t += NT_F) {
        dR[t] = R[t] * sc;
        dI[t] = I[t] * sc;
    }
}

// ---------------------------------------------------------------------------
// Tensor-core mixer: 512 threads / 16 warps, warp tile m16 x n16, LDSM loads.
// ---------------------------------------------------------------------------
__device__ __forceinline__ void mma16816(float* d, const uint32_t* a, const uint32_t* b) {
    asm volatile("mma.sync.aligned.m16n8k16.row.col.f32.bf16.bf16.f32 "
        "{%0,%1,%2,%3}, {%4,%5,%6,%7}, {%8,%9}, {%0,%1,%2,%3};"
        : "+f"(d[0]), "+f"(d[1]), "+f"(d[2]), "+f"(d[3])
        : "r"(a[0]), "r"(a[1]), "r"(a[2]), "r"(a[3]), "r"(b[0]), "r"(b[1]));
}

// warp tile m16 (warp_m = (wid&7)*16) x n16 (warp_n = (wid>>3)*16, 2 x n8)
// LDSM x4: A = m16k16 fragment; B = n16k16 covering both nt sub-tiles.
__device__ __forceinline__ void gemm32(uint32_t smW_a, uint32_t smX_a,
                                       float* aOr, float* aP, float* aOi,
                                       int warp_m, int warp_n, int lane) {
    // A lane->address: lanes 0-7 m0 rows +0..7 k0; 8-15 m1 rows +8..15 k0;
    //                  16-23 m2 rows +0..7 k0+8; 24-31 m3 rows +8..15 k0+8.
    const uint32_t aOff = (uint32_t)((warp_m + (lane & 15)) * WP + ((lane >> 4) << 3)) * 2;
    // B lane->address: m0 rows n+0..7 k0 | m1 rows n+0..7 k0+8 |
    //                  m2 rows n+8..15 k0 | m3 rows n+8..15 k0+8.
    const uint32_t bOff = (uint32_t)((warp_n + ((lane >> 4) << 3) + (lane & 7)) * WP
                                     + (((lane >> 3) & 1) << 3)) * 2;
    #pragma unroll 1
    for (int kk = 0; kk < 8; kk++) {
        const uint32_t k0b = (uint32_t)kk * 32;   // k0 * 2 bytes
        uint32_t A[4][4];
        #pragma unroll
        for (int pl = 0; pl < 4; pl++)
            LDSM_X4(A[pl], smW_a + (uint32_t)pl * (PLW * 2) + aOff + k0b);
        uint32_t Bf[4][4];                         // [pl][nt*2 + {b0,b1}]
        #pragma unroll
        for (int pl = 0; pl < 4; pl++)
            LDSM_X4(Bf[pl], smX_a + (uint32_t)pl * (PLX32 * 2) + bOff + k0b);
        #pragma unroll
        for (int nt = 0; nt < 2; nt++) {
            float* dOr = aOr + nt * 4;
            float* dP  = aP  + nt * 4;
            float* dOi = aOi + nt * 4;
            const uint32_t* bR = &Bf[0][nt * 2];   // XrH
            const uint32_t* bRl = &Bf[1][nt * 2];  // XrL
            const uint32_t* bI = &Bf[2][nt * 2];   // XiH
            const uint32_t* bIl = &Bf[3][nt * 2];  // XiL
            mma16816(dOr, A[0], bR);    // WrH*XrH
            mma16816(dOr, A[1], bR);    // WrL*XrH
            mma16816(dOr, A[0], bRl);   // WrH*XrL
            mma16816(dP,  A[2], bI);    // WiH*XiH
            mma16816(dP,  A[3], bI);    // WiL*XiH
            mma16816(dP,  A[2], bIl);   // WiH*XiL
            mma16816(dOi, A[2], bR);    // WiH*XrH
            mma16816(dOi, A[3], bR);    // WiL*XrH
            mma16816(dOi, A[2], bRl);   // WiH*XrL
            mma16816(dOi, A[0], bI);    // WrH*XiH
            mma16816(dOi, A[1], bI);    // WrL*XiH
            mma16816(dOi, A[0], bIl);   // WrH*XiL
        }
    }
}

__device__ __forceinline__ void chunk_range(int c, int& start, int& cnt) {
    start = c * 29;
    cnt   = (c == 8) ? 28 : 29;
}

// L1 smem: W planes | X planes | raw staging
#define L1_OFF_X   (4 * PLW * 2)                     // 139264
#define L1_OFF_RAW (L1_OFF_X + 4 * PLX32 * 2)        // 174080
#define SM_L1      (L1_OFF_RAW + 2 * 128 * RPITCH * 4)  // 210944
// L2 smem: W planes | 2x X plane buffers
#define L2_OFF_X   (4 * PLW * 2)
#define SM_L2      (L2_OFF_X + 2 * 4 * PLX32 * 2)       // 208896

// ================= Layer 1 kernel =================
__global__ void __launch_bounds__(NT_M, 1)
kmixL1(const float* __restrict__ b1) {
    extern __shared__ char smem[];
    unsigned short* smW = (unsigned short*)smem;
    unsigned short* smX = (unsigned short*)(smem + L1_OFF_X);
    float*          raw = (float*)(smem + L1_OFF_RAW);
    const uint32_t raw_u32 = smem_u32(raw);
    const uint32_t smW_a = smem_u32(smW);
    const uint32_t smX_a = smem_u32(smX);

    const int tid = threadIdx.x;
    const int wid = tid >> 5, lane = tid & 31;
    const int gid = lane >> 2, tig = lane & 3;
    const int warp_m = (wid & 7) * 16;
    const int warp_n = (wid >> 3) * 16;
    const int bg = blockIdx.x;
    const int b = bg >> 2, g = bg & 3;
    int start, cnt;
    chunk_range(blockIdx.y, start, cnt);
    const int end = start + cnt;

    const size_t chanbase = ((size_t)b * C_ + (size_t)g * D_) * F_;

    // prefetch first tile raw spec (async)
    {
        for (int i = tid; i < 2048; i += NT_M) {
            int pl = i >> 10, rem = i & 1023, c = rem >> 3, seg = rem & 7;
            const float* src = (pl ? g_specI : g_specR) + chanbase + (size_t)c * F_
                             + (size_t)start * 32 + seg * 4;
            uint32_t dst = raw_u32 + (uint32_t)(pl * (128 * RPITCH * 4) + c * (RPITCH * 4) + seg * 16);
            CP_ASYNC16(dst, src);
        }
        CP_COMMIT();
    }

    // W1 planes: once per CTA
    {
        const float4* ws = (const float4*)(g_wimg + (size_t)(0 * 4 + g) * 4 * PLW);
        float4* wd = (float4*)smW;
        for (int i = tid; i < 4 * PLW / 8; i += NT_M) wd[i] = ws[i];
    }

    // bias values (fixed rows per warp)
    const int r0 = warp_m + gid;
    const float br0  = b1[g * D_ + r0];
    const float br1_ = b1[g * D_ + r0 + 8];
    const float bi0  = b1[(G_ + g) * D_ + r0];
    const float bi1_ = b1[(G_ + g) * D_ + r0 + 8];

    for (int t = start; t < end; t++) {
        CP_WAIT0();
        __syncthreads();

        // convert raw -> X planes (split); 4096 elems / 512 threads
        #pragma unroll
        for (int n = 0; n < 8; n++) {
            int it = tid + n * NT_M;
            int c = it >> 5, f = it & 31;
            float vr = raw[c * RPITCH + f];
            float vi = raw[128 * RPITCH + c * RPITCH + f];
            unsigned short rh, rl, ih, il;
            split_bf16(vr, rh, rl);
            split_bf16(vi, ih, il);
            int o = f * WP + c;
            smX[o] = rh; smX[PLX32 + o] = rl;
            smX[2 * PLX32 + o] = ih; smX[3 * PLX32 + o] = il;
        }
        __syncthreads();

        // prefetch next tile raw (overlaps GEMM)
        if (t + 1 < end) {
            for (int i = tid; i < 2048; i += NT_M) {
                int pl = i >> 10, rem = i & 1023, c = rem >> 3, seg = rem & 7;
                const float* src = (pl ? g_specI : g_specR) + chanbase + (size_t)c * F_
                                 + (size_t)(t + 1) * 32 + seg * 4;
                uint32_t dst = raw_u32 + (uint32_t)(pl * (128 * RPITCH * 4) + c * (RPITCH * 4) + seg * 16);
                CP_ASYNC16(dst, src);
            }
            CP_COMMIT();
        }

        float aOr[8], aP[8], aOi[8];
        #pragma unroll
        for (int i = 0; i < 8; i++) { aOr[i] = 0.f; aP[i] = 0.f; aOi[i] = 0.f; }
        gemm32(smW_a, smX_a, aOr, aP, aOi, warp_m, warp_n, lane);
        __syncthreads();

        // epilogue: bias + relu, split, write O1 planes back into smX
        #pragma unroll
        for (int nt = 0; nt < 2; nt++) {
            int c0 = warp_n + nt * 8 + tig * 2;
            int ai = nt * 4;
            #pragma unroll
            for (int e = 0; e < 4; e++) {
                int row = (e >= 2) ? r0 + 8 : r0;
                int col = c0 + (e & 1);
                float brv = (e >= 2) ? br1_ : br0;
                float biv = (e >= 2) ? bi1_ : bi0;
                float vr = aOr[ai + e] - aP[ai + e] + brv; vr = vr > 0.f ? vr : 0.f;
                float vi = aOi[ai + e] + biv;              vi = vi > 0.f ? vi : 0.f;
                unsigned short rh, rl, ih, il;
                split_bf16(vr, rh, rl);
                split_bf16(vi, ih, il);
                int o = col * WP + row;
                smX[o] = rh; smX[PLX32 + o] = rl;
                smX[2 * PLX32 + o] = ih; smX[3 * PLX32 + o] = il;
            }
        }
        __syncthreads();

        // coalesced copy-out smX planes -> g_o1: 4 planes x 32 f x 16 uint4
        {
            uint4* dst = (uint4*)(g_o1 + ((size_t)bg * NTILE + t) * 16384);
            for (int i = tid; i < 2048; i += NT_M) {
                int pl = i >> 9, rem = i & 511, f = rem >> 4, c16 = rem & 15;
                dst[i] = *(const uint4*)(smX + pl * PLX32 + f * WP + c16 * 8);
            }
        }
    }
}

// ================= Layer 2 kernel =================
__global__ void __launch_bounds__(NT_M, 1)
kmixL2(const float* __restrict__ b2) {
    extern __shared__ char smem[];
    unsigned short* smW  = (unsigned short*)smem;
    unsigned short* smX0 = (unsigned short*)(smem + L2_OFF_X);
    const uint32_t smW_a = smem_u32(smW);

    const int tid = threadIdx.x;
    const int wid = tid >> 5, lane = tid & 31;
    const int gid = lane >> 2, tig = lane & 3;
    const int warp_m = (wid & 7) * 16;
    const int warp_n = (wid >> 3) * 16;
    const int bg = blockIdx.x;
    const int b = bg >> 2, g = bg & 3;
    int start, cnt;
    chunk_range(blockIdx.y, start, cnt);
    const int end = start + cnt;

    const size_t chanbase = ((size_t)b * C_ + (size_t)g * D_) * F_;

    // prefetch first tile O1 planes into buf0
    {
        const uint4* src = (const uint4*)(g_o1 + ((size_t)bg * NTILE + start) * 16384);
        uint32_t bufb = smem_u32(smX0);
        for (int i = tid; i < 2048; i += NT_M) {
            int pl = i >> 9, rem = i & 511, f = rem >> 4, c16 = rem & 15;
            uint32_t dst = bufb + (uint32_t)((pl * PLX32 + f * WP) * 2 + c16 * 16);
            CP_ASYNC16(dst, src + i);
        }
        CP_COMMIT();
    }

    // W2 planes
    {
        const float4* ws = (const float4*)(g_wimg + (size_t)(1 * 4 + g) * 4 * PLW);
        float4* wd = (float4*)smW;
        for (int i = tid; i < 4 * PLW / 8; i += NT_M) wd[i] = ws[i];
    }

    const int r0 = warp_m + gid;
    const float br0  = b2[g * D_ + r0];
    const float br1_ = b2[g * D_ + r0 + 8];
    const float bi0  = b2[(G_ + g) * D_ + r0];
    const float bi1_ = b2[(G_ + g) * D_ + r0 + 8];

    for (int t = start; t < end; t++) {
        unsigned short* buf = smX0 + ((t - start) & 1) * (4 * PLX32);
        CP_WAIT0();
        __syncthreads();

        // prefetch next tile into other buffer (overlaps GEMM)
        if (t + 1 < end) {
            unsigned short* nb = smX0 + (((t - start) + 1) & 1) * (4 * PLX32);
            const uint4* src = (const uint4*)(g_o1 + ((size_t)bg * NTILE + (t + 1)) * 16384);
            uint32_t bufb = smem_u32(nb);
            for (int i = tid; i < 2048; i += NT_M) {
                int pl = i >> 9, rem = i & 511, f = rem >> 4, c16 = rem & 15;
                uint32_t dst = bufb + (uint32_t)((pl * PLX32 + f * WP) * 2 + c16 * 16);
                CP_ASYNC16(dst, src + i);
            }
            CP_COMMIT();
        }

        // prefetch origin spec values into registers (consumed in epilogue)
        float2 oxr[4], oxi[4];
        #pragma unroll
        for (int nt = 0; nt < 2; nt++)
            #pragma unroll
            for (int rp = 0; rp < 2; rp++) {
                int row = r0 + rp * 8;
                int c0  = warp_n + nt * 8 + tig * 2;
                size_t gi = chanbase + (size_t)row * F_ + (size_t)t * 32 + c0;
                int idx = nt * 2 + rp;
                oxr[idx] = *(const float2*)&g_specR[gi];
                oxi[idx] = *(const float2*)&g_specI[gi];
            }

        float aOr[8], aP[8], aOi[8];
        #pragma unroll
        for (int i = 0; i < 8; i++) { aOr[i] = 0.f; aP[i] = 0.f; aOi[i] = 0.f; }
        gemm32(smW_a, smem_u32(buf), aOr, aP, aOi, warp_m, warp_n, lane);

        // epilogue: bias, multiply by origin, store
        #pragma unroll
        for (int nt = 0; nt < 2; nt++) {
            int c0 = warp_n + nt * 8 + tig * 2;
            int ai = nt * 4;
            #pragma unroll
            for (int rp = 0; rp < 2; rp++) {
                int row = r0 + rp * 8;
                float brv = rp ? br1_ : br0;
                float biv = rp ? bi1_ : bi0;
                int idx = nt * 2 + rp;
                float2 xr = oxr[idx], xi = oxi[idx];
                size_t gi = chanbase + (size_t)row * F_ + (size_t)t * 32 + c0;
                float vr0 = aOr[ai + rp * 2]     - aP[ai + rp * 2]     + brv;
                float vi0 = aOi[ai + rp * 2]     + biv;
                float vr1 = aOr[ai + rp * 2 + 1] - aP[ai + rp * 2 + 1] + brv;
                float vi1 = aOi[ai + rp * 2 + 1] + biv;
                float2 orv, oiv;
                orv.x = vr0 * xr.x - vi0 * xi.x;
                oiv.x = vr0 * xi.x + vi0 * xr.x;
                orv.y = vr1 * xr.y - vi1 * xi.y;
                oiv.y = vr1 * xi.y + vi1 * xr.y;
                *(float2*)&g_outR[gi] = orv;
                *(float2*)&g_outI[gi] = oiv;
            }
        }
    }
}

// ---------------------------------------------------------------------------
__global__ void __launch_bounds__(NT_F, 2) kfft_inv(float* __restrict__ y) {
    extern __shared__ float sm[];
    float* R   = sm;
    float* I   = sm + UBUF;
    float* twR = sm + 2 * UBUF;
    float* twI = twR + 64;

    const int tid = threadIdx.x;
    const int img = blockIdx.x;

    if (tid < 64) {
        float s, c;
        sincospif((float)tid / 64.0f, &s, &c);
        twR[tid] = c; twI[tid] = s;
    }

    const float* srcR = g_outR + (size_t)img * F_;
    const float* srcI = g_outI + (size_t)img * F_;
    for (int t = tid; t < F_; t += NT_F) {
        int h = t / WF_, k = t - h * WF_;
        int hb = brev7(h);
        R[hb * CPIT + k] = srcR[t];
        I[hb * CPIT + k] = srcI[t];
    }
    __syncthreads();

    pass4_cols<1>(R, I, twR, twI); __syncthreads();
    pass4_cols<3>(R, I, twR, twI); __syncthreads();
    pass4_cols<5>(R, I, twR, twI); __syncthreads();
    pass2_cols   (R, I, twR, twI); __syncthreads();

    float zr[16], zi[16];
    #pragma unroll
    for (int n = 0; n < 16; n++) {
        int it = tid + n * NT_F;
        int w = it & 127, p = it >> 7;
        int r0 = (2 * p) * CPIT, r1 = r0 + CPIT;
        if (w <= 64) {
            float x0r = R[r0 + w], x0i = I[r0 + w];
            float x1r = R[r1 + w], x1i = I[r1 + w];
            if (w == 0 || w == 64) { x0i = 0.f; x1i = 0.f; }
            zr[n] = x0r - x1i;
            zi[n] = x0i + x1r;
        } else {
            int m = 128 - w;
            float x0r = R[r0 + m], x0i = I[r0 + m];
            float x1r = R[r1 + m], x1i = I[r1 + m];
            zr[n] = x0r + x1i;
            zi[n] = x1r - x0i;
        }
    }
    __syncthreads();
    #pragma unroll
    for (int n = 0; n < 16; n++) {
        int it = tid + n * NT_F;
        int w = it & 127, p = it >> 7;
        int wb = brev7(w);
        R[p * RPIT + wb] = zr[n];
        I[p * RPIT + wb] = zi[n];
    }
    __syncthreads();

    pass4_rows<1>(R, I, twR, twI); __syncthreads();
    pass4_rows<3>(R, I, twR, twI); __syncthreads();
    pass4_rows<5>(R, I, twR, twI); __syncthreads();
    pass2_rows   (R, I, twR, twI); __syncthreads();

    float* dst = y + (size_t)img * (H_ * W_);
    const float sc = 1.0f / 128.0f;
    for (int t = tid; t < 64 * 128; t += NT_F) {
        int p = t >> 7, c = t & 127;
        dst[(2 * p) * 128 + c]       = R[p * RPIT + c] * sc;
        dst[(2 * p) * 128 + 128 + c] = I[p * RPIT + c] * sc;
    }
}

// ---------------------------------------------------------------------------
extern "C" void kernel_launch(void* const* d_in, const int* in_sizes, int n_in,
                              void* d_out, int out_size) {
    const float* x  = (const float*)d_in[0];
    const float* w1 = (const float*)d_in[1];
    const float* w2 = (const float*)d_in[2];
    const float* b1 = (const float*)d_in[3];
    const float* b2 = (const float*)d_in[4];
    float* y = (float*)d_out;

    const int smFFT = (2 * UBUF + 128) * (int)sizeof(float);   // ~65.5 KB

    cudaFuncSetAttribute(kfft_fwd, cudaFuncAttributeMaxDynamicSharedMemorySize, smFFT);
    cudaFuncSetAttribute(kmixL1,   cudaFuncAttributeMaxDynamicSharedMemorySize, SM_L1);
    cudaFuncSetAttribute(kmixL2,   cudaFuncAttributeMaxDynamicSharedMemorySize, SM_L2);
    cudaFuncSetAttribute(kfft_inv, cudaFuncAttributeMaxDynamicSharedMemorySize, smFFT);

    wprep<<<1024, 256>>>(w1, w2);
    kfft_fwd<<<NIMG, NT_F, smFFT>>>(x);
    kmixL1<<<dim3(32, NCHUNK), NT_M, SM_L1>>>(b1);
    kmixL2<<<dim3(32, NCHUNK), NT_M, SM_L2>>>(b2);
    kfft_inv<<<NIMG, NT_F, smFFT>>>(y);
}

// round 13
// speedup vs baseline: 1.1983x; 1.0190x over previous
#include <cuda_runtime.h>
#include <cuda_bf16.h>
#include <math.h>
#include <stdint.h>

#define B_   8
#define C_   512
#define G_   4
#define D_   128
#define H_   128
#define W_   128
#define WF_  65
#define F_   (H_*WF_)        // 8320
#define NIMG (B_*C_)         // 4096

// Scratch (allocation-free requirement -> device globals).
static __device__ float g_specR[(size_t)NIMG * F_];
static __device__ float g_specI[(size_t)NIMG * F_];
static __device__ float g_outR [(size_t)NIMG * F_];
static __device__ float g_outI [(size_t)NIMG * F_];
static __device__ unsigned short g_wimg[32 * 128 * 136];            // pre-split W planes
static __device__ unsigned short g_o1[(size_t)32 * 260 * 16384];    // O1 planes (~273MB)

#define RPIT 129
#define CPIT 65
#define UBUF 8320
#define NT_F 512

#define WP    136           // bf16 plane pitch (shorts)
#define PLW   (128 * WP)    // W plane elems (17408)
#define PLX32 (32 * WP)     // X plane elems, N=32 tile (4352)
#define NTILE 260           // 8320 / 32
#define NCHUNK 9
#define RPITCH 36           // raw staging pitch (floats)
#define NT_M  512           // mixer threads (16 warps)

__device__ __forceinline__ int brev7(int v) { return (int)(__brev((unsigned)v) >> 25); }

__device__ __forceinline__ void split_bf16(float v, unsigned short& h, unsigned short& l) {
    __nv_bfloat16 hb = __float2bfloat16(v);
    float r = v - __bfloat162float(hb);
    h = __bfloat16_as_ushort(hb);
    l = __bfloat16_as_ushort(__float2bfloat16(r));
}

__device__ __forceinline__ uint32_t smem_u32(const void* p) {
    uint32_t a;
    asm("{ .reg .u64 t; cvta.to.shared.u64 t, %1; cvt.u32.u64 %0, t; }" : "=r"(a) : "l"(p));
    return a;
}
#define CP_ASYNC16(dst, src) \
    asm volatile("cp.async.cg.shared.global [%0], [%1], 16;" :: "r"(dst), "l"(src))
#define CP_COMMIT() asm volatile("cp.async.commit_group;" ::: "memory")
#define CP_WAIT0()  asm volatile("cp.async.wait_group 0;"  ::: "memory")

#define LDSM_X4(r, addr) \
    asm volatile("ldmatrix.sync.aligned.m8n8.x4.shared.b16 {%0,%1,%2,%3}, [%4];" \
        : "=r"((r)[0]), "=r"((r)[1]), "=r"((r)[2]), "=r"((r)[3]) : "r"(addr))

// ---------------------------------------------------------------------------
// Weight prep
// ---------------------------------------------------------------------------
__global__ void __launch_bounds__(256) wprep(const float* __restrict__ w1,
                                             const float* __restrict__ w2) {
    int idx = blockIdx.x * 256 + threadIdx.x;      // 262144
    int m    = idx & 127;
    int k    = (idx >> 7) & 127;
    int part = (idx >> 14) & 1;
    int g    = (idx >> 15) & 3;
    int l    = (idx >> 17) & 1;
    const float* src = l ? w2 : w1;
    float v = src[(((size_t)(part * 4 + g) * 128 + k) * 128) + m];
    unsigned short h, lo;
    split_bf16(v, h, lo);
    size_t base = (size_t)((l * 4 + g) * 4 + part * 2) * PLW;
    g_wimg[base + m * WP + k]       = h;
    g_wimg[base + PLW + m * WP + k] = lo;
}

// ============================ FFT passes ====================================
// Radix-8: three fused radix-2 stages S, S+1, S+2 (DIT, bit-reversed input).
template<int S>
__device__ __forceinline__ void pass8_rows(float* R, float* I,
                                           const float* twR, const float* twI) {
    const int h = 1 << (S - 1);
    for (int it = threadIdx.x; it < 64 * 16; it += NT_F) {
        int r = it & 63, q = it >> 6;
        int j = q & (h - 1);
        int base = (q >> (S - 1)) << (S + 2);
        int i0 = r * RPIT + base + j;
        float er[8], ei[8];
        #pragma unroll
        for (int k = 0; k < 8; k++) { er[k] = R[i0 + k * h]; ei[k] = I[i0 + k * h]; }
        // stage S: pairs (0,1)(2,3)(4,5)(6,7), w1
        {
            float wr = twR[j << (7 - S)], wi = twI[j << (7 - S)];
            #pragma unroll
            for (int k = 0; k < 8; k += 2) {
                float tr = er[k+1] * wr - ei[k+1] * wi;
                float ti = er[k+1] * wi + ei[k+1] * wr;
                er[k+1] = er[k] - tr; ei[k+1] = ei[k] - ti;
                er[k]  += tr;         ei[k]  += ti;
            }
        }
        // stage S+1: pairs (0,2)(1,3)(4,6)(5,7), w2/w3
        {
            float w2r = twR[j << (6 - S)],       w2i = twI[j << (6 - S)];
            float w3r = twR[(j + h) << (6 - S)], w3i = twI[(j + h) << (6 - S)];
            #pragma unroll
            for (int gq = 0; gq < 8; gq += 4) {
                float tr = er[gq+2] * w2r - ei[gq+2] * w2i;
                float ti = er[gq+2] * w2i + ei[gq+2] * w2r;
                er[gq+2] = er[gq] - tr; ei[gq+2] = ei[gq] - ti;
                er[gq]  += tr;          ei[gq]  += ti;
                tr = er[gq+3] * w3r - ei[gq+3] * w3i;
                ti = er[gq+3] * w3i + ei[gq+3] * w3r;
                er[gq+3] = er[gq+1] - tr; ei[gq+3] = ei[gq+1] - ti;
                er[gq+1] += tr;           ei[gq+1] += ti;
            }
        }
        // stage S+2: pairs (k, k+4), twiddle tw[(j+k*h) << (5-S)]
        #pragma unroll
        for (int k = 0; k < 4; k++) {
            float wr = twR[(j + k * h) << (5 - S)], wi = twI[(j + k * h) << (5 - S)];
            float tr = er[k+4] * wr - ei[k+4] * wi;
            float ti = er[k+4] * wi + ei[k+4] * wr;
            er[k+4] = er[k] - tr; ei[k+4] = ei[k] - ti;
            er[k]  += tr;         ei[k]  += ti;
        }
        #pragma unroll
        for (int k = 0; k < 8; k++) { R[i0 + k * h] = er[k]; I[i0 + k * h] = ei[k]; }
    }
}

__device__ __forceinline__ void pass2_rows(float* R, float* I,
                                           const float* twR, const float* twI) {
    for (int it = threadIdx.x; it < 64 * 64; it += NT_F) {
        int r = it & 63, j = it >> 6;
        int i0 = r * RPIT + j, i1 = i0 + 64;
        float wr = twR[j], wi = twI[j];
        float ar = R[i0], ai = I[i0], br = R[i1], bi = I[i1];
        float tr = br*wr - bi*wi, ti = br*wi + bi*wr;
        R[i0] = ar + tr; I[i0] = ai + ti;
        R[i1] = ar - tr; I[i1] = ai - ti;
    }
}

template<int S>
__device__ __forceinline__ void pass8_cols(float* R, float* I,
                                           const float* twR, const float* twI) {
    const int h = 1 << (S - 1);
    const int st = h * CPIT;
    for (int it = threadIdx.x; it < 65 * 16; it += NT_F) {
        int c = it % 65, q = it / 65;
        int j = q & (h - 1);
        int base = (q >> (S - 1)) << (S + 2);
        int i0 = (base + j) * CPIT + c;
        float er[8], ei[8];
        #pragma unroll
        for (int k = 0; k < 8; k++) { er[k] = R[i0 + k * st]; ei[k] = I[i0 + k * st]; }
        {
            float wr = twR[j << (7 - S)], wi = twI[j << (7 - S)];
            #pragma unroll
            for (int k = 0; k < 8; k += 2) {
                float tr = er[k+1] * wr - ei[k+1] * wi;
                float ti = er[k+1] * wi + ei[k+1] * wr;
                er[k+1] = er[k] - tr; ei[k+1] = ei[k] - ti;
                er[k]  += tr;         ei[k]  += ti;
            }
        }
        {
            float w2r = twR[j << (6 - S)],       w2i = twI[j << (6 - S)];
            float w3r = twR[(j + h) << (6 - S)], w3i = twI[(j + h) << (6 - S)];
            #pragma unroll
            for (int gq = 0; gq < 8; gq += 4) {
                float tr = er[gq+2] * w2r - ei[gq+2] * w2i;
                float ti = er[gq+2] * w2i + ei[gq+2] * w2r;
                er[gq+2] = er[gq] - tr; ei[gq+2] = ei[gq] - ti;
                er[gq]  += tr;          ei[gq]  += ti;
                tr = er[gq+3] * w3r - ei[gq+3] * w3i;
                ti = er[gq+3] * w3i + ei[gq+3] * w3r;
                er[gq+3] = er[gq+1] - tr; ei[gq+3] = ei[gq+1] - ti;
                er[gq+1] += tr;           ei[gq+1] += ti;
            }
        }
        #pragma unroll
        for (int k = 0; k < 4; k++) {
            float wr = twR[(j + k * h) << (5 - S)], wi = twI[(j + k * h) << (5 - S)];
            float tr = er[k+4] * wr - ei[k+4] * wi;
            float ti = er[k+4] * wi + ei[k+4] * wr;
            er[k+4] = er[k] - tr; ei[k+4] = ei[k] - ti;
            er[k]  += tr;         ei[k]  += ti;
        }
        #pragma unroll
        for (int k = 0; k < 8; k++) { R[i0 + k * st] = er[k]; I[i0 + k * st] = ei[k]; }
    }
}

__device__ __forceinline__ void pass2_cols(float* R, float* I,
                                           const float* twR, const float* twI) {
    for (int it = threadIdx.x; it < 65 * 64; it += NT_F) {
        int c = it % 65, j = it / 65;
        int i0 = j * CPIT + c, i1 = i0 + 64 * CPIT;
        float wr = twR[j], wi = twI[j];
        float ar = R[i0], ai = I[i0], br = R[i1], bi = I[i1];
        float tr = br*wr - bi*wi, ti = br*wi + bi*wr;
        R[i0] = ar + tr; I[i0] = ai + ti;
        R[i1] = ar - tr; I[i1] = ai - ti;
    }
}

__global__ void __launch_bounds__(NT_F, 2) kfft_fwd(const float* __restrict__ x) {
    extern __shared__ float sm[];
    float* R   = sm;
    float* I   = sm + UBUF;
    float* twR = sm + 2 * UBUF;
    float* twI = twR + 64;

    const int tid = threadIdx.x;
    const int img = blockIdx.x;

    if (tid < 64) {
        float s, c;
        sincospif(-(float)tid / 64.0f, &s, &c);
        twR[tid] = c; twI[tid] = s;
    }

    const float* src = x + (size_t)img * (H_ * W_);
    for (int t = tid; t < 64 * 128; t += NT_F) {
        int p = t >> 7, c = t & 127;
        int cb = brev7(c);
        R[p * RPIT + cb] = src[(2 * p) * 128 + c];
        I[p * RPIT + cb] = src[(2 * p) * 128 + 128 + c];
    }
    __syncthreads();

    pass8_rows<1>(R, I, twR, twI); __syncthreads();
    pass8_rows<4>(R, I, twR, twI); __syncthreads();
    pass2_rows   (R, I, twR, twI); __syncthreads();

    float u0r[9], u0i[9], u1r[9], u1i[9];
    #pragma unroll
    for (int n = 0; n < 9; n++) {
        int it = tid + n * NT_F;
        if (it < 64 * 65) {
            int k = it % 65, p = it / 65;
            int m = (128 - k) & 127;
            float a = R[p * RPIT + k], b = I[p * RPIT + k];
            float c2 = R[p * RPIT + m], d = I[p * RPIT + m];
            u0r[n] = 0.5f * (a + c2); u0i[n] = 0.5f * (b - d);
            u1r[n] = 0.5f * (b + d);  u1i[n] = 0.5f * (c2 - a);
        }
    }
    __syncthreads();
    #pragma unroll
    for (int n = 0; n < 9; n++) {
        int it = tid + n * NT_F;
        if (it < 64 * 65) {
            int k = it % 65, p = it / 65;
            int h0 = brev7(2 * p), h1 = brev7(2 * p + 1);
            R[h0 * CPIT + k] = u0r[n]; I[h0 * CPIT + k] = u0i[n];
            R[h1 * CPIT + k] = u1r[n]; I[h1 * CPIT + k] = u1i[n];
        }
    }
    __syncthreads();

    pass8_cols<1>(R, I, twR, twI); __syncthreads();
    pass8_cols<4>(R, I, twR, twI); __syncthreads();
    pass2_cols   (R, I, twR, twI); __syncthreads();

    float* dR = g_specR + (size_t)img * F_;
    float* dI = g_specI + (size_t)img * F_;
    const float sc = 1.0f / 128.0f;
    for (int t = tid; t < F_; t += NT_F) {
        dR[t] = R[t] * sc;
        dI[t] = I[t] * sc;
    }
}

// ---------------------------------------------------------------------------
// Tensor-core mixer: 512 threads / 16 warps, warp tile m16 x n16, LDSM loads.
// ---------------------------------------------------------------------------
__device__ __forceinline__ void mma16816(float* d, const uint32_t* a, const uint32_t* b) {
    asm volatile("mma.sync.aligned.m16n8k16.row.col.f32.bf16.bf16.f32 "
        "{%0,%1,%2,%3}, {%4,%5,%6,%7}, {%8,%9}, {%0,%1,%2,%3};"
        : "+f"(d[0]), "+f"(d[1]), "+f"(d[2]), "+f"(d[3])
        : "r"(a[0]), "r"(a[1]), "r"(a[2]), "r"(a[3]), "r"(b[0]), "r"(b[1]));
}

// warp tile m16 (warp_m = (wid&7)*16) x n16 (warp_n = (wid>>3)*16, 2 x n8)
// LDSM x4: A = m16k16 fragment; B = n16k16 covering both nt sub-tiles.
__device__ __forceinline__ void gemm32(uint32_t smW_a, uint32_t smX_a,
                                       float* aOr, float* aP, float* aOi,
                                       int warp_m, int warp_n, int lane) {
    const uint32_t aOff = (uint32_t)((warp_m + (lane & 15)) * WP + ((lane >> 4) << 3)) * 2;
    const uint32_t bOff = (uint32_t)((warp_n + ((lane >> 4) << 3) + (lane & 7)) * WP
                                     + (((lane >> 3) & 1) << 3)) * 2;
    #pragma unroll 1
    for (int kk = 0; kk < 8; kk++) {
        const uint32_t k0b = (uint32_t)kk * 32;
        uint32_t A[4][4];
        #pragma unroll
        for (int pl = 0; pl < 4; pl++)
            LDSM_X4(A[pl], smW_a + (uint32_t)pl * (PLW * 2) + aOff + k0b);
        uint32_t Bf[4][4];
        #pragma unroll
        for (int pl = 0; pl < 4; pl++)
            LDSM_X4(Bf[pl], smX_a + (uint32_t)pl * (PLX32 * 2) + bOff + k0b);
        #pragma unroll
        for (int nt = 0; nt < 2; nt++) {
            float* dOr = aOr + nt * 4;
            float* dP  = aP  + nt * 4;
            float* dOi = aOi + nt * 4;
            const uint32_t* bR  = &Bf[0][nt * 2];
            const uint32_t* bRl = &Bf[1][nt * 2];
            const uint32_t* bI  = &Bf[2][nt * 2];
            const uint32_t* bIl = &Bf[3][nt * 2];
            mma16816(dOr, A[0], bR);
            mma16816(dOr, A[1], bR);
            mma16816(dOr, A[0], bRl);
            mma16816(dP,  A[2], bI);
            mma16816(dP,  A[3], bI);
            mma16816(dP,  A[2], bIl);
            mma16816(dOi, A[2], bR);
            mma16816(dOi, A[3], bR);
            mma16816(dOi, A[2], bRl);
            mma16816(dOi, A[0], bI);
            mma16816(dOi, A[1], bI);
            mma16816(dOi, A[0], bIl);
        }
    }
}

__device__ __forceinline__ void chunk_range(int c, int& start, int& cnt) {
    start = c * 29;
    cnt   = (c == 8) ? 28 : 29;
}

// L1 smem: W planes | X planes | raw staging
#define L1_OFF_X   (4 * PLW * 2)                     // 139264
#define L1_OFF_RAW (L1_OFF_X + 4 * PLX32 * 2)        // 174080
#define SM_L1      (L1_OFF_RAW + 2 * 128 * RPITCH * 4)  // 210944
// L2 smem: W planes | 2x X plane buffers
#define L2_OFF_X   (4 * PLW * 2)
#define SM_L2      (L2_OFF_X + 2 * 4 * PLX32 * 2)       // 208896

// ================= Layer 1 kernel =================
__global__ void __launch_bounds__(NT_M, 1)
kmixL1(const float* __restrict__ b1) {
    extern __shared__ char smem[];
    unsigned short* smW = (unsigned short*)smem;
    unsigned short* smX = (unsigned short*)(smem + L1_OFF_X);
    float*          raw = (float*)(smem + L1_OFF_RAW);
    const uint32_t raw_u32 = smem_u32(raw);
    const uint32_t smW_a = smem_u32(smW);
    const uint32_t smX_a = smem_u32(smX);

    const int tid = threadIdx.x;
    const int wid = tid >> 5, lane = tid & 31;
    const int gid = lane >> 2, tig = lane & 3;
    const int warp_m = (wid & 7) * 16;
    const int warp_n = (wid >> 3) * 16;
    const int bg = blockIdx.x;
    const int b = bg >> 2, g = bg & 3;
    int start, cnt;
    chunk_range(blockIdx.y, start, cnt);
    const int end = start + cnt;

    const size_t chanbase = ((size_t)b * C_ + (size_t)g * D_) * F_;

    // prefetch first tile raw spec (async)
    {
        for (int i = tid; i < 2048; i += NT_M) {
            int pl = i >> 10, rem = i & 1023, c = rem >> 3, seg = rem & 7;
            const float* src = (pl ? g_specI : g_specR) + chanbase + (size_t)c * F_
                             + (size_t)start * 32 + seg * 4;
            uint32_t dst = raw_u32 + (uint32_t)(pl * (128 * RPITCH * 4) + c * (RPITCH * 4) + seg * 16);
            CP_ASYNC16(dst, src);
        }
        CP_COMMIT();
    }

    // W1 planes: once per CTA
    {
        const float4* ws = (const float4*)(g_wimg + (size_t)(0 * 4 + g) * 4 * PLW);
        float4* wd = (float4*)smW;
        for (int i = tid; i < 4 * PLW / 8; i += NT_M) wd[i] = ws[i];
    }

    // bias values (fixed rows per warp)
    const int r0 = warp_m + gid;
    const float br0  = b1[g * D_ + r0];
    const float br1_ = b1[g * D_ + r0 + 8];
    const float bi0  = b1[(G_ + g) * D_ + r0];
    const float bi1_ = b1[(G_ + g) * D_ + r0 + 8];

    for (int t = start; t < end; t++) {
        CP_WAIT0();
        __syncthreads();

        // convert raw -> X planes (split); 4096 elems / 512 threads
        #pragma unroll
        for (int n = 0; n < 8; n++) {
            int it = tid + n * NT_M;
            int c = it >> 5, f = it & 31;
            float vr = raw[c * RPITCH + f];
            float vi = raw[128 * RPITCH + c * RPITCH + f];
            unsigned short rh, rl, ih, il;
            split_bf16(vr, rh, rl);
            split_bf16(vi, ih, il);
            int o = f * WP + c;
            smX[o] = rh; smX[PLX32 + o] = rl;
            smX[2 * PLX32 + o] = ih; smX[3 * PLX32 + o] = il;
        }
        __syncthreads();

        // prefetch next tile raw (overlaps GEMM)
        if (t + 1 < end) {
            for (int i = tid; i < 2048; i += NT_M) {
                int pl = i >> 10, rem = i & 1023, c = rem >> 3, seg = rem & 7;
                const float* src = (pl ? g_specI : g_specR) + chanbase + (size_t)c * F_
                                 + (size_t)(t + 1) * 32 + seg * 4;
                uint32_t dst = raw_u32 + (uint32_t)(pl * (128 * RPITCH * 4) + c * (RPITCH * 4) + seg * 16);
                CP_ASYNC16(dst, src);
            }
            CP_COMMIT();
        }

        float aOr[8], aP[8], aOi[8];
        #pragma unroll
        for (int i = 0; i < 8; i++) { aOr[i] = 0.f; aP[i] = 0.f; aOi[i] = 0.f; }
        gemm32(smW_a, smX_a, aOr, aP, aOi, warp_m, warp_n, lane);
        __syncthreads();

        // epilogue: bias + relu, split, write O1 planes back into smX
        #pragma unroll
        for (int nt = 0; nt < 2; nt++) {
            int c0 = warp_n + nt * 8 + tig * 2;
            int ai = nt * 4;
            #pragma unroll
            for (int e = 0; e < 4; e++) {
                int row = (e >= 2) ? r0 + 8 : r0;
                int col = c0 + (e & 1);
                float brv = (e >= 2) ? br1_ : br0;
                float biv = (e >= 2) ? bi1_ : bi0;
                float vr = aOr[ai + e] - aP[ai + e] + brv; vr = vr > 0.f ? vr : 0.f;
                float vi = aOi[ai + e] + biv;              vi = vi > 0.f ? vi : 0.f;
                unsigned short rh, rl, ih, il;
                split_bf16(vr, rh, rl);
                split_bf16(vi, ih, il);
                int o = col * WP + row;
                smX[o] = rh; smX[PLX32 + o] = rl;
                smX[2 * PLX32 + o] = ih; smX[3 * PLX32 + o] = il;
            }
        }
        __syncthreads();

        // coalesced copy-out smX planes -> g_o1: 4 planes x 32 f x 16 uint4
        {
            uint4* dst = (uint4*)(g_o1 + ((size_t)bg * NTILE + t) * 16384);
            for (int i = tid; i < 2048; i += NT_M) {
                int pl = i >> 9, rem = i & 511, f = rem >> 4, c16 = rem & 15;
                dst[i] = *(const uint4*)(smX + pl * PLX32 + f * WP + c16 * 8);
            }
        }
    }
}

// ================= Layer 2 kernel =================
__global__ void __launch_bounds__(NT_M, 1)
kmixL2(const float* __restrict__ b2) {
    extern __shared__ char smem[];
    unsigned short* smW  = (unsigned short*)smem;
    unsigned short* smX0 = (unsigned short*)(smem + L2_OFF_X);
    const uint32_t smW_a = smem_u32(smW);

    const int tid = threadIdx.x;
    const int wid = tid >> 5, lane = tid & 31;
    const int gid = lane >> 2, tig = lane & 3;
    const int warp_m = (wid & 7) * 16;
    const int warp_n = (wid >> 3) * 16;
    const int bg = blockIdx.x;
    const int b = bg >> 2, g = bg & 3;
    int start, cnt;
    chunk_range(blockIdx.y, start, cnt);
    const int end = start + cnt;

    const size_t chanbase = ((size_t)b * C_ + (size_t)g * D_) * F_;

    // prefetch first tile O1 planes into buf0
    {
        const uint4* src = (const uint4*)(g_o1 + ((size_t)bg * NTILE + start) * 16384);
        uint32_t bufb = smem_u32(smX0);
        for (int i = tid; i < 2048; i += NT_M) {
            int pl = i >> 9, rem = i & 511, f = rem >> 4, c16 = rem & 15;
            uint32_t dst = bufb + (uint32_t)((pl * PLX32 + f * WP) * 2 + c16 * 16);
            CP_ASYNC16(dst, src + i);
        }
        CP_COMMIT();
    }

    // W2 planes
    {
        const float4* ws = (const float4*)(g_wimg + (size_t)(1 * 4 + g) * 4 * PLW);
        float4* wd = (float4*)smW;
        for (int i = tid; i < 4 * PLW / 8; i += NT_M) wd[i] = ws[i];
    }

    const int r0 = warp_m + gid;
    const float br0  = b2[g * D_ + r0];
    const float br1_ = b2[g * D_ + r0 + 8];
    const float bi0  = b2[(G_ + g) * D_ + r0];
    const float bi1_ = b2[(G_ + g) * D_ + r0 + 8];

    for (int t = start; t < end; t++) {
        unsigned short* buf = smX0 + ((t - start) & 1) * (4 * PLX32);
        CP_WAIT0();
        __syncthreads();

        // prefetch next tile into other buffer (overlaps GEMM)
        if (t + 1 < end) {
            unsigned short* nb = smX0 + (((t - start) + 1) & 1) * (4 * PLX32);
            const uint4* src = (const uint4*)(g_o1 + ((size_t)bg * NTILE + (t + 1)) * 16384);
            uint32_t bufb = smem_u32(nb);
            for (int i = tid; i < 2048; i += NT_M) {
                int pl = i >> 9, rem = i & 511, f = rem >> 4, c16 = rem & 15;
                uint32_t dst = bufb + (uint32_t)((pl * PLX32 + f * WP) * 2 + c16 * 16);
                CP_ASYNC16(dst, src + i);
            }
            CP_COMMIT();
        }

        // prefetch origin spec values into registers (consumed in epilogue)
        float2 oxr[4], oxi[4];
        #pragma unroll
        for (int nt = 0; nt < 2; nt++)
            #pragma unroll
            for (int rp = 0; rp < 2; rp++) {
                int row = r0 + rp * 8;
                int c0  = warp_n + nt * 8 + tig * 2;
                size_t gi = chanbase + (size_t)row * F_ + (size_t)t * 32 + c0;
                int idx = nt * 2 + rp;
                oxr[idx] = *(const float2*)&g_specR[gi];
                oxi[idx] = *(const float2*)&g_specI[gi];
            }

        float aOr[8], aP[8], aOi[8];
        #pragma unroll
        for (int i = 0; i < 8; i++) { aOr[i] = 0.f; aP[i] = 0.f; aOi[i] = 0.f; }
        gemm32(smW_a, smem_u32(buf), aOr, aP, aOi, warp_m, warp_n, lane);

        // epilogue: bias, multiply by origin, store
        #pragma unroll
        for (int nt = 0; nt < 2; nt++) {
            int c0 = warp_n + nt * 8 + tig * 2;
            int ai = nt * 4;
            #pragma unroll
            for (int rp = 0; rp < 2; rp++) {
                int row = r0 + rp * 8;
                float brv = rp ? br1_ : br0;
                float biv = rp ? bi1_ : bi0;
                int idx = nt * 2 + rp;
                float2 xr = oxr[idx], xi = oxi[idx];
                size_t gi = chanbase + (size_t)row * F_ + (size_t)t * 32 + c0;
                float vr0 = aOr[ai + rp * 2]     - aP[ai + rp * 2]     + brv;
                float vi0 = aOi[ai + rp * 2]     + biv;
                float vr1 = aOr[ai + rp * 2 + 1] - aP[ai + rp * 2 + 1] + brv;
                float vi1 = aOi[ai + rp * 2 + 1] + biv;
                float2 orv, oiv;
                orv.x = vr0 * xr.x - vi0 * xi.x;
                oiv.x = vr0 * xi.x + vi0 * xr.x;
                orv.y = vr1 * xr.y - vi1 * xi.y;
                oiv.y = vr1 * xi.y + vi1 * xr.y;
                *(float2*)&g_outR[gi] = orv;
                *(float2*)&g_outI[gi] = oiv;
            }
        }
    }
}

// ---------------------------------------------------------------------------
__global__ void __launch_bounds__(NT_F, 2) kfft_inv(float* __restrict__ y) {
    extern __shared__ float sm[];
    float* R   = sm;
    float* I   = sm + UBUF;
    float* twR = sm + 2 * UBUF;
    float* twI = twR + 64;

    const int tid = threadIdx.x;
    const int img = blockIdx.x;

    if (tid < 64) {
        float s, c;
        sincospif((float)tid / 64.0f, &s, &c);
        twR[tid] = c; twI[tid] = s;
    }

    const float* srcR = g_outR + (size_t)img * F_;
    const float* srcI = g_outI + (size_t)img * F_;
    for (int t = tid; t < F_; t += NT_F) {
        int h = t / WF_, k = t - h * WF_;
        int hb = brev7(h);
        R[hb * CPIT + k] = srcR[t];
        I[hb * CPIT + k] = srcI[t];
    }
    __syncthreads();

    pass8_cols<1>(R, I, twR, twI); __syncthreads();
    pass8_cols<4>(R, I, twR, twI); __syncthreads();
    pass2_cols   (R, I, twR, twI); __syncthreads();

    float zr[16], zi[16];
    #pragma unroll
    for (int n = 0; n < 16; n++) {
        int it = tid + n * NT_F;
        int w = it & 127, p = it >> 7;
        int r0 = (2 * p) * CPIT, r1 = r0 + CPIT;
        if (w <= 64) {
            float x0r = R[r0 + w], x0i = I[r0 + w];
            float x1r = R[r1 + w], x1i = I[r1 + w];
            if (w == 0 || w == 64) { x0i = 0.f; x1i = 0.f; }
            zr[n] = x0r - x1i;
            zi[n] = x0i + x1r;
        } else {
            int m = 128 - w;
            float x0r = R[r0 + m], x0i = I[r0 + m];
            float x1r = R[r1 + m], x1i = I[r1 + m];
            zr[n] = x0r + x1i;
            zi[n] = x1r - x0i;
        }
    }
    __syncthreads();
    #pragma unroll
    for (int n = 0; n < 16; n++) {
        int it = tid + n * NT_F;
        int w = it & 127, p = it >> 7;
        int wb = brev7(w);
        R[p * RPIT + wb] = zr[n];
        I[p * RPIT + wb] = zi[n];
    }
    __syncthreads();

    pass8_rows<1>(R, I, twR, twI); __syncthreads();
    pass8_rows<4>(R, I, twR, twI); __syncthreads();
    pass2_rows   (R, I, twR, twI); __syncthreads();

    float* dst = y + (size_t)img * (H_ * W_);
    const float sc = 1.0f / 128.0f;
    for (int t = tid; t < 64 * 128; t += NT_F) {
        int p = t >> 7, c = t & 127;
        dst[(2 * p) * 128 + c]       = R[p * RPIT + c] * sc;
        dst[(2 * p) * 128 + 128 + c] = I[p * RPIT + c] * sc;
    }
}

// ---------------------------------------------------------------------------
extern "C" void kernel_launch(void* const* d_in, const int* in_sizes, int n_in,
                              void* d_out, int out_size) {
    const float* x  = (const float*)d_in[0];
    const float* w1 = (const float*)d_in[1];
    const float* w2 = (const float*)d_in[2];
    const float* b1 = (const float*)d_in[3];
    const float* b2 = (const float*)d_in[4];
    float* y = (float*)d_out;

    const int smFFT = (2 * UBUF + 128) * (int)sizeof(float);   // ~65.5 KB

    cudaFuncSetAttribute(kfft_fwd, cudaFuncAttributeMaxDynamicSharedMemorySize, smFFT);
    cudaFuncSetAttribute(kmixL1,   cudaFuncAttributeMaxDynamicSharedMemorySize, SM_L1);
    cudaFuncSetAttribute(kmixL2,   cudaFuncAttributeMaxDynamicSharedMemorySize, SM_L2);
    cudaFuncSetAttribute(kfft_inv, cudaFuncAttributeMaxDynamicSharedMemorySize, smFFT);

    wprep<<<1024, 256>>>(w1, w2);
    kfft_fwd<<<NIMG, NT_F, smFFT>>>(x);
    kmixL1<<<dim3(32, NCHUNK), NT_M, SM_L1>>>(b1);
    kmixL2<<<dim3(32, NCHUNK), NT_M, SM_L2>>>(b2);
    kfft_inv<<<NIMG, NT_F, smFFT>>>(y);
}

// round 14
// speedup vs baseline: 1.2263x; 1.0234x over previous
#include <cuda_runtime.h>
#include <cuda_bf16.h>
#include <math.h>
#include <stdint.h>

#define B_   8
#define C_   512
#define G_   4
#define D_   128
#define H_   128
#define W_   128
#define WF_  65
#define F_   (H_*WF_)        // 8320
#define NIMG (B_*C_)         // 4096

// Scratch (allocation-free requirement -> device globals).
static __device__ float g_specR[(size_t)NIMG * F_];
static __device__ float g_specI[(size_t)NIMG * F_];
static __device__ float g_outR [(size_t)NIMG * F_];
static __device__ float g_outI [(size_t)NIMG * F_];
static __device__ unsigned short g_wimg[32 * 128 * 136];            // pre-split W planes
static __device__ unsigned short g_o1[(size_t)32 * 260 * 16384];    // O1 planes (~273MB)

#define RPIT 129
#define CPIT 65
#define UBUF 8320
#define NT_F 512

#define WP    136           // bf16 plane pitch (shorts)
#define PLW   (128 * WP)    // W plane elems (17408)
#define PLX32 (32 * WP)     // X plane elems, N=32 tile (4352)
#define NTILE 260           // 8320 / 32
#define NCHUNK 9
#define RPITCH 36           // raw staging pitch (floats)
#define NT_M  512           // mixer threads (16 warps)

__device__ __forceinline__ int brev7(int v) { return (int)(__brev((unsigned)v) >> 25); }

__device__ __forceinline__ void split_bf16(float v, unsigned short& h, unsigned short& l) {
    __nv_bfloat16 hb = __float2bfloat16(v);
    float r = v - __bfloat162float(hb);
    h = __bfloat16_as_ushort(hb);
    l = __bfloat16_as_ushort(__float2bfloat16(r));
}

__device__ __forceinline__ uint32_t smem_u32(const void* p) {
    uint32_t a;
    asm("{ .reg .u64 t; cvta.to.shared.u64 t, %1; cvt.u32.u64 %0, t; }" : "=r"(a) : "l"(p));
    return a;
}
#define CP_ASYNC16(dst, src) \
    asm volatile("cp.async.cg.shared.global [%0], [%1], 16;" :: "r"(dst), "l"(src))
#define CP_COMMIT() asm volatile("cp.async.commit_group;" ::: "memory")
#define CP_WAIT0()  asm volatile("cp.async.wait_group 0;"  ::: "memory")

#define LDSM_X4(r, addr) \
    asm volatile("ldmatrix.sync.aligned.m8n8.x4.shared.b16 {%0,%1,%2,%3}, [%4];" \
        : "=r"((r)[0]), "=r"((r)[1]), "=r"((r)[2]), "=r"((r)[3]) : "r"(addr))

// ---------------------------------------------------------------------------
// Weight prep
// ---------------------------------------------------------------------------
__global__ void __launch_bounds__(256) wprep(const float* __restrict__ w1,
                                             const float* __restrict__ w2) {
    int idx = blockIdx.x * 256 + threadIdx.x;      // 262144
    int m    = idx & 127;
    int k    = (idx >> 7) & 127;
    int part = (idx >> 14) & 1;
    int g    = (idx >> 15) & 3;
    int l    = (idx >> 17) & 1;
    const float* src = l ? w2 : w1;
    float v = src[(((size_t)(part * 4 + g) * 128 + k) * 128) + m];
    unsigned short h, lo;
    split_bf16(v, h, lo);
    size_t base = (size_t)((l * 4 + g) * 4 + part * 2) * PLW;
    g_wimg[base + m * WP + k]       = h;
    g_wimg[base + PLW + m * WP + k] = lo;
}

// ============================ FFT passes ====================================
// Radix-8: three fused radix-2 stages S, S+1, S+2 (DIT, bit-reversed input).
template<int S>
__device__ __forceinline__ void pass8_rows(float* R, float* I,
                                           const float* twR, const float* twI) {
    const int h = 1 << (S - 1);
    for (int it = threadIdx.x; it < 64 * 16; it += NT_F) {
        int r = it & 63, q = it >> 6;
        int j = q & (h - 1);
        int base = (q >> (S - 1)) << (S + 2);
        int i0 = r * RPIT + base + j;
        float er[8], ei[8];
        #pragma unroll
        for (int k = 0; k < 8; k++) { er[k] = R[i0 + k * h]; ei[k] = I[i0 + k * h]; }
        {
            float wr = twR[j << (7 - S)], wi = twI[j << (7 - S)];
            #pragma unroll
            for (int k = 0; k < 8; k += 2) {
                float tr = er[k+1] * wr - ei[k+1] * wi;
                float ti = er[k+1] * wi + ei[k+1] * wr;
                er[k+1] = er[k] - tr; ei[k+1] = ei[k] - ti;
                er[k]  += tr;         ei[k]  += ti;
            }
        }
        {
            float w2r = twR[j << (6 - S)],       w2i = twI[j << (6 - S)];
            float w3r = twR[(j + h) << (6 - S)], w3i = twI[(j + h) << (6 - S)];
            #pragma unroll
            for (int gq = 0; gq < 8; gq += 4) {
                float tr = er[gq+2] * w2r - ei[gq+2] * w2i;
                float ti = er[gq+2] * w2i + ei[gq+2] * w2r;
                er[gq+2] = er[gq] - tr; ei[gq+2] = ei[gq] - ti;
                er[gq]  += tr;          ei[gq]  += ti;
                tr = er[gq+3] * w3r - ei[gq+3] * w3i;
                ti = er[gq+3] * w3i + ei[gq+3] * w3r;
                er[gq+3] = er[gq+1] - tr; ei[gq+3] = ei[gq+1] - ti;
                er[gq+1] += tr;           ei[gq+1] += ti;
            }
        }
        #pragma unroll
        for (int k = 0; k < 4; k++) {
            float wr = twR[(j + k * h) << (5 - S)], wi = twI[(j + k * h) << (5 - S)];
            float tr = er[k+4] * wr - ei[k+4] * wi;
            float ti = er[k+4] * wi + ei[k+4] * wr;
            er[k+4] = er[k] - tr; ei[k+4] = ei[k] - ti;
            er[k]  += tr;         ei[k]  += ti;
        }
        #pragma unroll
        for (int k = 0; k < 8; k++) { R[i0 + k * h] = er[k]; I[i0 + k * h] = ei[k]; }
    }
}

template<int S>
__device__ __forceinline__ void pass8_cols(float* R, float* I,
                                           const float* twR, const float* twI) {
    const int h = 1 << (S - 1);
    const int st = h * CPIT;
    for (int it = threadIdx.x; it < 65 * 16; it += NT_F) {
        int c = it % 65, q = it / 65;
        int j = q & (h - 1);
        int base = (q >> (S - 1)) << (S + 2);
        int i0 = (base + j) * CPIT + c;
        float er[8], ei[8];
        #pragma unroll
        for (int k = 0; k < 8; k++) { er[k] = R[i0 + k * st]; ei[k] = I[i0 + k * st]; }
        {
            float wr = twR[j << (7 - S)], wi = twI[j << (7 - S)];
            #pragma unroll
            for (int k = 0; k < 8; k += 2) {
                float tr = er[k+1] * wr - ei[k+1] * wi;
                float ti = er[k+1] * wi + ei[k+1] * wr;
                er[k+1] = er[k] - tr; ei[k+1] = ei[k] - ti;
                er[k]  += tr;         ei[k]  += ti;
            }
        }
        {
            float w2r = twR[j << (6 - S)],       w2i = twI[j << (6 - S)];
            float w3r = twR[(j + h) << (6 - S)], w3i = twI[(j + h) << (6 - S)];
            #pragma unroll
            for (int gq = 0; gq < 8; gq += 4) {
                float tr = er[gq+2] * w2r - ei[gq+2] * w2i;
                float ti = er[gq+2] * w2i + ei[gq+2] * w2r;
                er[gq+2] = er[gq] - tr; ei[gq+2] = ei[gq] - ti;
                er[gq]  += tr;          ei[gq]  += ti;
                tr = er[gq+3] * w3r - ei[gq+3] * w3i;
                ti = er[gq+3] * w3i + ei[gq+3] * w3r;
                er[gq+3] = er[gq+1] - tr; ei[gq+3] = ei[gq+1] - ti;
                er[gq+1] += tr;           ei[gq+1] += ti;
            }
        }
        #pragma unroll
        for (int k = 0; k < 4; k++) {
            float wr = twR[(j + k * h) << (5 - S)], wi = twI[(j + k * h) << (5 - S)];
            float tr = er[k+4] * wr - ei[k+4] * wi;
            float ti = er[k+4] * wi + ei[k+4] * wr;
            er[k+4] = er[k] - tr; ei[k+4] = ei[k] - ti;
            er[k]  += tr;         ei[k]  += ti;
        }
        #pragma unroll
        for (int k = 0; k < 8; k++) { R[i0 + k * st] = er[k]; I[i0 + k * st] = ei[k]; }
    }
}

// Radix-16: fused radix-2 stages 4,5,6,7 (h=8..64). Each thread: 16 elems j+8k.
__device__ __forceinline__ void pass16_rows(float* R, float* I,
                                            const float* twR, const float* twI) {
    for (int it = threadIdx.x; it < 512; it += NT_F) {
        int r = it & 63, j = it >> 6;
        int i0 = r * RPIT + j;
        float er[16], ei[16];
        #pragma unroll
        for (int k = 0; k < 16; k++) { er[k] = R[i0 + 8 * k]; ei[k] = I[i0 + 8 * k]; }
        // stage 4 (half=8): pairs (k,k+1), tw[j<<3]
        {
            float wr = twR[j << 3], wi = twI[j << 3];
            #pragma unroll
            for (int k = 0; k < 16; k += 2) {
                float tr = er[k+1] * wr - ei[k+1] * wi;
                float ti = er[k+1] * wi + ei[k+1] * wr;
                er[k+1] = er[k] - tr; ei[k+1] = ei[k] - ti;
                er[k]  += tr;         ei[k]  += ti;
            }
        }
        // stage 5 (half=16): pairs (k,k+2), tw[(j+8*(k&1))<<2]
        {
            float w0r = twR[j << 2],       w0i = twI[j << 2];
            float w1r = twR[(j + 8) << 2], w1i = twI[(j + 8) << 2];
            #pragma unroll
            for (int b = 0; b < 16; b += 4) {
                float tr = er[b+2] * w0r - ei[b+2] * w0i;
                float ti = er[b+2] * w0i + ei[b+2] * w0r;
                er[b+2] = er[b] - tr; ei[b+2] = ei[b] - ti;
                er[b]  += tr;         ei[b]  += ti;
                tr = er[b+3] * w1r - ei[b+3] * w1i;
                ti = er[b+3] * w1i + ei[b+3] * w1r;
                er[b+3] = er[b+1] - tr; ei[b+3] = ei[b+1] - ti;
                er[b+1] += tr;          ei[b+1] += ti;
            }
        }
        // stage 6 (half=32): pairs (k,k+4), tw[(j+8*(k&3))<<1]
        #pragma unroll
        for (int b = 0; b < 16; b += 8) {
            #pragma unroll
            for (int m = 0; m < 4; m++) {
                float wr = twR[(j + 8 * m) << 1], wi = twI[(j + 8 * m) << 1];
                float tr = er[b+m+4] * wr - ei[b+m+4] * wi;
                float ti = er[b+m+4] * wi + ei[b+m+4] * wr;
                er[b+m+4] = er[b+m] - tr; ei[b+m+4] = ei[b+m] - ti;
                er[b+m]  += tr;           ei[b+m]  += ti;
            }
        }
        // stage 7 (half=64): pairs (m,m+8), tw[j+8m]
        #pragma unroll
        for (int m = 0; m < 8; m++) {
            float wr = twR[j + 8 * m], wi = twI[j + 8 * m];
            float tr = er[m+8] * wr - ei[m+8] * wi;
            float ti = er[m+8] * wi + ei[m+8] * wr;
            er[m+8] = er[m] - tr; ei[m+8] = ei[m] - ti;
            er[m]  += tr;         ei[m]  += ti;
        }
        #pragma unroll
        for (int k = 0; k < 16; k++) { R[i0 + 8 * k] = er[k]; I[i0 + 8 * k] = ei[k]; }
    }
}

__device__ __forceinline__ void pass16_cols(float* R, float* I,
                                            const float* twR, const float* twI) {
    for (int it = threadIdx.x; it < 65 * 8; it += NT_F) {
        int c = it % 65, j = it / 65;
        int i0 = j * CPIT + c;
        float er[16], ei[16];
        #pragma unroll
        for (int k = 0; k < 16; k++) { er[k] = R[i0 + 8 * k * CPIT]; ei[k] = I[i0 + 8 * k * CPIT]; }
        {
            float wr = twR[j << 3], wi = twI[j << 3];
            #pragma unroll
            for (int k = 0; k < 16; k += 2) {
                float tr = er[k+1] * wr - ei[k+1] * wi;
                float ti = er[k+1] * wi + ei[k+1] * wr;
                er[k+1] = er[k] - tr; ei[k+1] = ei[k] - ti;
                er[k]  += tr;         ei[k]  += ti;
            }
        }
        {
            float w0r = twR[j << 2],       w0i = twI[j << 2];
            float w1r = twR[(j + 8) << 2], w1i = twI[(j + 8) << 2];
            #pragma unroll
            for (int b = 0; b < 16; b += 4) {
                float tr = er[b+2] * w0r - ei[b+2] * w0i;
                float ti = er[b+2] * w0i + ei[b+2] * w0r;
                er[b+2] = er[b] - tr; ei[b+2] = ei[b] - ti;
                er[b]  += tr;         ei[b]  += ti;
                tr = er[b+3] * w1r - ei[b+3] * w1i;
                ti = er[b+3] * w1i + ei[b+3] * w1r;
                er[b+3] = er[b+1] - tr; ei[b+3] = ei[b+1] - ti;
                er[b+1] += tr;          ei[b+1] += ti;
            }
        }
        #pragma unroll
        for (int b = 0; b < 16; b += 8) {
            #pragma unroll
            for (int m = 0; m < 4; m++) {
                float wr = twR[(j + 8 * m) << 1], wi = twI[(j + 8 * m) << 1];
                float tr = er[b+m+4] * wr - ei[b+m+4] * wi;
                float ti = er[b+m+4] * wi + ei[b+m+4] * wr;
                er[b+m+4] = er[b+m] - tr; ei[b+m+4] = ei[b+m] - ti;
                er[b+m]  += tr;           ei[b+m]  += ti;
            }
        }
        #pragma unroll
        for (int m = 0; m < 8; m++) {
            float wr = twR[j + 8 * m], wi = twI[j + 8 * m];
            float tr = er[m+8] * wr - ei[m+8] * wi;
            float ti = er[m+8] * wi + ei[m+8] * wr;
            er[m+8] = er[m] - tr; ei[m+8] = ei[m] - ti;
            er[m]  += tr;         ei[m]  += ti;
        }
        #pragma unroll
        for (int k = 0; k < 16; k++) { R[i0 + 8 * k * CPIT] = er[k]; I[i0 + 8 * k * CPIT] = ei[k]; }
    }
}

__global__ void __launch_bounds__(NT_F, 2) kfft_fwd(const float* __restrict__ x) {
    extern __shared__ float sm[];
    float* R   = sm;
    float* I   = sm + UBUF;
    float* twR = sm + 2 * UBUF;
    float* twI = twR + 64;

    const int tid = threadIdx.x;
    const int img = blockIdx.x;

    if (tid < 64) {
        float s, c;
        sincospif(-(float)tid / 64.0f, &s, &c);
        twR[tid] = c; twI[tid] = s;
    }

    const float* src = x + (size_t)img * (H_ * W_);
    for (int t = tid; t < 64 * 128; t += NT_F) {
        int p = t >> 7, c = t & 127;
        int cb = brev7(c);
        R[p * RPIT + cb] = src[(2 * p) * 128 + c];
        I[p * RPIT + cb] = src[(2 * p) * 128 + 128 + c];
    }
    __syncthreads();

    pass8_rows<1>(R, I, twR, twI); __syncthreads();
    pass16_rows  (R, I, twR, twI); __syncthreads();

    float u0r[9], u0i[9], u1r[9], u1i[9];
    #pragma unroll
    for (int n = 0; n < 9; n++) {
        int it = tid + n * NT_F;
        if (it < 64 * 65) {
            int k = it % 65, p = it / 65;
            int m = (128 - k) & 127;
            float a = R[p * RPIT + k], b = I[p * RPIT + k];
            float c2 = R[p * RPIT + m], d = I[p * RPIT + m];
            u0r[n] = 0.5f * (a + c2); u0i[n] = 0.5f * (b - d);
            u1r[n] = 0.5f * (b + d);  u1i[n] = 0.5f * (c2 - a);
        }
    }
    __syncthreads();
    #pragma unroll
    for (int n = 0; n < 9; n++) {
        int it = tid + n * NT_F;
        if (it < 64 * 65) {
            int k = it % 65, p = it / 65;
            int h0 = brev7(2 * p), h1 = brev7(2 * p + 1);
            R[h0 * CPIT + k] = u0r[n]; I[h0 * CPIT + k] = u0i[n];
            R[h1 * CPIT + k] = u1r[n]; I[h1 * CPIT + k] = u1i[n];
        }
    }
    __syncthreads();

    pass8_cols<1>(R, I, twR, twI); __syncthreads();
    pass16_cols  (R, I, twR, twI); __syncthreads();

    float* dR = g_specR + (size_t)img * F_;
    float* dI = g_specI + (size_t)img * F_;
    const float sc = 1.0f / 128.0f;
    for (int t = tid; t < F_; t += NT_F) {
        dR[t] = R[t] * sc;
        dI[t] = I[t] * sc;
    }
}

// ---------------------------------------------------------------------------
// Tensor-core mixer: 512 threads / 16 warps, warp tile m16 x n16, LDSM loads.
// ---------------------------------------------------------------------------
__device__ __forceinline__ void mma16816(float* d, const uint32_t* a, const uint32_t* b) {
    asm volatile("mma.sync.aligned.m16n8k16.row.col.f32.bf16.bf16.f32 "
        "{%0,%1,%2,%3}, {%4,%5,%6,%7}, {%8,%9}, {%0,%1,%2,%3};"
        : "+f"(d[0]), "+f"(d[1]), "+f"(d[2]), "+f"(d[3])
        : "r"(a[0]), "r"(a[1]), "r"(a[2]), "r"(a[3]), "r"(b[0]), "r"(b[1]));
}

// warp tile m16 (warp_m = (wid&7)*16) x n16 (warp_n = (wid>>3)*16, 2 x n8)
__device__ __forceinline__ void gemm32(uint32_t smW_a, uint32_t smX_a,
                                       float* aOr, float* aP, float* aOi,
                                       int warp_m, int warp_n, int lane) {
    const uint32_t aOff = (uint32_t)((warp_m + (lane & 15)) * WP + ((lane >> 4) << 3)) * 2;
    const uint32_t bOff = (uint32_t)((warp_n + ((lane >> 4) << 3) + (lane & 7)) * WP
                                     + (((lane >> 3) & 1) << 3)) * 2;
    #pragma unroll 1
    for (int kk = 0; kk < 8; kk++) {
        const uint32_t k0b = (uint32_t)kk * 32;
        uint32_t A[4][4];
        #pragma unroll
        for (int pl = 0; pl < 4; pl++)
            LDSM_X4(A[pl], smW_a + (uint32_t)pl * (PLW * 2) + aOff + k0b);
        uint32_t Bf[4][4];
        #pragma unroll
        for (int pl = 0; pl < 4; pl++)
            LDSM_X4(Bf[pl], smX_a + (uint32_t)pl * (PLX32 * 2) + bOff + k0b);
        #pragma unroll
        for (int nt = 0; nt < 2; nt++) {
            float* dOr = aOr + nt * 4;
            float* dP  = aP  + nt * 4;
            float* dOi = aOi + nt * 4;
            const uint32_t* bR  = &Bf[0][nt * 2];
            const uint32_t* bRl = &Bf[1][nt * 2];
            const uint32_t* bI  = &Bf[2][nt * 2];
            const uint32_t* bIl = &Bf[3][nt * 2];
            mma16816(dOr, A[0], bR);
            mma16816(dOr, A[1], bR);
            mma16816(dOr, A[0], bRl);
            mma16816(dP,  A[2], bI);
            mma16816(dP,  A[3], bI);
            mma16816(dP,  A[2], bIl);
            mma16816(dOi, A[2], bR);
            mma16816(dOi, A[3], bR);
            mma16816(dOi, A[2], bRl);
            mma16816(dOi, A[0], bI);
            mma16816(dOi, A[1], bI);
            mma16816(dOi, A[0], bIl);
        }
    }
}

__device__ __forceinline__ void chunk_range(int c, int& start, int& cnt) {
    start = c * 29;
    cnt   = (c == 8) ? 28 : 29;
}

// L1 smem: W planes | X planes | raw staging
#define L1_OFF_X   (4 * PLW * 2)                     // 139264
#define L1_OFF_RAW (L1_OFF_X + 4 * PLX32 * 2)        // 174080
#define SM_L1      (L1_OFF_RAW + 2 * 128 * RPITCH * 4)  // 210944
// L2 smem: W planes | 2x X plane buffers
#define L2_OFF_X   (4 * PLW * 2)
#define SM_L2      (L2_OFF_X + 2 * 4 * PLX32 * 2)       // 208896

// ================= Layer 1 kernel =================
__global__ void __launch_bounds__(NT_M, 1)
kmixL1(const float* __restrict__ b1) {
    extern __shared__ char smem[];
    unsigned short* smW = (unsigned short*)smem;
    unsigned short* smX = (unsigned short*)(smem + L1_OFF_X);
    float*          raw = (float*)(smem + L1_OFF_RAW);
    const uint32_t raw_u32 = smem_u32(raw);
    const uint32_t smW_a = smem_u32(smW);
    const uint32_t smX_a = smem_u32(smX);

    const int tid = threadIdx.x;
    const int wid = tid >> 5, lane = tid & 31;
    const int gid = lane >> 2, tig = lane & 3;
    const int warp_m = (wid & 7) * 16;
    const int warp_n = (wid >> 3) * 16;
    const int bg = blockIdx.x;
    const int b = bg >> 2, g = bg & 3;
    int start, cnt;
    chunk_range(blockIdx.y, start, cnt);
    const int end = start + cnt;

    const size_t chanbase = ((size_t)b * C_ + (size_t)g * D_) * F_;

    // prefetch first tile raw spec (async)
    {
        for (int i = tid; i < 2048; i += NT_M) {
            int pl = i >> 10, rem = i & 1023, c = rem >> 3, seg = rem & 7;
            const float* src = (pl ? g_specI : g_specR) + chanbase + (size_t)c * F_
                             + (size_t)start * 32 + seg * 4;
            uint32_t dst = raw_u32 + (uint32_t)(pl * (128 * RPITCH * 4) + c * (RPITCH * 4) + seg * 16);
            CP_ASYNC16(dst, src);
        }
        CP_COMMIT();
    }

    // W1 planes: once per CTA
    {
        const float4* ws = (const float4*)(g_wimg + (size_t)(0 * 4 + g) * 4 * PLW);
        float4* wd = (float4*)smW;
        for (int i = tid; i < 4 * PLW / 8; i += NT_M) wd[i] = ws[i];
    }

    // bias values (fixed rows per warp)
    const int r0 = warp_m + gid;
    const float br0  = b1[g * D_ + r0];
    const float br1_ = b1[g * D_ + r0 + 8];
    const float bi0  = b1[(G_ + g) * D_ + r0];
    const float bi1_ = b1[(G_ + g) * D_ + r0 + 8];

    for (int t = start; t < end; t++) {
        CP_WAIT0();
        __syncthreads();

        // convert raw -> X planes (split); 4096 elems / 512 threads
        #pragma unroll
        for (int n = 0; n < 8; n++) {
            int it = tid + n * NT_M;
            int c = it >> 5, f = it & 31;
            float vr = raw[c * RPITCH + f];
            float vi = raw[128 * RPITCH + c * RPITCH + f];
            unsigned short rh, rl, ih, il;
            split_bf16(vr, rh, rl);
            split_bf16(vi, ih, il);
            int o = f * WP + c;
            smX[o] = rh; smX[PLX32 + o] = rl;
            smX[2 * PLX32 + o] = ih; smX[3 * PLX32 + o] = il;
        }
        __syncthreads();

        // prefetch next tile raw (overlaps GEMM)
        if (t + 1 < end) {
            for (int i = tid; i < 2048; i += NT_M) {
                int pl = i >> 10, rem = i & 1023, c = rem >> 3, seg = rem & 7;
                const float* src = (pl ? g_specI : g_specR) + chanbase + (size_t)c * F_
                                 + (size_t)(t + 1) * 32 + seg * 4;
                uint32_t dst = raw_u32 + (uint32_t)(pl * (128 * RPITCH * 4) + c * (RPITCH * 4) + seg * 16);
                CP_ASYNC16(dst, src);
            }
            CP_COMMIT();
        }

        float aOr[8], aP[8], aOi[8];
        #pragma unroll
        for (int i = 0; i < 8; i++) { aOr[i] = 0.f; aP[i] = 0.f; aOi[i] = 0.f; }
        gemm32(smW_a, smX_a, aOr, aP, aOi, warp_m, warp_n, lane);
        __syncthreads();

        // epilogue: bias + relu, split, write O1 planes back into smX
        #pragma unroll
        for (int nt = 0; nt < 2; nt++) {
            int c0 = warp_n + nt * 8 + tig * 2;
            int ai = nt * 4;
            #pragma unroll
            for (int e = 0; e < 4; e++) {
                int row = (e >= 2) ? r0 + 8 : r0;
                int col = c0 + (e & 1);
                float brv = (e >= 2) ? br1_ : br0;
                float biv = (e >= 2) ? bi1_ : bi0;
                float vr = aOr[ai + e] - aP[ai + e] + brv; vr = vr > 0.f ? vr : 0.f;
                float vi = aOi[ai + e] + biv;              vi = vi > 0.f ? vi : 0.f;
                unsigned short rh, rl, ih, il;
                split_bf16(vr, rh, rl);
                split_bf16(vi, ih, il);
                int o = col * WP + row;
                smX[o] = rh; smX[PLX32 + o] = rl;
                smX[2 * PLX32 + o] = ih; smX[3 * PLX32 + o] = il;
            }
        }
        __syncthreads();

        // coalesced copy-out smX planes -> g_o1: 4 planes x 32 f x 16 uint4
        {
            uint4* dst = (uint4*)(g_o1 + ((size_t)bg * NTILE + t) * 16384);
            for (int i = tid; i < 2048; i += NT_M) {
                int pl = i >> 9, rem = i & 511, f = rem >> 4, c16 = rem & 15;
                dst[i] = *(const uint4*)(smX + pl * PLX32 + f * WP + c16 * 8);
            }
        }
    }
}

// ================= Layer 2 kernel =================
__global__ void __launch_bounds__(NT_M, 1)
kmixL2(const float* __restrict__ b2) {
    extern __shared__ char smem[];
    unsigned short* smW  = (unsigned short*)smem;
    unsigned short* smX0 = (unsigned short*)(smem + L2_OFF_X);
    const uint32_t smW_a = smem_u32(smW);

    const int tid = threadIdx.x;
    const int wid = tid >> 5, lane = tid & 31;
    const int gid = lane >> 2, tig = lane & 3;
    const int warp_m = (wid & 7) * 16;
    const int warp_n = (wid >> 3) * 16;
    const int bg = blockIdx.x;
    const int b = bg >> 2, g = bg & 3;
    int start, cnt;
    chunk_range(blockIdx.y, start, cnt);
    const int end = start + cnt;

    const size_t chanbase = ((size_t)b * C_ + (size_t)g * D_) * F_;

    // prefetch first tile O1 planes into buf0
    {
        const uint4* src = (const uint4*)(g_o1 + ((size_t)bg * NTILE + start) * 16384);
        uint32_t bufb = smem_u32(smX0);
        for (int i = tid; i < 2048; i += NT_M) {
            int pl = i >> 9, rem = i & 511, f = rem >> 4, c16 = rem & 15;
            uint32_t dst = bufb + (uint32_t)((pl * PLX32 + f * WP) * 2 + c16 * 16);
            CP_ASYNC16(dst, src + i);
        }
        CP_COMMIT();
    }

    // W2 planes
    {
        const float4* ws = (const float4*)(g_wimg + (size_t)(1 * 4 + g) * 4 * PLW);
        float4* wd = (float4*)smW;
        for (int i = tid; i < 4 * PLW / 8; i += NT_M) wd[i] = ws[i];
    }

    const int r0 = warp_m + gid;
    const float br0  = b2[g * D_ + r0];
    const float br1_ = b2[g * D_ + r0 + 8];
    const float bi0  = b2[(G_ + g) * D_ + r0];
    const float bi1_ = b2[(G_ + g) * D_ + r0 + 8];

    for (int t = start; t < end; t++) {
        unsigned short* buf = smX0 + ((t - start) & 1) * (4 * PLX32);
        CP_WAIT0();
        __syncthreads();

        // prefetch next tile into other buffer (overlaps GEMM)
        if (t + 1 < end) {
            unsigned short* nb = smX0 + (((t - start) + 1) & 1) * (4 * PLX32);
            const uint4* src = (const uint4*)(g_o1 + ((size_t)bg * NTILE + (t + 1)) * 16384);
            uint32_t bufb = smem_u32(nb);
            for (int i = tid; i < 2048; i += NT_M) {
                int pl = i >> 9, rem = i & 511, f = rem >> 4, c16 = rem & 15;
                uint32_t dst = bufb + (uint32_t)((pl * PLX32 + f * WP) * 2 + c16 * 16);
                CP_ASYNC16(dst, src + i);
            }
            CP_COMMIT();
        }

        // prefetch origin spec values into registers (consumed in epilogue)
        float2 oxr[4], oxi[4];
        #pragma unroll
        for (int nt = 0; nt < 2; nt++)
            #pragma unroll
            for (int rp = 0; rp < 2; rp++) {
                int row = r0 + rp * 8;
                int c0  = warp_n + nt * 8 + tig * 2;
                size_t gi = chanbase + (size_t)row * F_ + (size_t)t * 32 + c0;
                int idx = nt * 2 + rp;
                oxr[idx] = *(const float2*)&g_specR[gi];
                oxi[idx] = *(const float2*)&g_specI[gi];
            }

        float aOr[8], aP[8], aOi[8];
        #pragma unroll
        for (int i = 0; i < 8; i++) { aOr[i] = 0.f; aP[i] = 0.f; aOi[i] = 0.f; }
        gemm32(smW_a, smem_u32(buf), aOr, aP, aOi, warp_m, warp_n, lane);

        // epilogue: bias, multiply by origin, store
        #pragma unroll
        for (int nt = 0; nt < 2; nt++) {
            int c0 = warp_n + nt * 8 + tig * 2;
            int ai = nt * 4;
            #pragma unroll
            for (int rp = 0; rp < 2; rp++) {
                int row = r0 + rp * 8;
                float brv = rp ? br1_ : br0;
                float biv = rp ? bi1_ : bi0;
                int idx = nt * 2 + rp;
                float2 xr = oxr[idx], xi = oxi[idx];
                size_t gi = chanbase + (size_t)row * F_ + (size_t)t * 32 + c0;
                float vr0 = aOr[ai + rp * 2]     - aP[ai + rp * 2]     + brv;
                float vi0 = aOi[ai + rp * 2]     + biv;
                float vr1 = aOr[ai + rp * 2 + 1] - aP[ai + rp * 2 + 1] + brv;
                float vi1 = aOi[ai + rp * 2 + 1] + biv;
                float2 orv, oiv;
                orv.x = vr0 * xr.x - vi0 * xi.x;
                oiv.x = vr0 * xi.x + vi0 * xr.x;
                orv.y = vr1 * xr.y - vi1 * xi.y;
                oiv.y = vr1 * xi.y + vi1 * xr.y;
                *(float2*)&g_outR[gi] = orv;
                *(float2*)&g_outI[gi] = oiv;
            }
        }
    }
}

// ---------------------------------------------------------------------------
__global__ void __launch_bounds__(NT_F, 2) kfft_inv(float* __restrict__ y) {
    extern __shared__ float sm[];
    float* R   = sm;
    float* I   = sm + UBUF;
    float* twR = sm + 2 * UBUF;
    float* twI = twR + 64;

    const int tid = threadIdx.x;
    const int img = blockIdx.x;

    if (tid < 64) {
        float s, c;
        sincospif((float)tid / 64.0f, &s, &c);
        twR[tid] = c; twI[tid] = s;
    }

    const float* srcR = g_outR + (size_t)img * F_;
    const float* srcI = g_outI + (size_t)img * F_;
    for (int t = tid; t < F_; t += NT_F) {
        int h = t / WF_, k = t - h * WF_;
        int hb = brev7(h);
        R[hb * CPIT + k] = srcR[t];
        I[hb * CPIT + k] = srcI[t];
    }
    __syncthreads();

    pass8_cols<1>(R, I, twR, twI); __syncthreads();
    pass16_cols  (R, I, twR, twI); __syncthreads();

    float zr[16], zi[16];
    #pragma unroll
    for (int n = 0; n < 16; n++) {
        int it = tid + n * NT_F;
        int w = it & 127, p = it >> 7;
        int r0 = (2 * p) * CPIT, r1 = r0 + CPIT;
        if (w <= 64) {
            float x0r = R[r0 + w], x0i = I[r0 + w];
            float x1r = R[r1 + w], x1i = I[r1 + w];
            if (w == 0 || w == 64) { x0i = 0.f; x1i = 0.f; }
            zr[n] = x0r - x1i;
            zi[n] = x0i + x1r;
        } else {
            int m = 128 - w;
            float x0r = R[r0 + m], x0i = I[r0 + m];
            float x1r = R[r1 + m], x1i = I[r1 + m];
            zr[n] = x0r + x1i;
            zi[n] = x1r - x0i;
        }
    }
    __syncthreads();
    #pragma unroll
    for (int n = 0; n < 16; n++) {
        int it = tid + n * NT_F;
        int w = it & 127, p = it >> 7;
        int wb = brev7(w);
        R[p * RPIT + wb] = zr[n];
        I[p * RPIT + wb] = zi[n];
    }
    __syncthreads();

    pass8_rows<1>(R, I, twR, twI); __syncthreads();
    pass16_rows  (R, I, twR, twI); __syncthreads();

    float* dst = y + (size_t)img * (H_ * W_);
    const float sc = 1.0f / 128.0f;
    for (int t = tid; t < 64 * 128; t += NT_F) {
        int p = t >> 7, c = t & 127;
        dst[(2 * p) * 128 + c]       = R[p * RPIT + c] * sc;
        dst[(2 * p) * 128 + 128 + c] = I[p * RPIT + c] * sc;
    }
}

// ---------------------------------------------------------------------------
extern "C" void kernel_launch(void* const* d_in, const int* in_sizes, int n_in,
                              void* d_out, int out_size) {
    const float* x  = (const float*)d_in[0];
    const float* w1 = (const float*)d_in[1];
    const float* w2 = (const float*)d_in[2];
    const float* b1 = (const float*)d_in[3];
    const float* b2 = (const float*)d_in[4];
    float* y = (float*)d_out;

    const int smFFT = (2 * UBUF + 128) * (int)sizeof(float);   // ~65.5 KB

    cudaFuncSetAttribute(kfft_fwd, cudaFuncAttributeMaxDynamicSharedMemorySize, smFFT);
    cudaFuncSetAttribute(kmixL1,   cudaFuncAttributeMaxDynamicSharedMemorySize, SM_L1);
    cudaFuncSetAttribute(kmixL2,   cudaFuncAttributeMaxDynamicSharedMemorySize, SM_L2);
    cudaFuncSetAttribute(kfft_inv, cudaFuncAttributeMaxDynamicSharedMemorySize, smFFT);

    wprep<<<1024, 256>>>(w1, w2);
    kfft_fwd<<<NIMG, NT_F, smFFT>>>(x);
    kmixL1<<<dim3(32, NCHUNK), NT_M, SM_L1>>>(b1);
    kmixL2<<<dim3(32, NCHUNK), NT_M, SM_L2>>>(b2);
    kfft_inv<<<NIMG, NT_F, smFFT>>>(y);
}

// round 15
// speedup vs baseline: 1.2741x; 1.0390x over previous
#include <cuda_runtime.h>
#include <cuda_bf16.h>
#include <math.h>
#include <stdint.h>

#define B_   8
#define C_   512
#define G_   4
#define D_   128
#define H_   128
#define W_   128
#define WF_  65
#define F_   (H_*WF_)        // 8320
#define NIMG (B_*C_)         // 4096

// Scratch (allocation-free requirement -> device globals).
static __device__ float g_specR[(size_t)NIMG * F_];
static __device__ float g_specI[(size_t)NIMG * F_];
static __device__ float g_outR [(size_t)NIMG * F_];
static __device__ float g_outI [(size_t)NIMG * F_];
static __device__ unsigned short g_wimg[32 * 128 * 136];            // pre-split W planes
static __device__ unsigned short g_o1[(size_t)32 * 260 * 16384];    // O1 planes (~273MB)

#define RPIT 129
#define CPIT 65
#define UBUF 8320
#define NT_F 512

#define WP    136           // bf16 plane pitch (shorts)
#define PLW   (128 * WP)    // W plane elems (17408)
#define PLX32 (32 * WP)     // X plane elems, N=32 tile (4352)
#define NTILE 260           // 8320 / 32
#define NCHUNK 9
#define RPITCH 36           // raw staging pitch (floats)
#define NT_M  512           // mixer threads (16 warps)

__device__ __forceinline__ int brev7(int v) { return (int)(__brev((unsigned)v) >> 25); }

__device__ __forceinline__ void split_bf16(float v, unsigned short& h, unsigned short& l) {
    __nv_bfloat16 hb = __float2bfloat16(v);
    float r = v - __bfloat162float(hb);
    h = __bfloat16_as_ushort(hb);
    l = __bfloat16_as_ushort(__float2bfloat16(r));
}

__device__ __forceinline__ uint32_t smem_u32(const void* p) {
    uint32_t a;
    asm("{ .reg .u64 t; cvta.to.shared.u64 t, %1; cvt.u32.u64 %0, t; }" : "=r"(a) : "l"(p));
    return a;
}
#define CP_ASYNC16(dst, src) \
    asm volatile("cp.async.cg.shared.global [%0], [%1], 16;" :: "r"(dst), "l"(src))
#define CP_COMMIT() asm volatile("cp.async.commit_group;" ::: "memory")
#define CP_WAIT0()  asm volatile("cp.async.wait_group 0;"  ::: "memory")

#define LDSM_X4(r, addr) \
    asm volatile("ldmatrix.sync.aligned.m8n8.x4.shared.b16 {%0,%1,%2,%3}, [%4];" \
        : "=r"((r)[0]), "=r"((r)[1]), "=r"((r)[2]), "=r"((r)[3]) : "r"(addr))

// ---------------------------------------------------------------------------
// Weight prep
// ---------------------------------------------------------------------------
__global__ void __launch_bounds__(256) wprep(const float* __restrict__ w1,
                                             const float* __restrict__ w2) {
    int idx = blockIdx.x * 256 + threadIdx.x;      // 262144
    int m    = idx & 127;
    int k    = (idx >> 7) & 127;
    int part = (idx >> 14) & 1;
    int g    = (idx >> 15) & 3;
    int l    = (idx >> 17) & 1;
    const float* src = l ? w2 : w1;
    float v = src[(((size_t)(part * 4 + g) * 128 + k) * 128) + m];
    unsigned short h, lo;
    split_bf16(v, h, lo);
    size_t base = (size_t)((l * 4 + g) * 4 + part * 2) * PLW;
    g_wimg[base + m * WP + k]       = h;
    g_wimg[base + PLW + m * WP + k] = lo;
}

// ============================ FFT passes ====================================
// Radix-8: three fused radix-2 stages S, S+1, S+2 (DIT, bit-reversed input).
template<int S>
__device__ __forceinline__ void pass8_rows(float* R, float* I,
                                           const float* twR, const float* twI) {
    const int h = 1 << (S - 1);
    for (int it = threadIdx.x; it < 64 * 16; it += NT_F) {
        int r = it & 63, q = it >> 6;
        int j = q & (h - 1);
        int base = (q >> (S - 1)) << (S + 2);
        int i0 = r * RPIT + base + j;
        float er[8], ei[8];
        #pragma unroll
        for (int k = 0; k < 8; k++) { er[k] = R[i0 + k * h]; ei[k] = I[i0 + k * h]; }
        {
            float wr = twR[j << (7 - S)], wi = twI[j << (7 - S)];
            #pragma unroll
            for (int k = 0; k < 8; k += 2) {
                float tr = er[k+1] * wr - ei[k+1] * wi;
                float ti = er[k+1] * wi + ei[k+1] * wr;
                er[k+1] = er[k] - tr; ei[k+1] = ei[k] - ti;
                er[k]  += tr;         ei[k]  += ti;
            }
        }
        {
            float w2r = twR[j << (6 - S)],       w2i = twI[j << (6 - S)];
            float w3r = twR[(j + h) << (6 - S)], w3i = twI[(j + h) << (6 - S)];
            #pragma unroll
            for (int gq = 0; gq < 8; gq += 4) {
                float tr = er[gq+2] * w2r - ei[gq+2] * w2i;
                float ti = er[gq+2] * w2i + ei[gq+2] * w2r;
                er[gq+2] = er[gq] - tr; ei[gq+2] = ei[gq] - ti;
                er[gq]  += tr;          ei[gq]  += ti;
                tr = er[gq+3] * w3r - ei[gq+3] * w3i;
                ti = er[gq+3] * w3i + ei[gq+3] * w3r;
                er[gq+3] = er[gq+1] - tr; ei[gq+3] = ei[gq+1] - ti;
                er[gq+1] += tr;           ei[gq+1] += ti;
            }
        }
        #pragma unroll
        for (int k = 0; k < 4; k++) {
            float wr = twR[(j + k * h) << (5 - S)], wi = twI[(j + k * h) << (5 - S)];
            float tr = er[k+4] * wr - ei[k+4] * wi;
            float ti = er[k+4] * wi + ei[k+4] * wr;
            er[k+4] = er[k] - tr; ei[k+4] = ei[k] - ti;
            er[k]  += tr;         ei[k]  += ti;
        }
        #pragma unroll
        for (int k = 0; k < 8; k++) { R[i0 + k * h] = er[k]; I[i0 + k * h] = ei[k]; }
    }
}

template<int S>
__device__ __forceinline__ void pass8_cols(float* R, float* I,
                                           const float* twR, const float* twI) {
    const int h = 1 << (S - 1);
    const int st = h * CPIT;
    for (int it = threadIdx.x; it < 65 * 16; it += NT_F) {
        int c = it % 65, q = it / 65;
        int j = q & (h - 1);
        int base = (q >> (S - 1)) << (S + 2);
        int i0 = (base + j) * CPIT + c;
        float er[8], ei[8];
        #pragma unroll
        for (int k = 0; k < 8; k++) { er[k] = R[i0 + k * st]; ei[k] = I[i0 + k * st]; }
        {
            float wr = twR[j << (7 - S)], wi = twI[j << (7 - S)];
            #pragma unroll
            for (int k = 0; k < 8; k += 2) {
                float tr = er[k+1] * wr - ei[k+1] * wi;
                float ti = er[k+1] * wi + ei[k+1] * wr;
                er[k+1] = er[k] - tr; ei[k+1] = ei[k] - ti;
                er[k]  += tr;         ei[k]  += ti;
            }
        }
        {
            float w2r = twR[j << (6 - S)],       w2i = twI[j << (6 - S)];
            float w3r = twR[(j + h) << (6 - S)], w3i = twI[(j + h) << (6 - S)];
            #pragma unroll
            for (int gq = 0; gq < 8; gq += 4) {
                float tr = er[gq+2] * w2r - ei[gq+2] * w2i;
                float ti = er[gq+2] * w2i + ei[gq+2] * w2r;
                er[gq+2] = er[gq] - tr; ei[gq+2] = ei[gq] - ti;
                er[gq]  += tr;          ei[gq]  += ti;
                tr = er[gq+3] * w3r - ei[gq+3] * w3i;
                ti = er[gq+3] * w3i + ei[gq+3] * w3r;
                er[gq+3] = er[gq+1] - tr; ei[gq+3] = ei[gq+1] - ti;
                er[gq+1] += tr;           ei[gq+1] += ti;
            }
        }
        #pragma unroll
        for (int k = 0; k < 4; k++) {
            float wr = twR[(j + k * h) << (5 - S)], wi = twI[(j + k * h) << (5 - S)];
            float tr = er[k+4] * wr - ei[k+4] * wi;
            float ti = er[k+4] * wi + ei[k+4] * wr;
            er[k+4] = er[k] - tr; ei[k+4] = ei[k] - ti;
            er[k]  += tr;         ei[k]  += ti;
        }
        #pragma unroll
        for (int k = 0; k < 8; k++) { R[i0 + k * st] = er[k]; I[i0 + k * st] = ei[k]; }
    }
}

// Radix-16: fused radix-2 stages 4,5,6,7 (h=8..64). Each thread: 16 elems j+8k.
__device__ __forceinline__ void pass16_rows(float* R, float* I,
                                            const float* twR, const float* twI) {
    for (int it = threadIdx.x; it < 512; it += NT_F) {
        int r = it & 63, j = it >> 6;
        int i0 = r * RPIT + j;
        float er[16], ei[16];
        #pragma unroll
        for (int k = 0; k < 16; k++) { er[k] = R[i0 + 8 * k]; ei[k] = I[i0 + 8 * k]; }
        {
            float wr = twR[j << 3], wi = twI[j << 3];
            #pragma unroll
            for (int k = 0; k < 16; k += 2) {
                float tr = er[k+1] * wr - ei[k+1] * wi;
                float ti = er[k+1] * wi + ei[k+1] * wr;
                er[k+1] = er[k] - tr; ei[k+1] = ei[k] - ti;
                er[k]  += tr;         ei[k]  += ti;
            }
        }
        {
            float w0r = twR[j << 2],       w0i = twI[j << 2];
            float w1r = twR[(j + 8) << 2], w1i = twI[(j + 8) << 2];
            #pragma unroll
            for (int b = 0; b < 16; b += 4) {
                float tr = er[b+2] * w0r - ei[b+2] * w0i;
                float ti = er[b+2] * w0i + ei[b+2] * w0r;
                er[b+2] = er[b] - tr; ei[b+2] = ei[b] - ti;
                er[b]  += tr;         ei[b]  += ti;
                tr = er[b+3] * w1r - ei[b+3] * w1i;
                ti = er[b+3] * w1i + ei[b+3] * w1r;
                er[b+3] = er[b+1] - tr; ei[b+3] = ei[b+1] - ti;
                er[b+1] += tr;          ei[b+1] += ti;
            }
        }
        #pragma unroll
        for (int b = 0; b < 16; b += 8) {
            #pragma unroll
            for (int m = 0; m < 4; m++) {
                float wr = twR[(j + 8 * m) << 1], wi = twI[(j + 8 * m) << 1];
                float tr = er[b+m+4] * wr - ei[b+m+4] * wi;
                float ti = er[b+m+4] * wi + ei[b+m+4] * wr;
                er[b+m+4] = er[b+m] - tr; ei[b+m+4] = ei[b+m] - ti;
                er[b+m]  += tr;           ei[b+m]  += ti;
            }
        }
        #pragma unroll
        for (int m = 0; m < 8; m++) {
            float wr = twR[j + 8 * m], wi = twI[j + 8 * m];
            float tr = er[m+8] * wr - ei[m+8] * wi;
            float ti = er[m+8] * wi + ei[m+8] * wr;
            er[m+8] = er[m] - tr; ei[m+8] = ei[m] - ti;
            er[m]  += tr;         ei[m]  += ti;
        }
        #pragma unroll
        for (int k = 0; k < 16; k++) { R[i0 + 8 * k] = er[k]; I[i0 + 8 * k] = ei[k]; }
    }
}

__device__ __forceinline__ void pass16_cols(float* R, float* I,
                                            const float* twR, const float* twI) {
    for (int it = threadIdx.x; it < 65 * 8; it += NT_F) {
        int c = it % 65, j = it / 65;
        int i0 = j * CPIT + c;
        float er[16], ei[16];
        #pragma unroll
        for (int k = 0; k < 16; k++) { er[k] = R[i0 + 8 * k * CPIT]; ei[k] = I[i0 + 8 * k * CPIT]; }
        {
            float wr = twR[j << 3], wi = twI[j << 3];
            #pragma unroll
            for (int k = 0; k < 16; k += 2) {
                float tr = er[k+1] * wr - ei[k+1] * wi;
                float ti = er[k+1] * wi + ei[k+1] * wr;
                er[k+1] = er[k] - tr; ei[k+1] = ei[k] - ti;
                er[k]  += tr;         ei[k]  += ti;
            }
        }
        {
            float w0r = twR[j << 2],       w0i = twI[j << 2];
            float w1r = twR[(j + 8) << 2], w1i = twI[(j + 8) << 2];
            #pragma unroll
            for (int b = 0; b < 16; b += 4) {
                float tr = er[b+2] * w0r - ei[b+2] * w0i;
                float ti = er[b+2] * w0i + ei[b+2] * w0r;
                er[b+2] = er[b] - tr; ei[b+2] = ei[b] - ti;
                er[b]  += tr;         ei[b]  += ti;
                tr = er[b+3] * w1r - ei[b+3] * w1i;
                ti = er[b+3] * w1i + ei[b+3] * w1r;
                er[b+3] = er[b+1] - tr; ei[b+3] = ei[b+1] - ti;
                er[b+1] += tr;          ei[b+1] += ti;
            }
        }
        #pragma unroll
        for (int b = 0; b < 16; b += 8) {
            #pragma unroll
            for (int m = 0; m < 4; m++) {
                float wr = twR[(j + 8 * m) << 1], wi = twI[(j + 8 * m) << 1];
                float tr = er[b+m+4] * wr - ei[b+m+4] * wi;
                float ti = er[b+m+4] * wi + ei[b+m+4] * wr;
                er[b+m+4] = er[b+m] - tr; ei[b+m+4] = ei[b+m] - ti;
                er[b+m]  += tr;           ei[b+m]  += ti;
            }
        }
        #pragma unroll
        for (int m = 0; m < 8; m++) {
            float wr = twR[j + 8 * m], wi = twI[j + 8 * m];
            float tr = er[m+8] * wr - ei[m+8] * wi;
            float ti = er[m+8] * wi + ei[m+8] * wr;
            er[m+8] = er[m] - tr; ei[m+8] = ei[m] - ti;
            er[m]  += tr;         ei[m]  += ti;
        }
        #pragma unroll
        for (int k = 0; k < 16; k++) { R[i0 + 8 * k * CPIT] = er[k]; I[i0 + 8 * k * CPIT] = ei[k]; }
    }
}

__global__ void __launch_bounds__(NT_F, 2) kfft_fwd(const float* __restrict__ x) {
    extern __shared__ float sm[];
    float* R   = sm;
    float* I   = sm + UBUF;
    float* twR = sm + 2 * UBUF;
    float* twI = twR + 64;

    const int tid = threadIdx.x;
    const int img = blockIdx.x;

    if (tid < 64) {
        float s, c;
        sincospif(-(float)tid / 64.0f, &s, &c);
        twR[tid] = c; twI[tid] = s;
    }

    const float* src = x + (size_t)img * (H_ * W_);
    for (int t = tid; t < 64 * 128; t += NT_F) {
        int p = t >> 7, c = t & 127;
        int cb = brev7(c);
        R[p * RPIT + cb] = src[(2 * p) * 128 + c];
        I[p * RPIT + cb] = src[(2 * p) * 128 + 128 + c];
    }
    __syncthreads();

    pass8_rows<1>(R, I, twR, twI); __syncthreads();
    pass16_rows  (R, I, twR, twI); __syncthreads();

    float u0r[9], u0i[9], u1r[9], u1i[9];
    #pragma unroll
    for (int n = 0; n < 9; n++) {
        int it = tid + n * NT_F;
        if (it < 64 * 65) {
            int k = it % 65, p = it / 65;
            int m = (128 - k) & 127;
            float a = R[p * RPIT + k], b = I[p * RPIT + k];
            float c2 = R[p * RPIT + m], d = I[p * RPIT + m];
            u0r[n] = 0.5f * (a + c2); u0i[n] = 0.5f * (b - d);
            u1r[n] = 0.5f * (b + d);  u1i[n] = 0.5f * (c2 - a);
        }
    }
    __syncthreads();
    #pragma unroll
    for (int n = 0; n < 9; n++) {
        int it = tid + n * NT_F;
        if (it < 64 * 65) {
            int k = it % 65, p = it / 65;
            int h0 = brev7(2 * p), h1 = brev7(2 * p + 1);
            R[h0 * CPIT + k] = u0r[n]; I[h0 * CPIT + k] = u0i[n];
            R[h1 * CPIT + k] = u1r[n]; I[h1 * CPIT + k] = u1i[n];
        }
    }
    __syncthreads();

    pass8_cols<1>(R, I, twR, twI); __syncthreads();
    pass16_cols  (R, I, twR, twI); __syncthreads();

    float* dR = g_specR + (size_t)img * F_;
    float* dI = g_specI + (size_t)img * F_;
    const float sc = 1.0f / 128.0f;
    for (int t = tid; t < F_; t += NT_F) {
        dR[t] = R[t] * sc;
        dI[t] = I[t] * sc;
    }
}

// ---------------------------------------------------------------------------
// Tensor-core mixer: 512 threads / 16 warps, warp tile m16 x n16, LDSM loads,
// software-pipelined k-loop (fragment double-buffering).
// ---------------------------------------------------------------------------
__device__ __forceinline__ void mma16816(float* d, const uint32_t* a, const uint32_t* b) {
    asm volatile("mma.sync.aligned.m16n8k16.row.col.f32.bf16.bf16.f32 "
        "{%0,%1,%2,%3}, {%4,%5,%6,%7}, {%8,%9}, {%0,%1,%2,%3};"
        : "+f"(d[0]), "+f"(d[1]), "+f"(d[2]), "+f"(d[3])
        : "r"(a[0]), "r"(a[1]), "r"(a[2]), "r"(a[3]), "r"(b[0]), "r"(b[1]));
}

__device__ __forceinline__ void ld_frags(uint32_t smW_a, uint32_t smX_a,
                                         uint32_t aOff, uint32_t bOff, uint32_t k0b,
                                         uint32_t A[4][4], uint32_t Bf[4][4]) {
    #pragma unroll
    for (int pl = 0; pl < 4; pl++)
        LDSM_X4(A[pl], smW_a + (uint32_t)pl * (PLW * 2) + aOff + k0b);
    #pragma unroll
    for (int pl = 0; pl < 4; pl++)
        LDSM_X4(Bf[pl], smX_a + (uint32_t)pl * (PLX32 * 2) + bOff + k0b);
}

__device__ __forceinline__ void mma_block(const uint32_t A[4][4], const uint32_t Bf[4][4],
                                          float* aOr, float* aP, float* aOi) {
    #pragma unroll
    for (int nt = 0; nt < 2; nt++) {
        float* dOr = aOr + nt * 4;
        float* dP  = aP  + nt * 4;
        float* dOi = aOi + nt * 4;
        const uint32_t* bR  = &Bf[0][nt * 2];
        const uint32_t* bRl = &Bf[1][nt * 2];
        const uint32_t* bI  = &Bf[2][nt * 2];
        const uint32_t* bIl = &Bf[3][nt * 2];
        mma16816(dOr, A[0], bR);
        mma16816(dOr, A[1], bR);
        mma16816(dOr, A[0], bRl);
        mma16816(dP,  A[2], bI);
        mma16816(dP,  A[3], bI);
        mma16816(dP,  A[2], bIl);
        mma16816(dOi, A[2], bR);
        mma16816(dOi, A[3], bR);
        mma16816(dOi, A[2], bRl);
        mma16816(dOi, A[0], bI);
        mma16816(dOi, A[1], bI);
        mma16816(dOi, A[0], bIl);
    }
}

// warp tile m16 (warp_m = (wid&7)*16) x n16 (warp_n = (wid>>3)*16, 2 x n8)
__device__ __forceinline__ void gemm32(uint32_t smW_a, uint32_t smX_a,
                                       float* aOr, float* aP, float* aOi,
                                       int warp_m, int warp_n, int lane) {
    const uint32_t aOff = (uint32_t)((warp_m + (lane & 15)) * WP + ((lane >> 4) << 3)) * 2;
    const uint32_t bOff = (uint32_t)((warp_n + ((lane >> 4) << 3) + (lane & 7)) * WP
                                     + (((lane >> 3) & 1) << 3)) * 2;
    uint32_t A[2][4][4], Bf[2][4][4];
    ld_frags(smW_a, smX_a, aOff, bOff, 0, A[0], Bf[0]);
    #pragma unroll
    for (int kk = 0; kk < 8; kk++) {
        const int cur = kk & 1, nxt = cur ^ 1;
        if (kk < 7)
            ld_frags(smW_a, smX_a, aOff, bOff, (uint32_t)(kk + 1) * 32, A[nxt], Bf[nxt]);
        mma_block(A[cur], Bf[cur], aOr, aP, aOi);
    }
}

__device__ __forceinline__ void chunk_range(int c, int& start, int& cnt) {
    start = c * 29;
    cnt   = (c == 8) ? 28 : 29;
}

// L1 smem: W planes | X planes | raw staging
#define L1_OFF_X   (4 * PLW * 2)                     // 139264
#define L1_OFF_RAW (L1_OFF_X + 4 * PLX32 * 2)        // 174080
#define SM_L1      (L1_OFF_RAW + 2 * 128 * RPITCH * 4)  // 210944
// L2 smem: W planes | 2x X plane buffers
#define L2_OFF_X   (4 * PLW * 2)
#define SM_L2      (L2_OFF_X + 2 * 4 * PLX32 * 2)       // 208896

// ================= Layer 1 kernel =================
__global__ void __launch_bounds__(NT_M, 1)
kmixL1(const float* __restrict__ b1) {
    extern __shared__ char smem[];
    unsigned short* smW = (unsigned short*)smem;
    unsigned short* smX = (unsigned short*)(smem + L1_OFF_X);
    float*          raw = (float*)(smem + L1_OFF_RAW);
    const uint32_t raw_u32 = smem_u32(raw);
    const uint32_t smW_a = smem_u32(smW);
    const uint32_t smX_a = smem_u32(smX);

    const int tid = threadIdx.x;
    const int wid = tid >> 5, lane = tid & 31;
    const int gid = lane >> 2, tig = lane & 3;
    const int warp_m = (wid & 7) * 16;
    const int warp_n = (wid >> 3) * 16;
    const int bg = blockIdx.x;
    const int b = bg >> 2, g = bg & 3;
    int start, cnt;
    chunk_range(blockIdx.y, start, cnt);
    const int end = start + cnt;

    const size_t chanbase = ((size_t)b * C_ + (size_t)g * D_) * F_;

    // prefetch first tile raw spec (async)
    {
        for (int i = tid; i < 2048; i += NT_M) {
            int pl = i >> 10, rem = i & 1023, c = rem >> 3, seg = rem & 7;
            const float* src = (pl ? g_specI : g_specR) + chanbase + (size_t)c * F_
                             + (size_t)start * 32 + seg * 4;
            uint32_t dst = raw_u32 + (uint32_t)(pl * (128 * RPITCH * 4) + c * (RPITCH * 4) + seg * 16);
            CP_ASYNC16(dst, src);
        }
        CP_COMMIT();
    }

    // W1 planes: once per CTA
    {
        const float4* ws = (const float4*)(g_wimg + (size_t)(0 * 4 + g) * 4 * PLW);
        float4* wd = (float4*)smW;
        for (int i = tid; i < 4 * PLW / 8; i += NT_M) wd[i] = ws[i];
    }

    // bias values (fixed rows per warp)
    const int r0 = warp_m + gid;
    const float br0  = b1[g * D_ + r0];
    const float br1_ = b1[g * D_ + r0 + 8];
    const float bi0  = b1[(G_ + g) * D_ + r0];
    const float bi1_ = b1[(G_ + g) * D_ + r0 + 8];

    for (int t = start; t < end; t++) {
        CP_WAIT0();
        __syncthreads();

        // convert raw -> X planes (split); 4096 elems / 512 threads
        #pragma unroll
        for (int n = 0; n < 8; n++) {
            int it = tid + n * NT_M;
            int c = it >> 5, f = it & 31;
            float vr = raw[c * RPITCH + f];
            float vi = raw[128 * RPITCH + c * RPITCH + f];
            unsigned short rh, rl, ih, il;
            split_bf16(vr, rh, rl);
            split_bf16(vi, ih, il);
            int o = f * WP + c;
            smX[o] = rh; smX[PLX32 + o] = rl;
            smX[2 * PLX32 + o] = ih; smX[3 * PLX32 + o] = il;
        }
        __syncthreads();

        // prefetch next tile raw (overlaps GEMM)
        if (t + 1 < end) {
            for (int i = tid; i < 2048; i += NT_M) {
                int pl = i >> 10, rem = i & 1023, c = rem >> 3, seg = rem & 7;
                const float* src = (pl ? g_specI : g_specR) + chanbase + (size_t)c * F_
                                 + (size_t)(t + 1) * 32 + seg * 4;
                uint32_t dst = raw_u32 + (uint32_t)(pl * (128 * RPITCH * 4) + c * (RPITCH * 4) + seg * 16);
                CP_ASYNC16(dst, src);
            }
            CP_COMMIT();
        }

        float aOr[8], aP[8], aOi[8];
        #pragma unroll
        for (int i = 0; i < 8; i++) { aOr[i] = 0.f; aP[i] = 0.f; aOi[i] = 0.f; }
        gemm32(smW_a, smX_a, aOr, aP, aOi, warp_m, warp_n, lane);
        __syncthreads();

        // epilogue: bias + relu, split, write O1 planes back into smX
        #pragma unroll
        for (int nt = 0; nt < 2; nt++) {
            int c0 = warp_n + nt * 8 + tig * 2;
            int ai = nt * 4;
            #pragma unroll
            for (int e = 0; e < 4; e++) {
                int row = (e >= 2) ? r0 + 8 : r0;
                int col = c0 + (e & 1);
                float brv = (e >= 2) ? br1_ : br0;
                float biv = (e >= 2) ? bi1_ : bi0;
                float vr = aOr[ai + e] - aP[ai + e] + brv; vr = vr > 0.f ? vr : 0.f;
                float vi = aOi[ai + e] + biv;              vi = vi > 0.f ? vi : 0.f;
                unsigned short rh, rl, ih, il;
                split_bf16(vr, rh, rl);
                split_bf16(vi, ih, il);
                int o = col * WP + row;
                smX[o] = rh; smX[PLX32 + o] = rl;
                smX[2 * PLX32 + o] = ih; smX[3 * PLX32 + o] = il;
            }
        }
        __syncthreads();

        // coalesced copy-out smX planes -> g_o1: 4 planes x 32 f x 16 uint4
        {
            uint4* dst = (uint4*)(g_o1 + ((size_t)bg * NTILE + t) * 16384);
            for (int i = tid; i < 2048; i += NT_M) {
                int pl = i >> 9, rem = i & 511, f = rem >> 4, c16 = rem & 15;
                dst[i] = *(const uint4*)(smX + pl * PLX32 + f * WP + c16 * 8);
            }
        }
    }
}

// ================= Layer 2 kernel =================
__global__ void __launch_bounds__(NT_M, 1)
kmixL2(const float* __restrict__ b2) {
    extern __shared__ char smem[];
    unsigned short* smW  = (unsigned short*)smem;
    unsigned short* smX0 = (unsigned short*)(smem + L2_OFF_X);
    const uint32_t smW_a = smem_u32(smW);

    const int tid = threadIdx.x;
    const int wid = tid >> 5, lane = tid & 31;
    const int gid = lane >> 2, tig = lane & 3;
    const int warp_m = (wid & 7) * 16;
    const int warp_n = (wid >> 3) * 16;
    const int bg = blockIdx.x;
    const int b = bg >> 2, g = bg & 3;
    int start, cnt;
    chunk_range(blockIdx.y, start, cnt);
    const int end = start + cnt;

    const size_t chanbase = ((size_t)b * C_ + (size_t)g * D_) * F_;

    // prefetch first tile O1 planes into buf0
    {
        const uint4* src = (const uint4*)(g_o1 + ((size_t)bg * NTILE + start) * 16384);
        uint32_t bufb = smem_u32(smX0);
        for (int i = tid; i < 2048; i += NT_M) {
            int pl = i >> 9, rem = i & 511, f = rem >> 4, c16 = rem & 15;
            uint32_t dst = bufb + (uint32_t)((pl * PLX32 + f * WP) * 2 + c16 * 16);
            CP_ASYNC16(dst, src + i);
        }
        CP_COMMIT();
    }

    // W2 planes
    {
        const float4* ws = (const float4*)(g_wimg + (size_t)(1 * 4 + g) * 4 * PLW);
        float4* wd = (float4*)smW;
        for (int i = tid; i < 4 * PLW / 8; i += NT_M) wd[i] = ws[i];
    }

    const int r0 = warp_m + gid;
    const float br0  = b2[g * D_ + r0];
    const float br1_ = b2[g * D_ + r0 + 8];
    const float bi0  = b2[(G_ + g) * D_ + r0];
    const float bi1_ = b2[(G_ + g) * D_ + r0 + 8];

    for (int t = start; t < end; t++) {
        unsigned short* buf = smX0 + ((t - start) & 1) * (4 * PLX32);
        CP_WAIT0();
        __syncthreads();

        // prefetch next tile into other buffer (overlaps GEMM)
        if (t + 1 < end) {
            unsigned short* nb = smX0 + (((t - start) + 1) & 1) * (4 * PLX32);
            const uint4* src = (const uint4*)(g_o1 + ((size_t)bg * NTILE + (t + 1)) * 16384);
            uint32_t bufb = smem_u32(nb);
            for (int i = tid; i < 2048; i += NT_M) {
                int pl = i >> 9, rem = i & 511, f = rem >> 4, c16 = rem & 15;
                uint32_t dst = bufb + (uint32_t)((pl * PLX32 + f * WP) * 2 + c16 * 16);
                CP_ASYNC16(dst, src + i);
            }
            CP_COMMIT();
        }

        // prefetch origin spec values into registers (consumed in epilogue)
        float2 oxr[4], oxi[4];
        #pragma unroll
        for (int nt = 0; nt < 2; nt++)
            #pragma unroll
            for (int rp = 0; rp < 2; rp++) {
                int row = r0 + rp * 8;
                int c0  = warp_n + nt * 8 + tig * 2;
                size_t gi = chanbase + (size_t)row * F_ + (size_t)t * 32 + c0;
                int idx = nt * 2 + rp;
                oxr[idx] = *(const float2*)&g_specR[gi];
                oxi[idx] = *(const float2*)&g_specI[gi];
            }

        float aOr[8], aP[8], aOi[8];
        #pragma unroll
        for (int i = 0; i < 8; i++) { aOr[i] = 0.f; aP[i] = 0.f; aOi[i] = 0.f; }
        gemm32(smW_a, smem_u32(buf), aOr, aP, aOi, warp_m, warp_n, lane);

        // epilogue: bias, multiply by origin, store
        #pragma unroll
        for (int nt = 0; nt < 2; nt++) {
            int c0 = warp_n + nt * 8 + tig * 2;
            int ai = nt * 4;
            #pragma unroll
            for (int rp = 0; rp < 2; rp++) {
                int row = r0 + rp * 8;
                float brv = rp ? br1_ : br0;
                float biv = rp ? bi1_ : bi0;
                int idx = nt * 2 + rp;
                float2 xr = oxr[idx], xi = oxi[idx];
                size_t gi = chanbase + (size_t)row * F_ + (size_t)t * 32 + c0;
                float vr0 = aOr[ai + rp * 2]     - aP[ai + rp * 2]     + brv;
                float vi0 = aOi[ai + rp * 2]     + biv;
                float vr1 = aOr[ai + rp * 2 + 1] - aP[ai + rp * 2 + 1] + brv;
                float vi1 = aOi[ai + rp * 2 + 1] + biv;
                float2 orv, oiv;
                orv.x = vr0 * xr.x - vi0 * xi.x;
                oiv.x = vr0 * xi.x + vi0 * xr.x;
                orv.y = vr1 * xr.y - vi1 * xi.y;
                oiv.y = vr1 * xi.y + vi1 * xr.y;
                *(float2*)&g_outR[gi] = orv;
                *(float2*)&g_outI[gi] = oiv;
            }
        }
    }
}

// ---------------------------------------------------------------------------
__global__ void __launch_bounds__(NT_F, 2) kfft_inv(float* __restrict__ y) {
    extern __shared__ float sm[];
    float* R   = sm;
    float* I   = sm + UBUF;
    float* twR = sm + 2 * UBUF;
    float* twI = twR + 64;

    const int tid = threadIdx.x;
    const int img = blockIdx.x;

    if (tid < 64) {
        float s, c;
        sincospif((float)tid / 64.0f, &s, &c);
        twR[tid] = c; twI[tid] = s;
    }

    const float* srcR = g_outR + (size_t)img * F_;
    const float* srcI = g_outI + (size_t)img * F_;
    for (int t = tid; t < F_; t += NT_F) {
        int h = t / WF_, k = t - h * WF_;
        int hb = brev7(h);
        R[hb * CPIT + k] = srcR[t];
        I[hb * CPIT + k] = srcI[t];
    }
    __syncthreads();

    pass8_cols<1>(R, I, twR, twI); __syncthreads();
    pass16_cols  (R, I, twR, twI); __syncthreads();

    float zr[16], zi[16];
    #pragma unroll
    for (int n = 0; n < 16; n++) {
        int it = tid + n * NT_F;
        int w = it & 127, p = it >> 7;
        int r0 = (2 * p) * CPIT, r1 = r0 + CPIT;
        if (w <= 64) {
            float x0r = R[r0 + w], x0i = I[r0 + w];
            float x1r = R[r1 + w], x1i = I[r1 + w];
            if (w == 0 || w == 64) { x0i = 0.f; x1i = 0.f; }
            zr[n] = x0r - x1i;
            zi[n] = x0i + x1r;
        } else {
            int m = 128 - w;
            float x0r = R[r0 + m], x0i = I[r0 + m];
            float x1r = R[r1 + m], x1i = I[r1 + m];
            zr[n] = x0r + x1i;
            zi[n] = x1r - x0i;
        }
    }
    __syncthreads();
    #pragma unroll
    for (int n = 0; n < 16; n++) {
        int it = tid + n * NT_F;
        int w = it & 127, p = it >> 7;
        int wb = brev7(w);
        R[p * RPIT + wb] = zr[n];
        I[p * RPIT + wb] = zi[n];
    }
    __syncthreads();

    pass8_rows<1>(R, I, twR, twI); __syncthreads();
    pass16_rows  (R, I, twR, twI); __syncthreads();

    float* dst = y + (size_t)img * (H_ * W_);
    const float sc = 1.0f / 128.0f;
    for (int t = tid; t < 64 * 128; t += NT_F) {
        int p = t >> 7, c = t & 127;
        dst[(2 * p) * 128 + c]       = R[p * RPIT + c] * sc;
        dst[(2 * p) * 128 + 128 + c] = I[p * RPIT + c] * sc;
    }
}

// ---------------------------------------------------------------------------
extern "C" void kernel_launch(void* const* d_in, const int* in_sizes, int n_in,
                              void* d_out, int out_size) {
    const float* x  = (const float*)d_in[0];
    const float* w1 = (const float*)d_in[1];
    const float* w2 = (const float*)d_in[2];
    const float* b1 = (const float*)d_in[3];
    const float* b2 = (const float*)d_in[4];
    float* y = (float*)d_out;

    const int smFFT = (2 * UBUF + 128) * (int)sizeof(float);   // ~65.5 KB

    cudaFuncSetAttribute(kfft_fwd, cudaFuncAttributeMaxDynamicSharedMemorySize, smFFT);
    cudaFuncSetAttribute(kmixL1,   cudaFuncAttributeMaxDynamicSharedMemorySize, SM_L1);
    cudaFuncSetAttribute(kmixL2,   cudaFuncAttributeMaxDynamicSharedMemorySize, SM_L2);
    cudaFuncSetAttribute(kfft_inv, cudaFuncAttributeMaxDynamicSharedMemorySize, smFFT);

    wprep<<<1024, 256>>>(w1, w2);
    kfft_fwd<<<NIMG, NT_F, smFFT>>>(x);
    kmixL1<<<dim3(32, NCHUNK), NT_M, SM_L1>>>(b1);
    kmixL2<<<dim3(32, NCHUNK), NT_M, SM_L2>>>(b2);
    kfft_inv<<<NIMG, NT_F, smFFT>>>(y);
}

// round 16
// speedup vs baseline: 1.3278x; 1.0422x over previous
#include <cuda_runtime.h>
#include <cuda_bf16.h>
#include <math.h>
#include <stdint.h>

#define B_   8
#define C_   512
#define G_   4
#define D_   128
#define H_   128
#define W_   128
#define WF_  65
#define F_   (H_*WF_)        // 8320
#define NIMG (B_*C_)         // 4096

// Scratch (allocation-free requirement -> device globals).
static __device__ float g_specR[(size_t)NIMG * F_];
static __device__ float g_specI[(size_t)NIMG * F_];
static __device__ float g_outR [(size_t)NIMG * F_];
static __device__ float g_outI [(size_t)NIMG * F_];
static __device__ unsigned short g_wimg[32 * 128 * 136];            // pre-split W planes
static __device__ unsigned short g_o1[(size_t)32 * 260 * 16384];    // O1 planes (~273MB)

#define RPIT 129
#define CPIT 65
#define UBUF 8320
#define NT_F 512

#define WP    136           // bf16 plane pitch (shorts)
#define PLW   (128 * WP)    // W plane elems (17408)
#define PLX32 (32 * WP)     // X plane elems, N=32 tile (4352)
#define NTILE 260           // 8320 / 32
#define NCHUNK 9
#define RPITCH 36           // raw staging pitch (floats)
#define NT_M  512           // mixer threads (16 warps)

__device__ __forceinline__ int brev7(int v) { return (int)(__brev((unsigned)v) >> 25); }

__device__ __forceinline__ void split_bf16(float v, unsigned short& h, unsigned short& l) {
    __nv_bfloat16 hb = __float2bfloat16(v);
    float r = v - __bfloat162float(hb);
    h = __bfloat16_as_ushort(hb);
    l = __bfloat16_as_ushort(__float2bfloat16(r));
}

__device__ __forceinline__ uint32_t smem_u32(const void* p) {
    uint32_t a;
    asm("{ .reg .u64 t; cvta.to.shared.u64 t, %1; cvt.u32.u64 %0, t; }" : "=r"(a) : "l"(p));
    return a;
}
#define CP_ASYNC16(dst, src) \
    asm volatile("cp.async.cg.shared.global [%0], [%1], 16;" :: "r"(dst), "l"(src))
#define CP_COMMIT() asm volatile("cp.async.commit_group;" ::: "memory")
#define CP_WAIT0()  asm volatile("cp.async.wait_group 0;"  ::: "memory")

#define LDSM_X4(r, addr) \
    asm volatile("ldmatrix.sync.aligned.m8n8.x4.shared.b16 {%0,%1,%2,%3}, [%4];" \
        : "=r"((r)[0]), "=r"((r)[1]), "=r"((r)[2]), "=r"((r)[3]) : "r"(addr))

// ---------------------------------------------------------------------------
// Weight prep
// ---------------------------------------------------------------------------
__global__ void __launch_bounds__(256) wprep(const float* __restrict__ w1,
                                             const float* __restrict__ w2) {
    int idx = blockIdx.x * 256 + threadIdx.x;      // 262144
    int m    = idx & 127;
    int k    = (idx >> 7) & 127;
    int part = (idx >> 14) & 1;
    int g    = (idx >> 15) & 3;
    int l    = (idx >> 17) & 1;
    const float* src = l ? w2 : w1;
    float v = src[(((size_t)(part * 4 + g) * 128 + k) * 128) + m];
    unsigned short h, lo;
    split_bf16(v, h, lo);
    size_t base = (size_t)((l * 4 + g) * 4 + part * 2) * PLW;
    g_wimg[base + m * WP + k]       = h;
    g_wimg[base + PLW + m * WP + k] = lo;
}

// ============================ FFT passes ====================================
// Radix-8: three fused radix-2 stages S, S+1, S+2 (DIT, bit-reversed input).
template<int S>
__device__ __forceinline__ void pass8_rows(float* R, float* I,
                                           const float* twR, const float* twI) {
    const int h = 1 << (S - 1);
    for (int it = threadIdx.x; it < 64 * 16; it += NT_F) {
        int r = it & 63, q = it >> 6;
        int j = q & (h - 1);
        int base = (q >> (S - 1)) << (S + 2);
        int i0 = r * RPIT + base + j;
        float er[8], ei[8];
        #pragma unroll
        for (int k = 0; k < 8; k++) { er[k] = R[i0 + k * h]; ei[k] = I[i0 + k * h]; }
        {
            float wr = twR[j << (7 - S)], wi = twI[j << (7 - S)];
            #pragma unroll
            for (int k = 0; k < 8; k += 2) {
                float tr = er[k+1] * wr - ei[k+1] * wi;
                float ti = er[k+1] * wi + ei[k+1] * wr;
                er[k+1] = er[k] - tr; ei[k+1] = ei[k] - ti;
                er[k]  += tr;         ei[k]  += ti;
            }
        }
        {
            float w2r = twR[j << (6 - S)],       w2i = twI[j << (6 - S)];
            float w3r = twR[(j + h) << (6 - S)], w3i = twI[(j + h) << (6 - S)];
            #pragma unroll
            for (int gq = 0; gq < 8; gq += 4) {
                float tr = er[gq+2] * w2r - ei[gq+2] * w2i;
                float ti = er[gq+2] * w2i + ei[gq+2] * w2r;
                er[gq+2] = er[gq] - tr; ei[gq+2] = ei[gq] - ti;
                er[gq]  += tr;          ei[gq]  += ti;
                tr = er[gq+3] * w3r - ei[gq+3] * w3i;
                ti = er[gq+3] * w3i + ei[gq+3] * w3r;
                er[gq+3] = er[gq+1] - tr; ei[gq+3] = ei[gq+1] - ti;
                er[gq+1] += tr;           ei[gq+1] += ti;
            }
        }
        #pragma unroll
        for (int k = 0; k < 4; k++) {
            float wr = twR[(j + k * h) << (5 - S)], wi = twI[(j + k * h) << (5 - S)];
            float tr = er[k+4] * wr - ei[k+4] * wi;
            float ti = er[k+4] * wi + ei[k+4] * wr;
            er[k+4] = er[k] - tr; ei[k+4] = ei[k] - ti;
            er[k]  += tr;         ei[k]  += ti;
        }
        #pragma unroll
        for (int k = 0; k < 8; k++) { R[i0 + k * h] = er[k]; I[i0 + k * h] = ei[k]; }
    }
}

template<int S>
__device__ __forceinline__ void pass8_cols(float* R, float* I,
                                           const float* twR, const float* twI) {
    const int h = 1 << (S - 1);
    const int st = h * CPIT;
    for (int it = threadIdx.x; it < 65 * 16; it += NT_F) {
        int c = it % 65, q = it / 65;
        int j = q & (h - 1);
        int base = (q >> (S - 1)) << (S + 2);
        int i0 = (base + j) * CPIT + c;
        float er[8], ei[8];
        #pragma unroll
        for (int k = 0; k < 8; k++) { er[k] = R[i0 + k * st]; ei[k] = I[i0 + k * st]; }
        {
            float wr = twR[j << (7 - S)], wi = twI[j << (7 - S)];
            #pragma unroll
            for (int k = 0; k < 8; k += 2) {
                float tr = er[k+1] * wr - ei[k+1] * wi;
                float ti = er[k+1] * wi + ei[k+1] * wr;
                er[k+1] = er[k] - tr; ei[k+1] = ei[k] - ti;
                er[k]  += tr;         ei[k]  += ti;
            }
        }
        {
            float w2r = twR[j << (6 - S)],       w2i = twI[j << (6 - S)];
            float w3r = twR[(j + h) << (6 - S)], w3i = twI[(j + h) << (6 - S)];
            #pragma unroll
            for (int gq = 0; gq < 8; gq += 4) {
                float tr = er[gq+2] * w2r - ei[gq+2] * w2i;
                float ti = er[gq+2] * w2i + ei[gq+2] * w2r;
                er[gq+2] = er[gq] - tr; ei[gq+2] = ei[gq] - ti;
                er[gq]  += tr;          ei[gq]  += ti;
                tr = er[gq+3] * w3r - ei[gq+3] * w3i;
                ti = er[gq+3] * w3i + ei[gq+3] * w3r;
                er[gq+3] = er[gq+1] - tr; ei[gq+3] = ei[gq+1] - ti;
                er[gq+1] += tr;           ei[gq+1] += ti;
            }
        }
        #pragma unroll
        for (int k = 0; k < 4; k++) {
            float wr = twR[(j + k * h) << (5 - S)], wi = twI[(j + k * h) << (5 - S)];
            float tr = er[k+4] * wr - ei[k+4] * wi;
            float ti = er[k+4] * wi + ei[k+4] * wr;
            er[k+4] = er[k] - tr; ei[k+4] = ei[k] - ti;
            er[k]  += tr;         ei[k]  += ti;
        }
        #pragma unroll
        for (int k = 0; k < 8; k++) { R[i0 + k * st] = er[k]; I[i0 + k * st] = ei[k]; }
    }
}

// Radix-16: fused radix-2 stages 4,5,6,7 (h=8..64). Each thread: 16 elems j+8k.
__device__ __forceinline__ void pass16_rows(float* R, float* I,
                                            const float* twR, const float* twI) {
    for (int it = threadIdx.x; it < 512; it += NT_F) {
        int r = it & 63, j = it >> 6;
        int i0 = r * RPIT + j;
        float er[16], ei[16];
        #pragma unroll
        for (int k = 0; k < 16; k++) { er[k] = R[i0 + 8 * k]; ei[k] = I[i0 + 8 * k]; }
        {
            float wr = twR[j << 3], wi = twI[j << 3];
            #pragma unroll
            for (int k = 0; k < 16; k += 2) {
                float tr = er[k+1] * wr - ei[k+1] * wi;
                float ti = er[k+1] * wi + ei[k+1] * wr;
                er[k+1] = er[k] - tr; ei[k+1] = ei[k] - ti;
                er[k]  += tr;         ei[k]  += ti;
            }
        }
        {
            float w0r = twR[j << 2],       w0i = twI[j << 2];
            float w1r = twR[(j + 8) << 2], w1i = twI[(j + 8) << 2];
            #pragma unroll
            for (int b = 0; b < 16; b += 4) {
                float tr = er[b+2] * w0r - ei[b+2] * w0i;
                float ti = er[b+2] * w0i + ei[b+2] * w0r;
                er[b+2] = er[b] - tr; ei[b+2] = ei[b] - ti;
                er[b]  += tr;         ei[b]  += ti;
                tr = er[b+3] * w1r - ei[b+3] * w1i;
                ti = er[b+3] * w1i + ei[b+3] * w1r;
                er[b+3] = er[b+1] - tr; ei[b+3] = ei[b+1] - ti;
                er[b+1] += tr;          ei[b+1] += ti;
            }
        }
        #pragma unroll
        for (int b = 0; b < 16; b += 8) {
            #pragma unroll
            for (int m = 0; m < 4; m++) {
                float wr = twR[(j + 8 * m) << 1], wi = twI[(j + 8 * m) << 1];
                float tr = er[b+m+4] * wr - ei[b+m+4] * wi;
                float ti = er[b+m+4] * wi + ei[b+m+4] * wr;
                er[b+m+4] = er[b+m] - tr; ei[b+m+4] = ei[b+m] - ti;
                er[b+m]  += tr;           ei[b+m]  += ti;
            }
        }
        #pragma unroll
        for (int m = 0; m < 8; m++) {
            float wr = twR[j + 8 * m], wi = twI[j + 8 * m];
            float tr = er[m+8] * wr - ei[m+8] * wi;
            float ti = er[m+8] * wi + ei[m+8] * wr;
            er[m+8] = er[m] - tr; ei[m+8] = ei[m] - ti;
            er[m]  += tr;         ei[m]  += ti;
        }
        #pragma unroll
        for (int k = 0; k < 16; k++) { R[i0 + 8 * k] = er[k]; I[i0 + 8 * k] = ei[k]; }
    }
}

__device__ __forceinline__ void pass16_cols(float* R, float* I,
                                            const float* twR, const float* twI) {
    for (int it = threadIdx.x; it < 65 * 8; it += NT_F) {
        int c = it % 65, j = it / 65;
        int i0 = j * CPIT + c;
        float er[16], ei[16];
        #pragma unroll
        for (int k = 0; k < 16; k++) { er[k] = R[i0 + 8 * k * CPIT]; ei[k] = I[i0 + 8 * k * CPIT]; }
        {
            float wr = twR[j << 3], wi = twI[j << 3];
            #pragma unroll
            for (int k = 0; k < 16; k += 2) {
                float tr = er[k+1] * wr - ei[k+1] * wi;
                float ti = er[k+1] * wi + ei[k+1] * wr;
                er[k+1] = er[k] - tr; ei[k+1] = ei[k] - ti;
                er[k]  += tr;         ei[k]  += ti;
            }
        }
        {
            float w0r = twR[j << 2],       w0i = twI[j << 2];
            float w1r = twR[(j + 8) << 2], w1i = twI[(j + 8) << 2];
            #pragma unroll
            for (int b = 0; b < 16; b += 4) {
                float tr = er[b+2] * w0r - ei[b+2] * w0i;
                float ti = er[b+2] * w0i + ei[b+2] * w0r;
                er[b+2] = er[b] - tr; ei[b+2] = ei[b] - ti;
                er[b]  += tr;         ei[b]  += ti;
                tr = er[b+3] * w1r - ei[b+3] * w1i;
                ti = er[b+3] * w1i + ei[b+3] * w1r;
                er[b+3] = er[b+1] - tr; ei[b+3] = ei[b+1] - ti;
                er[b+1] += tr;          ei[b+1] += ti;
            }
        }
        #pragma unroll
        for (int b = 0; b < 16; b += 8) {
            #pragma unroll
            for (int m = 0; m < 4; m++) {
                float wr = twR[(j + 8 * m) << 1], wi = twI[(j + 8 * m) << 1];
                float tr = er[b+m+4] * wr - ei[b+m+4] * wi;
                float ti = er[b+m+4] * wi + ei[b+m+4] * wr;
                er[b+m+4] = er[b+m] - tr; ei[b+m+4] = ei[b+m] - ti;
                er[b+m]  += tr;           ei[b+m]  += ti;
            }
        }
        #pragma unroll
        for (int m = 0; m < 8; m++) {
            float wr = twR[j + 8 * m], wi = twI[j + 8 * m];
            float tr = er[m+8] * wr - ei[m+8] * wi;
            float ti = er[m+8] * wi + ei[m+8] * wr;
            er[m+8] = er[m] - tr; ei[m+8] = ei[m] - ti;
            er[m]  += tr;         ei[m]  += ti;
        }
        #pragma unroll
        for (int k = 0; k < 16; k++) { R[i0 + 8 * k * CPIT] = er[k]; I[i0 + 8 * k * CPIT] = ei[k]; }
    }
}

__global__ void __launch_bounds__(NT_F, 3) kfft_fwd(const float* __restrict__ x) {
    extern __shared__ float sm[];
    float* R   = sm;
    float* I   = sm + UBUF;
    float* twR = sm + 2 * UBUF;
    float* twI = twR + 64;

    const int tid = threadIdx.x;
    const int img = blockIdx.x;

    if (tid < 64) {
        float s, c;
        sincospif(-(float)tid / 64.0f, &s, &c);
        twR[tid] = c; twI[tid] = s;
    }

    const float* src = x + (size_t)img * (H_ * W_);
    for (int t = tid; t < 64 * 128; t += NT_F) {
        int p = t >> 7, c = t & 127;
        int cb = brev7(c);
        R[p * RPIT + cb] = src[(2 * p) * 128 + c];
        I[p * RPIT + cb] = src[(2 * p) * 128 + 128 + c];
    }
    __syncthreads();

    pass8_rows<1>(R, I, twR, twI); __syncthreads();
    pass16_rows  (R, I, twR, twI); __syncthreads();

    float u0r[9], u0i[9], u1r[9], u1i[9];
    #pragma unroll
    for (int n = 0; n < 9; n++) {
        int it = tid + n * NT_F;
        if (it < 64 * 65) {
            int k = it % 65, p = it / 65;
            int m = (128 - k) & 127;
            float a = R[p * RPIT + k], b = I[p * RPIT + k];
            float c2 = R[p * RPIT + m], d = I[p * RPIT + m];
            u0r[n] = 0.5f * (a + c2); u0i[n] = 0.5f * (b - d);
            u1r[n] = 0.5f * (b + d);  u1i[n] = 0.5f * (c2 - a);
        }
    }
    __syncthreads();
    #pragma unroll
    for (int n = 0; n < 9; n++) {
        int it = tid + n * NT_F;
        if (it < 64 * 65) {
            int k = it % 65, p = it / 65;
            int h0 = brev7(2 * p), h1 = brev7(2 * p + 1);
            R[h0 * CPIT + k] = u0r[n]; I[h0 * CPIT + k] = u0i[n];
            R[h1 * CPIT + k] = u1r[n]; I[h1 * CPIT + k] = u1i[n];
        }
    }
    __syncthreads();

    pass8_cols<1>(R, I, twR, twI); __syncthreads();
    pass16_cols  (R, I, twR, twI); __syncthreads();

    float* dR = g_specR + (size_t)img * F_;
    float* dI = g_specI + (size_t)img * F_;
    const float sc = 1.0f / 128.0f;
    for (int t = tid; t < F_; t += NT_F) {
        dR[t] = R[t] * sc;
        dI[t] = I[t] * sc;
    }
}

// ---------------------------------------------------------------------------
// Tensor-core mixer: 512 threads / 16 warps, warp tile m16 x n16, LDSM loads,
// software-pipelined k-loop + nt-interleaved MMA chains.
// ---------------------------------------------------------------------------
__device__ __forceinline__ void mma16816(float* d, const uint32_t* a, const uint32_t* b) {
    asm volatile("mma.sync.aligned.m16n8k16.row.col.f32.bf16.bf16.f32 "
        "{%0,%1,%2,%3}, {%4,%5,%6,%7}, {%8,%9}, {%0,%1,%2,%3};"
        : "+f"(d[0]), "+f"(d[1]), "+f"(d[2]), "+f"(d[3])
        : "r"(a[0]), "r"(a[1]), "r"(a[2]), "r"(a[3]), "r"(b[0]), "r"(b[1]));
}

__device__ __forceinline__ void ld_frags(uint32_t smW_a, uint32_t smX_a,
                                         uint32_t aOff, uint32_t bOff, uint32_t k0b,
                                         uint32_t A[4][4], uint32_t Bf[4][4]) {
    #pragma unroll
    for (int pl = 0; pl < 4; pl++)
        LDSM_X4(A[pl], smW_a + (uint32_t)pl * (PLW * 2) + aOff + k0b);
    #pragma unroll
    for (int pl = 0; pl < 4; pl++)
        LDSM_X4(Bf[pl], smX_a + (uint32_t)pl * (PLX32 * 2) + bOff + k0b);
}

// nt0/nt1 interleaved: two independent accumulator chains in flight.
__device__ __forceinline__ void mma_block(const uint32_t A[4][4], const uint32_t Bf[4][4],
                                          float* aOr, float* aP, float* aOi) {
    #define MOP(dst, Aidx, Bpl) \
        mma16816((dst),     A[Aidx], &Bf[Bpl][0]); \
        mma16816((dst) + 4, A[Aidx], &Bf[Bpl][2]);
    MOP(aOr, 0, 0)   // WrH*XrH
    MOP(aOr, 1, 0)   // WrL*XrH
    MOP(aOr, 0, 1)   // WrH*XrL
    MOP(aP,  2, 2)   // WiH*XiH
    MOP(aP,  3, 2)   // WiL*XiH
    MOP(aP,  2, 3)   // WiH*XiL
    MOP(aOi, 2, 0)   // WiH*XrH
    MOP(aOi, 3, 0)   // WiL*XrH
    MOP(aOi, 2, 1)   // WiH*XrL
    MOP(aOi, 0, 2)   // WrH*XiH
    MOP(aOi, 1, 2)   // WrL*XiH
    MOP(aOi, 0, 3)   // WrH*XiL
    #undef MOP
}

// warp tile m16 (warp_m = (wid&7)*16) x n16 (warp_n = (wid>>3)*16, 2 x n8)
__device__ __forceinline__ void gemm32(uint32_t smW_a, uint32_t smX_a,
                                       float* aOr, float* aP, float* aOi,
                                       int warp_m, int warp_n, int lane) {
    const uint32_t aOff = (uint32_t)((warp_m + (lane & 15)) * WP + ((lane >> 4) << 3)) * 2;
    const uint32_t bOff = (uint32_t)((warp_n + ((lane >> 4) << 3) + (lane & 7)) * WP
                                     + (((lane >> 3) & 1) << 3)) * 2;
    uint32_t A[2][4][4], Bf[2][4][4];
    ld_frags(smW_a, smX_a, aOff, bOff, 0, A[0], Bf[0]);
    #pragma unroll
    for (int kk = 0; kk < 8; kk++) {
        const int cur = kk & 1, nxt = cur ^ 1;
        if (kk < 7)
            ld_frags(smW_a, smX_a, aOff, bOff, (uint32_t)(kk + 1) * 32, A[nxt], Bf[nxt]);
        mma_block(A[cur], Bf[cur], aOr, aP, aOi);
    }
}

__device__ __forceinline__ void chunk_range(int c, int& start, int& cnt) {
    start = c * 29;
    cnt   = (c == 8) ? 28 : 29;
}

// L1 smem: W planes | X planes | raw staging
#define L1_OFF_X   (4 * PLW * 2)                     // 139264
#define L1_OFF_RAW (L1_OFF_X + 4 * PLX32 * 2)        // 174080
#define SM_L1      (L1_OFF_RAW + 2 * 128 * RPITCH * 4)  // 210944
// L2 smem: W planes | 2x X plane buffers
#define L2_OFF_X   (4 * PLW * 2)
#define SM_L2      (L2_OFF_X + 2 * 4 * PLX32 * 2)       // 208896

// ================= Layer 1 kernel =================
__global__ void __launch_bounds__(NT_M, 1)
kmixL1(const float* __restrict__ b1) {
    extern __shared__ char smem[];
    unsigned short* smW = (unsigned short*)smem;
    unsigned short* smX = (unsigned short*)(smem + L1_OFF_X);
    float*          raw = (float*)(smem + L1_OFF_RAW);
    const uint32_t raw_u32 = smem_u32(raw);
    const uint32_t smW_a = smem_u32(smW);
    const uint32_t smX_a = smem_u32(smX);

    const int tid = threadIdx.x;
    const int wid = tid >> 5, lane = tid & 31;
    const int gid = lane >> 2, tig = lane & 3;
    const int warp_m = (wid & 7) * 16;
    const int warp_n = (wid >> 3) * 16;
    const int bg = blockIdx.x;
    const int b = bg >> 2, g = bg & 3;
    int start, cnt;
    chunk_range(blockIdx.y, start, cnt);
    const int end = start + cnt;

    const size_t chanbase = ((size_t)b * C_ + (size_t)g * D_) * F_;

    // prefetch first tile raw spec (async)
    {
        for (int i = tid; i < 2048; i += NT_M) {
            int pl = i >> 10, rem = i & 1023, c = rem >> 3, seg = rem & 7;
            const float* src = (pl ? g_specI : g_specR) + chanbase + (size_t)c * F_
                             + (size_t)start * 32 + seg * 4;
            uint32_t dst = raw_u32 + (uint32_t)(pl * (128 * RPITCH * 4) + c * (RPITCH * 4) + seg * 16);
            CP_ASYNC16(dst, src);
        }
        CP_COMMIT();
    }

    // W1 planes: once per CTA
    {
        const float4* ws = (const float4*)(g_wimg + (size_t)(0 * 4 + g) * 4 * PLW);
        float4* wd = (float4*)smW;
        for (int i = tid; i < 4 * PLW / 8; i += NT_M) wd[i] = ws[i];
    }

    // bias values (fixed rows per warp)
    const int r0 = warp_m + gid;
    const float br0  = b1[g * D_ + r0];
    const float br1_ = b1[g * D_ + r0 + 8];
    const float bi0  = b1[(G_ + g) * D_ + r0];
    const float bi1_ = b1[(G_ + g) * D_ + r0 + 8];

    for (int t = start; t < end; t++) {
        CP_WAIT0();
        __syncthreads();

        // convert raw -> X planes (split); 4096 elems / 512 threads
        #pragma unroll
        for (int n = 0; n < 8; n++) {
            int it = tid + n * NT_M;
            int c = it >> 5, f = it & 31;
            float vr = raw[c * RPITCH + f];
            float vi = raw[128 * RPITCH + c * RPITCH + f];
            unsigned short rh, rl, ih, il;
            split_bf16(vr, rh, rl);
            split_bf16(vi, ih, il);
            int o = f * WP + c;
            smX[o] = rh; smX[PLX32 + o] = rl;
            smX[2 * PLX32 + o] = ih; smX[3 * PLX32 + o] = il;
        }
        __syncthreads();

        // prefetch next tile raw (overlaps GEMM)
        if (t + 1 < end) {
            for (int i = tid; i < 2048; i += NT_M) {
                int pl = i >> 10, rem = i & 1023, c = rem >> 3, seg = rem & 7;
                const float* src = (pl ? g_specI : g_specR) + chanbase + (size_t)c * F_
                                 + (size_t)(t + 1) * 32 + seg * 4;
                uint32_t dst = raw_u32 + (uint32_t)(pl * (128 * RPITCH * 4) + c * (RPITCH * 4) + seg * 16);
                CP_ASYNC16(dst, src);
            }
            CP_COMMIT();
        }

        float aOr[8], aP[8], aOi[8];
        #pragma unroll
        for (int i = 0; i < 8; i++) { aOr[i] = 0.f; aP[i] = 0.f; aOi[i] = 0.f; }
        gemm32(smW_a, smX_a, aOr, aP, aOi, warp_m, warp_n, lane);
        __syncthreads();

        // epilogue: bias + relu, split, write O1 planes back into smX
        #pragma unroll
        for (int nt = 0; nt < 2; nt++) {
            int c0 = warp_n + nt * 8 + tig * 2;
            int ai = nt * 4;
            #pragma unroll
            for (int e = 0; e < 4; e++) {
                int row = (e >= 2) ? r0 + 8 : r0;
                int col = c0 + (e & 1);
                float brv = (e >= 2) ? br1_ : br0;
                float biv = (e >= 2) ? bi1_ : bi0;
                float vr = aOr[ai + e] - aP[ai + e] + brv; vr = vr > 0.f ? vr : 0.f;
                float vi = aOi[ai + e] + biv;              vi = vi > 0.f ? vi : 0.f;
                unsigned short rh, rl, ih, il;
                split_bf16(vr, rh, rl);
                split_bf16(vi, ih, il);
                int o = col * WP + row;
                smX[o] = rh; smX[PLX32 + o] = rl;
                smX[2 * PLX32 + o] = ih; smX[3 * PLX32 + o] = il;
            }
        }
        __syncthreads();

        // coalesced copy-out smX planes -> g_o1: 4 planes x 32 f x 16 uint4
        {
            uint4* dst = (uint4*)(g_o1 + ((size_t)bg * NTILE + t) * 16384);
            for (int i = tid; i < 2048; i += NT_M) {
                int pl = i >> 9, rem = i & 511, f = rem >> 4, c16 = rem & 15;
                dst[i] = *(const uint4*)(smX + pl * PLX32 + f * WP + c16 * 8);
            }
        }
    }
}

// ================= Layer 2 kernel =================
__global__ void __launch_bounds__(NT_M, 1)
kmixL2(const float* __restrict__ b2) {
    extern __shared__ char smem[];
    unsigned short* smW  = (unsigned short*)smem;
    unsigned short* smX0 = (unsigned short*)(smem + L2_OFF_X);
    const uint32_t smW_a = smem_u32(smW);

    const int tid = threadIdx.x;
    const int wid = tid >> 5, lane = tid & 31;
    const int gid = lane >> 2, tig = lane & 3;
    const int warp_m = (wid & 7) * 16;
    const int warp_n = (wid >> 3) * 16;
    const int bg = blockIdx.x;
    const int b = bg >> 2, g = bg & 3;
    int start, cnt;
    chunk_range(blockIdx.y, start, cnt);
    const int end = start + cnt;

    const size_t chanbase = ((size_t)b * C_ + (size_t)g * D_) * F_;

    // prefetch first tile O1 planes into buf0
    {
        const uint4* src = (const uint4*)(g_o1 + ((size_t)bg * NTILE + start) * 16384);
        uint32_t bufb = smem_u32(smX0);
        for (int i = tid; i < 2048; i += NT_M) {
            int pl = i >> 9, rem = i & 511, f = rem >> 4, c16 = rem & 15;
            uint32_t dst = bufb + (uint32_t)((pl * PLX32 + f * WP) * 2 + c16 * 16);
            CP_ASYNC16(dst, src + i);
        }
        CP_COMMIT();
    }

    // W2 planes
    {
        const float4* ws = (const float4*)(g_wimg + (size_t)(1 * 4 + g) * 4 * PLW);
        float4* wd = (float4*)smW;
        for (int i = tid; i < 4 * PLW / 8; i += NT_M) wd[i] = ws[i];
    }

    const int r0 = warp_m + gid;
    const float br0  = b2[g * D_ + r0];
    const float br1_ = b2[g * D_ + r0 + 8];
    const float bi0  = b2[(G_ + g) * D_ + r0];
    const float bi1_ = b2[(G_ + g) * D_ + r0 + 8];

    for (int t = start; t < end; t++) {
        unsigned short* buf = smX0 + ((t - start) & 1) * (4 * PLX32);
        CP_WAIT0();
        __syncthreads();

        // prefetch next tile into other buffer (overlaps GEMM)
        if (t + 1 < end) {
            unsigned short* nb = smX0 + (((t - start) + 1) & 1) * (4 * PLX32);
            const uint4* src = (const uint4*)(g_o1 + ((size_t)bg * NTILE + (t + 1)) * 16384);
            uint32_t bufb = smem_u32(nb);
            for (int i = tid; i < 2048; i += NT_M) {
                int pl = i >> 9, rem = i & 511, f = rem >> 4, c16 = rem & 15;
                uint32_t dst = bufb + (uint32_t)((pl * PLX32 + f * WP) * 2 + c16 * 16);
                CP_ASYNC16(dst, src + i);
            }
            CP_COMMIT();
        }

        // prefetch origin spec values into registers (consumed in epilogue)
        float2 oxr[4], oxi[4];
        #pragma unroll
        for (int nt = 0; nt < 2; nt++)
            #pragma unroll
            for (int rp = 0; rp < 2; rp++) {
                int row = r0 + rp * 8;
                int c0  = warp_n + nt * 8 + tig * 2;
                size_t gi = chanbase + (size_t)row * F_ + (size_t)t * 32 + c0;
                int idx = nt * 2 + rp;
                oxr[idx] = *(const float2*)&g_specR[gi];
                oxi[idx] = *(const float2*)&g_specI[gi];
            }

        float aOr[8], aP[8], aOi[8];
        #pragma unroll
        for (int i = 0; i < 8; i++) { aOr[i] = 0.f; aP[i] = 0.f; aOi[i] = 0.f; }
        gemm32(smW_a, smem_u32(buf), aOr, aP, aOi, warp_m, warp_n, lane);

        // epilogue: bias, multiply by origin, store
        #pragma unroll
        for (int nt = 0; nt < 2; nt++) {
            int c0 = warp_n + nt * 8 + tig * 2;
            int ai = nt * 4;
            #pragma unroll
            for (int rp = 0; rp < 2; rp++) {
                int row = r0 + rp * 8;
                float brv = rp ? br1_ : br0;
                float biv = rp ? bi1_ : bi0;
                int idx = nt * 2 + rp;
                float2 xr = oxr[idx], xi = oxi[idx];
                size_t gi = chanbase + (size_t)row * F_ + (size_t)t * 32 + c0;
                float vr0 = aOr[ai + rp * 2]     - aP[ai + rp * 2]     + brv;
                float vi0 = aOi[ai + rp * 2]     + biv;
                float vr1 = aOr[ai + rp * 2 + 1] - aP[ai + rp * 2 + 1] + brv;
                float vi1 = aOi[ai + rp * 2 + 1] + biv;
                float2 orv, oiv;
                orv.x = vr0 * xr.x - vi0 * xi.x;
                oiv.x = vr0 * xi.x + vi0 * xr.x;
                orv.y = vr1 * xr.y - vi1 * xi.y;
                oiv.y = vr1 * xi.y + vi1 * xr.y;
                *(float2*)&g_outR[gi] = orv;
                *(float2*)&g_outI[gi] = oiv;
            }
        }
    }
}

// ---------------------------------------------------------------------------
__global__ void __launch_bounds__(NT_F, 3) kfft_inv(float* __restrict__ y) {
    extern __shared__ float sm[];
    float* R   = sm;
    float* I   = sm + UBUF;
    float* twR = sm + 2 * UBUF;
    float* twI = twR + 64;

    const int tid = threadIdx.x;
    const int img = blockIdx.x;

    if (tid < 64) {
        float s, c;
        sincospif((float)tid / 64.0f, &s, &c);
        twR[tid] = c; twI[tid] = s;
    }

    const float* srcR = g_outR + (size_t)img * F_;
    const float* srcI = g_outI + (size_t)img * F_;
    for (int t = tid; t < F_; t += NT_F) {
        int h = t / WF_, k = t - h * WF_;
        int hb = brev7(h);
        R[hb * CPIT + k] = srcR[t];
        I[hb * CPIT + k] = srcI[t];
    }
    __syncthreads();

    pass8_cols<1>(R, I, twR, twI); __syncthreads();
    pass16_cols  (R, I, twR, twI); __syncthreads();

    float zr[16], zi[16];
    #pragma unroll
    for (int n = 0; n < 16; n++) {
        int it = tid + n * NT_F;
        int w = it & 127, p = it >> 7;
        int r0 = (2 * p) * CPIT, r1 = r0 + CPIT;
        if (w <= 64) {
            float x0r = R[r0 + w], x0i = I[r0 + w];
            float x1r = R[r1 + w], x1i = I[r1 + w];
            if (w == 0 || w == 64) { x0i = 0.f; x1i = 0.f; }
            zr[n] = x0r - x1i;
            zi[n] = x0i + x1r;
        } else {
            int m = 128 - w;
            float x0r = R[r0 + m], x0i = I[r0 + m];
            float x1r = R[r1 + m], x1i = I[r1 + m];
            zr[n] = x0r + x1i;
            zi[n] = x1r - x0i;
        }
    }
    __syncthreads();
    #pragma unroll
    for (int n = 0; n < 16; n++) {
        int it = tid + n * NT_F;
        int w = it & 127, p = it >> 7;
        int wb = brev7(w);
        R[p * RPIT + wb] = zr[n];
        I[p * RPIT + wb] = zi[n];
    }
    __syncthreads();

    pass8_rows<1>(R, I, twR, twI); __syncthreads();
    pass16_rows  (R, I, twR, twI); __syncthreads();

    float* dst = y + (size_t)img * (H_ * W_);
    const float sc = 1.0f / 128.0f;
    for (int t = tid; t < 64 * 128; t += NT_F) {
        int p = t >> 7, c = t & 127;
        dst[(2 * p) * 128 + c]       = R[p * RPIT + c] * sc;
        dst[(2 * p) * 128 + 128 + c] = I[p * RPIT + c] * sc;
    }
}

// ---------------------------------------------------------------------------
extern "C" void kernel_launch(void* const* d_in, const int* in_sizes, int n_in,
                              void* d_out, int out_size) {
    const float* x  = (const float*)d_in[0];
    const float* w1 = (const float*)d_in[1];
    const float* w2 = (const float*)d_in[2];
    const float* b1 = (const float*)d_in[3];
    const float* b2 = (const float*)d_in[4];
    float* y = (float*)d_out;

    const int smFFT = (2 * UBUF + 128) * (int)sizeof(float);   // ~65.5 KB

    cudaFuncSetAttribute(kfft_fwd, cudaFuncAttributeMaxDynamicSharedMemorySize, smFFT);
    cudaFuncSetAttribute(kmixL1,   cudaFuncAttributeMaxDynamicSharedMemorySize, SM_L1);
    cudaFuncSetAttribute(kmixL2,   cudaFuncAttributeMaxDynamicSharedMemorySize, SM_L2);
    cudaFuncSetAttribute(kfft_inv, cudaFuncAttributeMaxDynamicSharedMemorySize, smFFT);

    wprep<<<1024, 256>>>(w1, w2);
    kfft_fwd<<<NIMG, NT_F, smFFT>>>(x);
    kmixL1<<<dim3(32, NCHUNK), NT_M, SM_L1>>>(b1);
    kmixL2<<<dim3(32, NCHUNK), NT_M, SM_L2>>>(b2);
    kfft_inv<<<NIMG, NT_F, smFFT>>>(y);
}

// round 17
// speedup vs baseline: 1.3548x; 1.0203x over previous
#include <cuda_runtime.h>
#include <cuda_bf16.h>
#include <math.h>
#include <stdint.h>

#define B_   8
#define C_   512
#define G_   4
#define D_   128
#define H_   128
#define W_   128
#define WF_  65
#define F_   (H_*WF_)        // 8320
#define NIMG (B_*C_)         // 4096

// Scratch (allocation-free requirement -> device globals).
static __device__ float g_specR[(size_t)NIMG * F_];
static __device__ float g_specI[(size_t)NIMG * F_];
static __device__ float g_outR [(size_t)NIMG * F_];
static __device__ float g_outI [(size_t)NIMG * F_];
static __device__ unsigned short g_wimg[32 * 128 * 136];            // pre-split W planes
static __device__ unsigned short g_o1[(size_t)32 * 260 * 16384];    // O1 planes (~273MB)

#define RPIT 129
#define CPIT 65
#define UBUF 8320
#define NT_F 512

#define WP    136           // bf16 plane pitch (shorts)
#define PLW   (128 * WP)    // W plane elems (17408)
#define PLX32 (32 * WP)     // X plane elems, N=32 tile (4352)
#define NTILE 260           // 8320 / 32
#define NCHUNK 9
#define RPITCH 36           // raw staging pitch (floats)
#define NT_M  512           // mixer threads (16 warps)

__device__ __forceinline__ int brev7(int v) { return (int)(__brev((unsigned)v) >> 25); }

__device__ __forceinline__ void split_bf16(float v, unsigned short& h, unsigned short& l) {
    __nv_bfloat16 hb = __float2bfloat16(v);
    float r = v - __bfloat162float(hb);
    h = __bfloat16_as_ushort(hb);
    l = __bfloat16_as_ushort(__float2bfloat16(r));
}

__device__ __forceinline__ uint32_t smem_u32(const void* p) {
    uint32_t a;
    asm("{ .reg .u64 t; cvta.to.shared.u64 t, %1; cvt.u32.u64 %0, t; }" : "=r"(a) : "l"(p));
    return a;
}
#define CP_ASYNC16(dst, src) \
    asm volatile("cp.async.cg.shared.global [%0], [%1], 16;" :: "r"(dst), "l"(src))
#define CP_COMMIT() asm volatile("cp.async.commit_group;" ::: "memory")
#define CP_WAIT0()  asm volatile("cp.async.wait_group 0;"  ::: "memory")

#define LDSM_X4(r, addr) \
    asm volatile("ldmatrix.sync.aligned.m8n8.x4.shared.b16 {%0,%1,%2,%3}, [%4];" \
        : "=r"((r)[0]), "=r"((r)[1]), "=r"((r)[2]), "=r"((r)[3]) : "r"(addr))

// ---------------------------------------------------------------------------
// Weight prep
// ---------------------------------------------------------------------------
__global__ void __launch_bounds__(256) wprep(const float* __restrict__ w1,
                                             const float* __restrict__ w2) {
    int idx = blockIdx.x * 256 + threadIdx.x;      // 262144
    int m    = idx & 127;
    int k    = (idx >> 7) & 127;
    int part = (idx >> 14) & 1;
    int g    = (idx >> 15) & 3;
    int l    = (idx >> 17) & 1;
    const float* src = l ? w2 : w1;
    float v = src[(((size_t)(part * 4 + g) * 128 + k) * 128) + m];
    unsigned short h, lo;
    split_bf16(v, h, lo);
    size_t base = (size_t)((l * 4 + g) * 4 + part * 2) * PLW;
    g_wimg[base + m * WP + k]       = h;
    g_wimg[base + PLW + m * WP + k] = lo;
}

// ============================ FFT passes ====================================
// Radix-8: three fused radix-2 stages S, S+1, S+2 (DIT, bit-reversed input).
template<int S>
__device__ __forceinline__ void pass8_rows(float* R, float* I,
                                           const float* twR, const float* twI) {
    const int h = 1 << (S - 1);
    for (int it = threadIdx.x; it < 64 * 16; it += NT_F) {
        int r = it & 63, q = it >> 6;
        int j = q & (h - 1);
        int base = (q >> (S - 1)) << (S + 2);
        int i0 = r * RPIT + base + j;
        float er[8], ei[8];
        #pragma unroll
        for (int k = 0; k < 8; k++) { er[k] = R[i0 + k * h]; ei[k] = I[i0 + k * h]; }
        {
            float wr = twR[j << (7 - S)], wi = twI[j << (7 - S)];
            #pragma unroll
            for (int k = 0; k < 8; k += 2) {
                float tr = er[k+1] * wr - ei[k+1] * wi;
                float ti = er[k+1] * wi + ei[k+1] * wr;
                er[k+1] = er[k] - tr; ei[k+1] = ei[k] - ti;
                er[k]  += tr;         ei[k]  += ti;
            }
        }
        {
            float w2r = twR[j << (6 - S)],       w2i = twI[j << (6 - S)];
            float w3r = twR[(j + h) << (6 - S)], w3i = twI[(j + h) << (6 - S)];
            #pragma unroll
            for (int gq = 0; gq < 8; gq += 4) {
                float tr = er[gq+2] * w2r - ei[gq+2] * w2i;
                float ti = er[gq+2] * w2i + ei[gq+2] * w2r;
                er[gq+2] = er[gq] - tr; ei[gq+2] = ei[gq] - ti;
                er[gq]  += tr;          ei[gq]  += ti;
                tr = er[gq+3] * w3r - ei[gq+3] * w3i;
                ti = er[gq+3] * w3i + ei[gq+3] * w3r;
                er[gq+3] = er[gq+1] - tr; ei[gq+3] = ei[gq+1] - ti;
                er[gq+1] += tr;           ei[gq+1] += ti;
            }
        }
        #pragma unroll
        for (int k = 0; k < 4; k++) {
            float wr = twR[(j + k * h) << (5 - S)], wi = twI[(j + k * h) << (5 - S)];
            float tr = er[k+4] * wr - ei[k+4] * wi;
            float ti = er[k+4] * wi + ei[k+4] * wr;
            er[k+4] = er[k] - tr; ei[k+4] = ei[k] - ti;
            er[k]  += tr;         ei[k]  += ti;
        }
        #pragma unroll
        for (int k = 0; k < 8; k++) { R[i0 + k * h] = er[k]; I[i0 + k * h] = ei[k]; }
    }
}

template<int S>
__device__ __forceinline__ void pass8_cols(float* R, float* I,
                                           const float* twR, const float* twI) {
    const int h = 1 << (S - 1);
    const int st = h * CPIT;
    for (int it = threadIdx.x; it < 65 * 16; it += NT_F) {
        int c = it % 65, q = it / 65;
        int j = q & (h - 1);
        int base = (q >> (S - 1)) << (S + 2);
        int i0 = (base + j) * CPIT + c;
        float er[8], ei[8];
        #pragma unroll
        for (int k = 0; k < 8; k++) { er[k] = R[i0 + k * st]; ei[k] = I[i0 + k * st]; }
        {
            float wr = twR[j << (7 - S)], wi = twI[j << (7 - S)];
            #pragma unroll
            for (int k = 0; k < 8; k += 2) {
                float tr = er[k+1] * wr - ei[k+1] * wi;
                float ti = er[k+1] * wi + ei[k+1] * wr;
                er[k+1] = er[k] - tr; ei[k+1] = ei[k] - ti;
                er[k]  += tr;         ei[k]  += ti;
            }
        }
        {
            float w2r = twR[j << (6 - S)],       w2i = twI[j << (6 - S)];
            float w3r = twR[(j + h) << (6 - S)], w3i = twI[(j + h) << (6 - S)];
            #pragma unroll
            for (int gq = 0; gq < 8; gq += 4) {
                float tr = er[gq+2] * w2r - ei[gq+2] * w2i;
                float ti = er[gq+2] * w2i + ei[gq+2] * w2r;
                er[gq+2] = er[gq] - tr; ei[gq+2] = ei[gq] - ti;
                er[gq]  += tr;          ei[gq]  += ti;
                tr = er[gq+3] * w3r - ei[gq+3] * w3i;
                ti = er[gq+3] * w3i + ei[gq+3] * w3r;
                er[gq+3] = er[gq+1] - tr; ei[gq+3] = ei[gq+1] - ti;
                er[gq+1] += tr;           ei[gq+1] += ti;
            }
        }
        #pragma unroll
        for (int k = 0; k < 4; k++) {
            float wr = twR[(j + k * h) << (5 - S)], wi = twI[(j + k * h) << (5 - S)];
            float tr = er[k+4] * wr - ei[k+4] * wi;
            float ti = er[k+4] * wi + ei[k+4] * wr;
            er[k+4] = er[k] - tr; ei[k+4] = ei[k] - ti;
            er[k]  += tr;         ei[k]  += ti;
        }
        #pragma unroll
        for (int k = 0; k < 8; k++) { R[i0 + k * st] = er[k]; I[i0 + k * st] = ei[k]; }
    }
}

// Radix-16: fused radix-2 stages 4,5,6,7 (h=8..64). Each thread: 16 elems j+8k.
__device__ __forceinline__ void pass16_rows(float* R, float* I,
                                            const float* twR, const float* twI) {
    for (int it = threadIdx.x; it < 512; it += NT_F) {
        int r = it & 63, j = it >> 6;
        int i0 = r * RPIT + j;
        float er[16], ei[16];
        #pragma unroll
        for (int k = 0; k < 16; k++) { er[k] = R[i0 + 8 * k]; ei[k] = I[i0 + 8 * k]; }
        {
            float wr = twR[j << 3], wi = twI[j << 3];
            #pragma unroll
            for (int k = 0; k < 16; k += 2) {
                float tr = er[k+1] * wr - ei[k+1] * wi;
                float ti = er[k+1] * wi + ei[k+1] * wr;
                er[k+1] = er[k] - tr; ei[k+1] = ei[k] - ti;
                er[k]  += tr;         ei[k]  += ti;
            }
        }
        {
            float w0r = twR[j << 2],       w0i = twI[j << 2];
            float w1r = twR[(j + 8) << 2], w1i = twI[(j + 8) << 2];
            #pragma unroll
            for (int b = 0; b < 16; b += 4) {
                float tr = er[b+2] * w0r - ei[b+2] * w0i;
                float ti = er[b+2] * w0i + ei[b+2] * w0r;
                er[b+2] = er[b] - tr; ei[b+2] = ei[b] - ti;
                er[b]  += tr;         ei[b]  += ti;
                tr = er[b+3] * w1r - ei[b+3] * w1i;
                ti = er[b+3] * w1i + ei[b+3] * w1r;
                er[b+3] = er[b+1] - tr; ei[b+3] = ei[b+1] - ti;
                er[b+1] += tr;          ei[b+1] += ti;
            }
        }
        #pragma unroll
        for (int b = 0; b < 16; b += 8) {
            #pragma unroll
            for (int m = 0; m < 4; m++) {
                float wr = twR[(j + 8 * m) << 1], wi = twI[(j + 8 * m) << 1];
                float tr = er[b+m+4] * wr - ei[b+m+4] * wi;
                float ti = er[b+m+4] * wi + ei[b+m+4] * wr;
                er[b+m+4] = er[b+m] - tr; ei[b+m+4] = ei[b+m] - ti;
                er[b+m]  += tr;           ei[b+m]  += ti;
            }
        }
        #pragma unroll
        for (int m = 0; m < 8; m++) {
            float wr = twR[j + 8 * m], wi = twI[j + 8 * m];
            float tr = er[m+8] * wr - ei[m+8] * wi;
            float ti = er[m+8] * wi + ei[m+8] * wr;
            er[m+8] = er[m] - tr; ei[m+8] = ei[m] - ti;
            er[m]  += tr;         ei[m]  += ti;
        }
        #pragma unroll
        for (int k = 0; k < 16; k++) { R[i0 + 8 * k] = er[k]; I[i0 + 8 * k] = ei[k]; }
    }
}

__device__ __forceinline__ void pass16_cols(float* R, float* I,
                                            const float* twR, const float* twI) {
    for (int it = threadIdx.x; it < 65 * 8; it += NT_F) {
        int c = it % 65, j = it / 65;
        int i0 = j * CPIT + c;
        float er[16], ei[16];
        #pragma unroll
        for (int k = 0; k < 16; k++) { er[k] = R[i0 + 8 * k * CPIT]; ei[k] = I[i0 + 8 * k * CPIT]; }
        {
            float wr = twR[j << 3], wi = twI[j << 3];
            #pragma unroll
            for (int k = 0; k < 16; k += 2) {
                float tr = er[k+1] * wr - ei[k+1] * wi;
                float ti = er[k+1] * wi + ei[k+1] * wr;
                er[k+1] = er[k] - tr; ei[k+1] = ei[k] - ti;
                er[k]  += tr;         ei[k]  += ti;
            }
        }
        {
            float w0r = twR[j << 2],       w0i = twI[j << 2];
            float w1r = twR[(j + 8) << 2], w1i = twI[(j + 8) << 2];
            #pragma unroll
            for (int b = 0; b < 16; b += 4) {
                float tr = er[b+2] * w0r - ei[b+2] * w0i;
                float ti = er[b+2] * w0i + ei[b+2] * w0r;
                er[b+2] = er[b] - tr; ei[b+2] = ei[b] - ti;
                er[b]  += tr;         ei[b]  += ti;
                tr = er[b+3] * w1r - ei[b+3] * w1i;
                ti = er[b+3] * w1i + ei[b+3] * w1r;
                er[b+3] = er[b+1] - tr; ei[b+3] = ei[b+1] - ti;
                er[b+1] += tr;          ei[b+1] += ti;
            }
        }
        #pragma unroll
        for (int b = 0; b < 16; b += 8) {
            #pragma unroll
            for (int m = 0; m < 4; m++) {
                float wr = twR[(j + 8 * m) << 1], wi = twI[(j + 8 * m) << 1];
                float tr = er[b+m+4] * wr - ei[b+m+4] * wi;
                float ti = er[b+m+4] * wi + ei[b+m+4] * wr;
                er[b+m+4] = er[b+m] - tr; ei[b+m+4] = ei[b+m] - ti;
                er[b+m]  += tr;           ei[b+m]  += ti;
            }
        }
        #pragma unroll
        for (int m = 0; m < 8; m++) {
            float wr = twR[j + 8 * m], wi = twI[j + 8 * m];
            float tr = er[m+8] * wr - ei[m+8] * wi;
            float ti = er[m+8] * wi + ei[m+8] * wr;
            er[m+8] = er[m] - tr; ei[m+8] = ei[m] - ti;
            er[m]  += tr;         ei[m]  += ti;
        }
        #pragma unroll
        for (int k = 0; k < 16; k++) { R[i0 + 8 * k * CPIT] = er[k]; I[i0 + 8 * k * CPIT] = ei[k]; }
    }
}

__global__ void __launch_bounds__(NT_F, 3) kfft_fwd(const float* __restrict__ x) {
    extern __shared__ float sm[];
    float* R   = sm;
    float* I   = sm + UBUF;
    float* twR = sm + 2 * UBUF;
    float* twI = twR + 64;

    const int tid = threadIdx.x;
    const int img = blockIdx.x;

    if (tid < 64) {
        float s, c;
        sincospif(-(float)tid / 64.0f, &s, &c);
        twR[tid] = c; twI[tid] = s;
    }

    const float* src = x + (size_t)img * (H_ * W_);
    for (int t = tid; t < 64 * 128; t += NT_F) {
        int p = t >> 7, c = t & 127;
        int cb = brev7(c);
        R[p * RPIT + cb] = src[(2 * p) * 128 + c];
        I[p * RPIT + cb] = src[(2 * p) * 128 + 128 + c];
    }
    __syncthreads();

    pass8_rows<1>(R, I, twR, twI); __syncthreads();
    pass16_rows  (R, I, twR, twI); __syncthreads();

    float u0r[9], u0i[9], u1r[9], u1i[9];
    #pragma unroll
    for (int n = 0; n < 9; n++) {
        int it = tid + n * NT_F;
        if (it < 64 * 65) {
            int k = it % 65, p = it / 65;
            int m = (128 - k) & 127;
            float a = R[p * RPIT + k], b = I[p * RPIT + k];
            float c2 = R[p * RPIT + m], d = I[p * RPIT + m];
            u0r[n] = 0.5f * (a + c2); u0i[n] = 0.5f * (b - d);
            u1r[n] = 0.5f * (b + d);  u1i[n] = 0.5f * (c2 - a);
        }
    }
    __syncthreads();
    #pragma unroll
    for (int n = 0; n < 9; n++) {
        int it = tid + n * NT_F;
        if (it < 64 * 65) {
            int k = it % 65, p = it / 65;
            int h0 = brev7(2 * p), h1 = brev7(2 * p + 1);
            R[h0 * CPIT + k] = u0r[n]; I[h0 * CPIT + k] = u0i[n];
            R[h1 * CPIT + k] = u1r[n]; I[h1 * CPIT + k] = u1i[n];
        }
    }
    __syncthreads();

    pass8_cols<1>(R, I, twR, twI); __syncthreads();
    pass16_cols  (R, I, twR, twI); __syncthreads();

    float* dR = g_specR + (size_t)img * F_;
    float* dI = g_specI + (size_t)img * F_;
    const float sc = 1.0f / 128.0f;
    for (int t = tid; t < F_; t += NT_F) {
        dR[t] = R[t] * sc;
        dI[t] = I[t] * sc;
    }
}

// ---------------------------------------------------------------------------
// Tensor-core mixer: 512 threads / 16 warps, warp tile m16 x n16, LDSM loads,
// software-pipelined k-loop (round-15 sequential mma order — measured best).
// ---------------------------------------------------------------------------
__device__ __forceinline__ void mma16816(float* d, const uint32_t* a, const uint32_t* b) {
    asm volatile("mma.sync.aligned.m16n8k16.row.col.f32.bf16.bf16.f32 "
        "{%0,%1,%2,%3}, {%4,%5,%6,%7}, {%8,%9}, {%0,%1,%2,%3};"
        : "+f"(d[0]), "+f"(d[1]), "+f"(d[2]), "+f"(d[3])
        : "r"(a[0]), "r"(a[1]), "r"(a[2]), "r"(a[3]), "r"(b[0]), "r"(b[1]));
}

__device__ __forceinline__ void ld_frags(uint32_t smW_a, uint32_t smX_a,
                                         uint32_t aOff, uint32_t bOff, uint32_t k0b,
                                         uint32_t A[4][4], uint32_t Bf[4][4]) {
    #pragma unroll
    for (int pl = 0; pl < 4; pl++)
        LDSM_X4(A[pl], smW_a + (uint32_t)pl * (PLW * 2) + aOff + k0b);
    #pragma unroll
    for (int pl = 0; pl < 4; pl++)
        LDSM_X4(Bf[pl], smX_a + (uint32_t)pl * (PLX32 * 2) + bOff + k0b);
}

__device__ __forceinline__ void mma_block(const uint32_t A[4][4], const uint32_t Bf[4][4],
                                          float* aOr, float* aP, float* aOi) {
    #pragma unroll
    for (int nt = 0; nt < 2; nt++) {
        float* dOr = aOr + nt * 4;
        float* dP  = aP  + nt * 4;
        float* dOi = aOi + nt * 4;
        const uint32_t* bR  = &Bf[0][nt * 2];
        const uint32_t* bRl = &Bf[1][nt * 2];
        const uint32_t* bI  = &Bf[2][nt * 2];
        const uint32_t* bIl = &Bf[3][nt * 2];
        mma16816(dOr, A[0], bR);
        mma16816(dOr, A[1], bR);
        mma16816(dOr, A[0], bRl);
        mma16816(dP,  A[2], bI);
        mma16816(dP,  A[3], bI);
        mma16816(dP,  A[2], bIl);
        mma16816(dOi, A[2], bR);
        mma16816(dOi, A[3], bR);
        mma16816(dOi, A[2], bRl);
        mma16816(dOi, A[0], bI);
        mma16816(dOi, A[1], bI);
        mma16816(dOi, A[0], bIl);
    }
}

// warp tile m16 (warp_m = (wid&7)*16) x n16 (warp_n = (wid>>3)*16, 2 x n8)
__device__ __forceinline__ void gemm32(uint32_t smW_a, uint32_t smX_a,
                                       float* aOr, float* aP, float* aOi,
                                       int warp_m, int warp_n, int lane) {
    const uint32_t aOff = (uint32_t)((warp_m + (lane & 15)) * WP + ((lane >> 4) << 3)) * 2;
    const uint32_t bOff = (uint32_t)((warp_n + ((lane >> 4) << 3) + (lane & 7)) * WP
                                     + (((lane >> 3) & 1) << 3)) * 2;
    uint32_t A[2][4][4], Bf[2][4][4];
    ld_frags(smW_a, smX_a, aOff, bOff, 0, A[0], Bf[0]);
    #pragma unroll
    for (int kk = 0; kk < 8; kk++) {
        const int cur = kk & 1, nxt = cur ^ 1;
        if (kk < 7)
            ld_frags(smW_a, smX_a, aOff, bOff, (uint32_t)(kk + 1) * 32, A[nxt], Bf[nxt]);
        mma_block(A[cur], Bf[cur], aOr, aP, aOi);
    }
}

__device__ __forceinline__ void chunk_range(int c, int& start, int& cnt) {
    start = c * 29;
    cnt   = (c == 8) ? 28 : 29;
}

// L1 smem: W planes | X planes | raw staging
#define L1_OFF_X   (4 * PLW * 2)                     // 139264
#define L1_OFF_RAW (L1_OFF_X + 4 * PLX32 * 2)        // 174080
#define SM_L1      (L1_OFF_RAW + 2 * 128 * RPITCH * 4)  // 210944
// L2 smem: W planes | 2x X plane buffers
#define L2_OFF_X   (4 * PLW * 2)
#define SM_L2      (L2_OFF_X + 2 * 4 * PLX32 * 2)       // 208896

// ================= Layer 1 kernel =================
__global__ void __launch_bounds__(NT_M, 1)
kmixL1(const float* __restrict__ b1) {
    extern __shared__ char smem[];
    unsigned short* smW = (unsigned short*)smem;
    unsigned short* smX = (unsigned short*)(smem + L1_OFF_X);
    float*          raw = (float*)(smem + L1_OFF_RAW);
    const uint32_t raw_u32 = smem_u32(raw);
    const uint32_t smW_a = smem_u32(smW);
    const uint32_t smX_a = smem_u32(smX);

    const int tid = threadIdx.x;
    const int wid = tid >> 5, lane = tid & 31;
    const int gid = lane >> 2, tig = lane & 3;
    const int warp_m = (wid & 7) * 16;
    const int warp_n = (wid >> 3) * 16;
    const int bg = blockIdx.x;
    const int b = bg >> 2, g = bg & 3;
    int start, cnt;
    chunk_range(blockIdx.y, start, cnt);
    const int end = start + cnt;

    const size_t chanbase = ((size_t)b * C_ + (size_t)g * D_) * F_;

    // prefetch first tile raw spec (async)
    {
        for (int i = tid; i < 2048; i += NT_M) {
            int pl = i >> 10, rem = i & 1023, c = rem >> 3, seg = rem & 7;
            const float* src = (pl ? g_specI : g_specR) + chanbase + (size_t)c * F_
                             + (size_t)start * 32 + seg * 4;
            uint32_t dst = raw_u32 + (uint32_t)(pl * (128 * RPITCH * 4) + c * (RPITCH * 4) + seg * 16);
            CP_ASYNC16(dst, src);
        }
        CP_COMMIT();
    }

    // W1 planes: once per CTA
    {
        const float4* ws = (const float4*)(g_wimg + (size_t)(0 * 4 + g) * 4 * PLW);
        float4* wd = (float4*)smW;
        for (int i = tid; i < 4 * PLW / 8; i += NT_M) wd[i] = ws[i];
    }

    // bias values (fixed rows per warp)
    const int r0 = warp_m + gid;
    const float br0  = b1[g * D_ + r0];
    const float br1_ = b1[g * D_ + r0 + 8];
    const float bi0  = b1[(G_ + g) * D_ + r0];
    const float bi1_ = b1[(G_ + g) * D_ + r0 + 8];

    for (int t = start; t < end; t++) {
        CP_WAIT0();
        __syncthreads();

        // convert raw -> X planes (split); 4096 elems / 512 threads
        #pragma unroll
        for (int n = 0; n < 8; n++) {
            int it = tid + n * NT_M;
            int c = it >> 5, f = it & 31;
            float vr = raw[c * RPITCH + f];
            float vi = raw[128 * RPITCH + c * RPITCH + f];
            unsigned short rh, rl, ih, il;
            split_bf16(vr, rh, rl);
            split_bf16(vi, ih, il);
            int o = f * WP + c;
            smX[o] = rh; smX[PLX32 + o] = rl;
            smX[2 * PLX32 + o] = ih; smX[3 * PLX32 + o] = il;
        }
        __syncthreads();

        // prefetch next tile raw (overlaps GEMM)
        if (t + 1 < end) {
            for (int i = tid; i < 2048; i += NT_M) {
                int pl = i >> 10, rem = i & 1023, c = rem >> 3, seg = rem & 7;
                const float* src = (pl ? g_specI : g_specR) + chanbase + (size_t)c * F_
                                 + (size_t)(t + 1) * 32 + seg * 4;
                uint32_t dst = raw_u32 + (uint32_t)(pl * (128 * RPITCH * 4) + c * (RPITCH * 4) + seg * 16);
                CP_ASYNC16(dst, src);
            }
            CP_COMMIT();
        }

        float aOr[8], aP[8], aOi[8];
        #pragma unroll
        for (int i = 0; i < 8; i++) { aOr[i] = 0.f; aP[i] = 0.f; aOi[i] = 0.f; }
        gemm32(smW_a, smX_a, aOr, aP, aOi, warp_m, warp_n, lane);
        __syncthreads();

        // epilogue: bias + relu, split, write O1 planes back into smX
        #pragma unroll
        for (int nt = 0; nt < 2; nt++) {
            int c0 = warp_n + nt * 8 + tig * 2;
            int ai = nt * 4;
            #pragma unroll
            for (int e = 0; e < 4; e++) {
                int row = (e >= 2) ? r0 + 8 : r0;
                int col = c0 + (e & 1);
                float brv = (e >= 2) ? br1_ : br0;
                float biv = (e >= 2) ? bi1_ : bi0;
                float vr = aOr[ai + e] - aP[ai + e] + brv; vr = vr > 0.f ? vr : 0.f;
                float vi = aOi[ai + e] + biv;              vi = vi > 0.f ? vi : 0.f;
                unsigned short rh, rl, ih, il;
                split_bf16(vr, rh, rl);
                split_bf16(vi, ih, il);
                int o = col * WP + row;
                smX[o] = rh; smX[PLX32 + o] = rl;
                smX[2 * PLX32 + o] = ih; smX[3 * PLX32 + o] = il;
            }
        }
        __syncthreads();

        // coalesced copy-out smX planes -> g_o1: 4 planes x 32 f x 16 uint4
        {
            uint4* dst = (uint4*)(g_o1 + ((size_t)bg * NTILE + t) * 16384);
            for (int i = tid; i < 2048; i += NT_M) {
                int pl = i >> 9, rem = i & 511, f = rem >> 4, c16 = rem & 15;
                dst[i] = *(const uint4*)(smX + pl * PLX32 + f * WP + c16 * 8);
            }
        }
    }
}

// ================= Layer 2 kernel =================
__global__ void __launch_bounds__(NT_M, 1)
kmixL2(const float* __restrict__ b2) {
    extern __shared__ char smem[];
    unsigned short* smW  = (unsigned short*)smem;
    unsigned short* smX0 = (unsigned short*)(smem + L2_OFF_X);
    const uint32_t smW_a = smem_u32(smW);

    const int tid = threadIdx.x;
    const int wid = tid >> 5, lane = tid & 31;
    const int gid = lane >> 2, tig = lane & 3;
    const int warp_m = (wid & 7) * 16;
    const int warp_n = (wid >> 3) * 16;
    const int bg = blockIdx.x;
    const int b = bg >> 2, g = bg & 3;
    int start, cnt;
    chunk_range(blockIdx.y, start, cnt);
    const int end = start + cnt;

    const size_t chanbase = ((size_t)b * C_ + (size_t)g * D_) * F_;

    // prefetch first tile O1 planes into buf0
    {
        const uint4* src = (const uint4*)(g_o1 + ((size_t)bg * NTILE + start) * 16384);
        uint32_t bufb = smem_u32(smX0);
        for (int i = tid; i < 2048; i += NT_M) {
            int pl = i >> 9, rem = i & 511, f = rem >> 4, c16 = rem & 15;
            uint32_t dst = bufb + (uint32_t)((pl * PLX32 + f * WP) * 2 + c16 * 16);
            CP_ASYNC16(dst, src + i);
        }
        CP_COMMIT();
    }

    // W2 planes
    {
        const float4* ws = (const float4*)(g_wimg + (size_t)(1 * 4 + g) * 4 * PLW);
        float4* wd = (float4*)smW;
        for (int i = tid; i < 4 * PLW / 8; i += NT_M) wd[i] = ws[i];
    }

    const int r0 = warp_m + gid;
    const float br0  = b2[g * D_ + r0];
    const float br1_ = b2[g * D_ + r0 + 8];
    const float bi0  = b2[(G_ + g) * D_ + r0];
    const float bi1_ = b2[(G_ + g) * D_ + r0 + 8];

    for (int t = start; t < end; t++) {
        unsigned short* buf = smX0 + ((t - start) & 1) * (4 * PLX32);
        CP_WAIT0();
        __syncthreads();

        // prefetch next tile into other buffer (overlaps GEMM)
        if (t + 1 < end) {
            unsigned short* nb = smX0 + (((t - start) + 1) & 1) * (4 * PLX32);
            const uint4* src = (const uint4*)(g_o1 + ((size_t)bg * NTILE + (t + 1)) * 16384);
            uint32_t bufb = smem_u32(nb);
            for (int i = tid; i < 2048; i += NT_M) {
                int pl = i >> 9, rem = i & 511, f = rem >> 4, c16 = rem & 15;
                uint32_t dst = bufb + (uint32_t)((pl * PLX32 + f * WP) * 2 + c16 * 16);
                CP_ASYNC16(dst, src + i);
            }
            CP_COMMIT();
        }

        // prefetch origin spec values into registers (consumed in epilogue)
        float2 oxr[4], oxi[4];
        #pragma unroll
        for (int nt = 0; nt < 2; nt++)
            #pragma unroll
            for (int rp = 0; rp < 2; rp++) {
                int row = r0 + rp * 8;
                int c0  = warp_n + nt * 8 + tig * 2;
                size_t gi = chanbase + (size_t)row * F_ + (size_t)t * 32 + c0;
                int idx = nt * 2 + rp;
                oxr[idx] = *(const float2*)&g_specR[gi];
                oxi[idx] = *(const float2*)&g_specI[gi];
            }

        float aOr[8], aP[8], aOi[8];
        #pragma unroll
        for (int i = 0; i < 8; i++) { aOr[i] = 0.f; aP[i] = 0.f; aOi[i] = 0.f; }
        gemm32(smW_a, smem_u32(buf), aOr, aP, aOi, warp_m, warp_n, lane);

        // epilogue: bias, multiply by origin, store
        #pragma unroll
        for (int nt = 0; nt < 2; nt++) {
            int c0 = warp_n + nt * 8 + tig * 2;
            int ai = nt * 4;
            #pragma unroll
            for (int rp = 0; rp < 2; rp++) {
                int row = r0 + rp * 8;
                float brv = rp ? br1_ : br0;
                float biv = rp ? bi1_ : bi0;
                int idx = nt * 2 + rp;
                float2 xr = oxr[idx], xi = oxi[idx];
                size_t gi = chanbase + (size_t)row * F_ + (size_t)t * 32 + c0;
                float vr0 = aOr[ai + rp * 2]     - aP[ai + rp * 2]     + brv;
                float vi0 = aOi[ai + rp * 2]     + biv;
                float vr1 = aOr[ai + rp * 2 + 1] - aP[ai + rp * 2 + 1] + brv;
                float vi1 = aOi[ai + rp * 2 + 1] + biv;
                float2 orv, oiv;
                orv.x = vr0 * xr.x - vi0 * xi.x;
                oiv.x = vr0 * xi.x + vi0 * xr.x;
                orv.y = vr1 * xr.y - vi1 * xi.y;
                oiv.y = vr1 * xi.y + vi1 * xr.y;
                *(float2*)&g_outR[gi] = orv;
                *(float2*)&g_outI[gi] = oiv;
            }
        }
    }
}

// ---------------------------------------------------------------------------
__global__ void __launch_bounds__(NT_F, 3) kfft_inv(float* __restrict__ y) {
    extern __shared__ float sm[];
    float* R   = sm;
    float* I   = sm + UBUF;
    float* twR = sm + 2 * UBUF;
    float* twI = twR + 64;

    const int tid = threadIdx.x;
    const int img = blockIdx.x;

    if (tid < 64) {
        float s, c;
        sincospif((float)tid / 64.0f, &s, &c);
        twR[tid] = c; twI[tid] = s;
    }

    const float* srcR = g_outR + (size_t)img * F_;
    const float* srcI = g_outI + (size_t)img * F_;
    for (int t = tid; t < F_; t += NT_F) {
        int h = t / WF_, k = t - h * WF_;
        int hb = brev7(h);
        R[hb * CPIT + k] = srcR[t];
        I[hb * CPIT + k] = srcI[t];
    }
    __syncthreads();

    pass8_cols<1>(R, I, twR, twI); __syncthreads();
    pass16_cols  (R, I, twR, twI); __syncthreads();

    float zr[16], zi[16];
    #pragma unroll
    for (int n = 0; n < 16; n++) {
        int it = tid + n * NT_F;
        int w = it & 127, p = it >> 7;
        int r0 = (2 * p) * CPIT, r1 = r0 + CPIT;
        if (w <= 64) {
            float x0r = R[r0 + w], x0i = I[r0 + w];
            float x1r = R[r1 + w], x1i = I[r1 + w];
            if (w == 0 || w == 64) { x0i = 0.f; x1i = 0.f; }
            zr[n] = x0r - x1i;
            zi[n] = x0i + x1r;
        } else {
            int m = 128 - w;
            float x0r = R[r0 + m], x0i = I[r0 + m];
            float x1r = R[r1 + m], x1i = I[r1 + m];
            zr[n] = x0r + x1i;
            zi[n] = x1r - x0i;
        }
    }
    __syncthreads();
    #pragma unroll
    for (int n = 0; n < 16; n++) {
        int it = tid + n * NT_F;
        int w = it & 127, p = it >> 7;
        int wb = brev7(w);
        R[p * RPIT + wb] = zr[n];
        I[p * RPIT + wb] = zi[n];
    }
    __syncthreads();

    pass8_rows<1>(R, I, twR, twI); __syncthreads();
    pass16_rows  (R, I, twR, twI); __syncthreads();

    float* dst = y + (size_t)img * (H_ * W_);
    const float sc = 1.0f / 128.0f;
    for (int t = tid; t < 64 * 128; t += NT_F) {
        int p = t >> 7, c = t & 127;
        dst[(2 * p) * 128 + c]       = R[p * RPIT + c] * sc;
        dst[(2 * p) * 128 + 128 + c] = I[p * RPIT + c] * sc;
    }
}

// ---------------------------------------------------------------------------
extern "C" void kernel_launch(void* const* d_in, const int* in_sizes, int n_in,
                              void* d_out, int out_size) {
    const float* x  = (const float*)d_in[0];
    const float* w1 = (const float*)d_in[1];
    const float* w2 = (const float*)d_in[2];
    const float* b1 = (const float*)d_in[3];
    const float* b2 = (const float*)d_in[4];
    float* y = (float*)d_out;

    const int smFFT = (2 * UBUF + 128) * (int)sizeof(float);   // ~65.5 KB

    cudaFuncSetAttribute(kfft_fwd, cudaFuncAttributeMaxDynamicSharedMemorySize, smFFT);
    cudaFuncSetAttribute(kmixL1,   cudaFuncAttributeMaxDynamicSharedMemorySize, SM_L1);
    cudaFuncSetAttribute(kmixL2,   cudaFuncAttributeMaxDynamicSharedMemorySize, SM_L2);
    cudaFuncSetAttribute(kfft_inv, cudaFuncAttributeMaxDynamicSharedMemorySize, smFFT);

    wprep<<<1024, 256>>>(w1, w2);
    kfft_fwd<<<NIMG, NT_F, smFFT>>>(x);
    kmixL1<<<dim3(32, NCHUNK), NT_M, SM_L1>>>(b1);
    kmixL2<<<dim3(32, NCHUNK), NT_M, SM_L2>>>(b2);
    kfft_inv<<<NIMG, NT_F, smFFT>>>(y);
}